// round 1
// baseline (speedup 1.0000x reference)
#include <cuda_runtime.h>
#include <cstdint>
#include <cmath>

// ---------------- problem constants ----------------
#define TOKS 4096      // B*S
#define DMODEL 2048
#define DFF 8192
#define NHEADS 16
#define DKH 128        // head dim
#define SEQ 2048
#define BATCH 2

// ---------------- scratch (device globals; no runtime alloc) ----------------
__device__ float g_ln1[TOKS * DMODEL];
__device__ float g_ln2[TOKS * DMODEL];
__device__ float g_q[TOKS * DMODEL];   // [B*H, S, dk]
__device__ float g_k[TOKS * DMODEL];
__device__ float g_v[TOKS * DMODEL];
__device__ float g_ctx[TOKS * DMODEL]; // [token, H*dk]
__device__ float g_h[TOKS * DFF];
__device__ int   g_flag[1];

// ---------------- helpers ----------------
__device__ __forceinline__ float to_tf32(float x) {
    uint32_t u;
    asm("cvt.rna.tf32.f32 %0, %1;" : "=r"(u) : "f"(x));
    return __uint_as_float(u);
}
__device__ __forceinline__ uint32_t f2u(float x) { return __float_as_uint(x); }

__device__ __forceinline__ void mma8(float* c,
                                     uint32_t a0, uint32_t a1, uint32_t a2, uint32_t a3,
                                     uint32_t b0, uint32_t b1) {
    asm volatile(
        "mma.sync.aligned.m16n8k8.row.col.f32.tf32.tf32.f32 "
        "{%0,%1,%2,%3},{%4,%5,%6,%7},{%8,%9},{%0,%1,%2,%3};"
        : "+f"(c[0]), "+f"(c[1]), "+f"(c[2]), "+f"(c[3])
        : "r"(a0), "r"(a1), "r"(a2), "r"(a3), "r"(b0), "r"(b1));
}

// ---------------- LayerNorm (both norms of same x) ----------------
__global__ void ln_kernel(const float* __restrict__ x,
                          const float* __restrict__ ga1, const float* __restrict__ be1,
                          const float* __restrict__ ga2, const float* __restrict__ be2,
                          float* __restrict__ o1, float* __restrict__ o2) {
    int t = blockIdx.x;
    int tid = threadIdx.x;
    const float4* xr = (const float4*)(x + (size_t)t * DMODEL);
    float4 a = xr[tid];
    float4 bq = xr[tid + 256];
    float s  = a.x + a.y + a.z + a.w + bq.x + bq.y + bq.z + bq.w;
    float s2 = a.x*a.x + a.y*a.y + a.z*a.z + a.w*a.w +
               bq.x*bq.x + bq.y*bq.y + bq.z*bq.z + bq.w*bq.w;
    #pragma unroll
    for (int o = 16; o; o >>= 1) {
        s  += __shfl_xor_sync(0xffffffffu, s,  o);
        s2 += __shfl_xor_sync(0xffffffffu, s2, o);
    }
    __shared__ float rs[8], rs2[8], stats[2];
    if ((tid & 31) == 0) { rs[tid >> 5] = s; rs2[tid >> 5] = s2; }
    __syncthreads();
    if (tid == 0) {
        float S = 0.f, S2 = 0.f;
        for (int i = 0; i < 8; i++) { S += rs[i]; S2 += rs2[i]; }
        float mu = S * (1.0f / DMODEL);
        float var = S2 * (1.0f / DMODEL) - mu * mu;
        stats[0] = mu;
        stats[1] = rsqrtf(var + 1e-5f);
    }
    __syncthreads();
    float mu = stats[0], r = stats[1];
    const float4* G1 = (const float4*)ga1;
    const float4* B1 = (const float4*)be1;
    const float4* G2 = (const float4*)ga2;
    const float4* B2 = (const float4*)be2;
    float4* O1 = (float4*)(o1 + (size_t)t * DMODEL);
    float4* O2 = (float4*)(o2 + (size_t)t * DMODEL);
    #pragma unroll
    for (int i = 0; i < 2; i++) {
        int idx = tid + i * 256;
        float4 v = (i == 0) ? a : bq;
        float nx = (v.x - mu) * r, ny = (v.y - mu) * r, nz = (v.z - mu) * r, nw = (v.w - mu) * r;
        float4 g1v = G1[idx], b1v = B1[idx], g2v = G2[idx], b2v = B2[idx];
        float4 w1o, w2o;
        w1o.x = to_tf32(nx * g1v.x + b1v.x); w1o.y = to_tf32(ny * g1v.y + b1v.y);
        w1o.z = to_tf32(nz * g1v.z + b1v.z); w1o.w = to_tf32(nw * g1v.w + b1v.w);
        w2o.x = to_tf32(nx * g2v.x + b2v.x); w2o.y = to_tf32(ny * g2v.y + b2v.y);
        w2o.z = to_tf32(nz * g2v.z + b2v.z); w2o.w = to_tf32(nw * g2v.w + b2v.w);
        O1[idx] = w1o;
        O2[idx] = w2o;
    }
}

// ---------------- mask flag ----------------
__global__ void flag_init(int* flag) { if (threadIdx.x == 0) flag[0] = 1; }

__global__ void mask_reduce(const int* __restrict__ mask, int n, int* __restrict__ flag) {
    bool bad = false;
    for (int i = blockIdx.x * blockDim.x + threadIdx.x; i < n; i += gridDim.x * blockDim.x)
        if (mask[i] == 0) bad = true;
    if (bad) flag[0] = 0;
}

// ---------------- generic TF32 GEMM with fused epilogues ----------------
struct Epi {
    const float* c0;
    const float* c1;
    float* o0;
    float* o1;
    float* o2;
};

template <int E>
__device__ __forceinline__ void emit(int r, int c, int N, float v, const Epi& e) {
    if (E == 0) {               // QKV head split
        int which = c >> 11, rem = c & 2047, h = rem >> 7, d = rem & 127;
        int b = r >> 11, s = r & 2047;
        float* dst = (which == 0) ? e.o0 : ((which == 1) ? e.o1 : e.o2);
        dst[(size_t)((b << 4) + h) * (SEQ * DKH) + (size_t)s * DKH + d] = v;
    } else if (E == 1) {        // out = x + attn_out
        size_t i = (size_t)r * N + c;
        e.o0[i] = e.c0[i] + v;
    } else if (E == 2) {        // h = gelu(acc + b1), exact erf
        float t = v + e.c0[c];
        e.o0[(size_t)r * N + c] = 0.5f * t * (1.0f + erff(t * 0.70710678118654752f));
    } else {                    // out += layer_scale * (acc + b2)
        size_t i = (size_t)r * N + c;
        e.o0[i] += e.c1[c] * (v + e.c0[c]);
    }
}

template <int E>
__global__ __launch_bounds__(256)
void gemm_tf32(const float* __restrict__ A, const float* __restrict__ B,
               int M, int N, int K, Epi e) {
    __shared__ float As[128][20];    // stride 20 -> conflict-free A fragments
    __shared__ float Bs[16][136];    // stride 136 -> conflict-free B fragments
    int tid = threadIdx.x, warp = tid >> 5, lane = tid & 31;
    int g = lane >> 2, tq = lane & 3;
    int wm = (warp >> 2) * 64, wn = (warp & 3) * 32;
    int bm = blockIdx.y * 128, bn = blockIdx.x * 128;

    float acc[4][4][4];
    #pragma unroll
    for (int i = 0; i < 4; i++)
        #pragma unroll
        for (int j = 0; j < 4; j++)
            #pragma unroll
            for (int k = 0; k < 4; k++) acc[i][j][k] = 0.f;

    for (int k0 = 0; k0 < K; k0 += 16) {
        #pragma unroll
        for (int i = 0; i < 2; i++) {
            int f = tid + i * 256;
            int r = f >> 2, c = (f & 3) << 2;
            const float4 v = *(const float4*)(A + (size_t)(bm + r) * K + k0 + c);
            As[r][c]     = to_tf32(v.x);
            As[r][c + 1] = to_tf32(v.y);
            As[r][c + 2] = to_tf32(v.z);
            As[r][c + 3] = to_tf32(v.w);
        }
        #pragma unroll
        for (int i = 0; i < 2; i++) {
            int f = tid + i * 256;
            int r = f >> 5, c = (f & 31) << 2;
            const float4 v = *(const float4*)(B + (size_t)(k0 + r) * N + bn + c);
            Bs[r][c]     = to_tf32(v.x);
            Bs[r][c + 1] = to_tf32(v.y);
            Bs[r][c + 2] = to_tf32(v.z);
            Bs[r][c + 3] = to_tf32(v.w);
        }
        __syncthreads();
        #pragma unroll
        for (int kk = 0; kk < 2; kk++) {
            int kb = kk * 8;
            uint32_t a[4][4], b[4][2];
            #pragma unroll
            for (int mi = 0; mi < 4; mi++) {
                int r0 = wm + mi * 16 + g;
                a[mi][0] = f2u(As[r0][kb + tq]);
                a[mi][1] = f2u(As[r0 + 8][kb + tq]);
                a[mi][2] = f2u(As[r0][kb + tq + 4]);
                a[mi][3] = f2u(As[r0 + 8][kb + tq + 4]);
            }
            #pragma unroll
            for (int ni = 0; ni < 4; ni++) {
                int cc = wn + ni * 8 + g;
                b[ni][0] = f2u(Bs[kb + tq][cc]);
                b[ni][1] = f2u(Bs[kb + tq + 4][cc]);
            }
            #pragma unroll
            for (int mi = 0; mi < 4; mi++)
                #pragma unroll
                for (int ni = 0; ni < 4; ni++)
                    mma8(acc[mi][ni], a[mi][0], a[mi][1], a[mi][2], a[mi][3],
                         b[ni][0], b[ni][1]);
        }
        __syncthreads();
    }

    #pragma unroll
    for (int mi = 0; mi < 4; mi++) {
        int r0 = bm + wm + mi * 16 + g;
        #pragma unroll
        for (int ni = 0; ni < 4; ni++) {
            int c0 = bn + wn + ni * 8 + tq * 2;
            emit<E>(r0,     c0,     N, acc[mi][ni][0], e);
            emit<E>(r0,     c0 + 1, N, acc[mi][ni][1], e);
            emit<E>(r0 + 8, c0,     N, acc[mi][ni][2], e);
            emit<E>(r0 + 8, c0 + 1, N, acc[mi][ni][3], e);
        }
    }
}

// ---------------- flash attention (64q x 64k tiles, tf32 mma) ----------------
#define KS_STR 132
#define VS_STR 136
#define PS_STR 68
#define ATTN_SMEM ((64 * KS_STR + 64 * VS_STR + 4 * 16 * PS_STR) * 4)

__global__ __launch_bounds__(128, 2)
void attn_kernel(const float* __restrict__ Q, const float* __restrict__ K,
                 const float* __restrict__ V, const int* __restrict__ mask,
                 const int* __restrict__ flag, float* __restrict__ ctx) {
    extern __shared__ float sm[];
    float* Ks = sm;
    float* Vs = sm + 64 * KS_STR;
    float* Ps = Vs + 64 * VS_STR;
    int tid = threadIdx.x, warp = tid >> 5, lane = tid & 31;
    int g = lane >> 2, tq = lane & 3;
    int qt = blockIdx.x, bh = blockIdx.y;
    int b = bh >> 4, h = bh & 15;
    const float* Qb = Q + (size_t)bh * SEQ * DKH;
    const float* Kb = K + (size_t)bh * SEQ * DKH;
    const float* Vb = V + (size_t)bh * SEQ * DKH;
    int q0 = qt * 64 + warp * 16;
    int allv = flag[0];
    float* Pw = Ps + warp * 16 * PS_STR;

    // Q fragments in registers (reused over all 32 KV tiles)
    uint32_t qa[16][4];
    #pragma unroll
    for (int ks = 0; ks < 16; ks++) {
        int kc = ks * 8 + tq;
        qa[ks][0] = f2u(to_tf32(Qb[(size_t)(q0 + g) * DKH + kc]));
        qa[ks][1] = f2u(to_tf32(Qb[(size_t)(q0 + g + 8) * DKH + kc]));
        qa[ks][2] = f2u(to_tf32(Qb[(size_t)(q0 + g) * DKH + kc + 4]));
        qa[ks][3] = f2u(to_tf32(Qb[(size_t)(q0 + g + 8) * DKH + kc + 4]));
    }

    float o[16][4];
    #pragma unroll
    for (int i = 0; i < 16; i++)
        #pragma unroll
        for (int j = 0; j < 4; j++) o[i][j] = 0.f;
    float mA = -1e30f, mB = -1e30f, lA = 0.f, lB = 0.f;

    for (int j = 0; j < 32; j++) {
        // load K/V tiles (tf32-rounded)
        #pragma unroll
        for (int i = 0; i < 16; i++) {
            int f = tid + i * 128;
            int r = f >> 5, c = (f & 31) << 2;
            float4 kv = *(const float4*)(Kb + (size_t)(j * 64 + r) * DKH + c);
            Ks[r * KS_STR + c]     = to_tf32(kv.x);
            Ks[r * KS_STR + c + 1] = to_tf32(kv.y);
            Ks[r * KS_STR + c + 2] = to_tf32(kv.z);
            Ks[r * KS_STR + c + 3] = to_tf32(kv.w);
            float4 vv = *(const float4*)(Vb + (size_t)(j * 64 + r) * DKH + c);
            Vs[r * VS_STR + c]     = to_tf32(vv.x);
            Vs[r * VS_STR + c + 1] = to_tf32(vv.y);
            Vs[r * VS_STR + c + 2] = to_tf32(vv.z);
            Vs[r * VS_STR + c + 3] = to_tf32(vv.w);
        }
        __syncthreads();

        // S = Q @ K^T
        float sc[8][4];
        #pragma unroll
        for (int ni = 0; ni < 8; ni++)
            #pragma unroll
            for (int c = 0; c < 4; c++) sc[ni][c] = 0.f;
        #pragma unroll
        for (int ks = 0; ks < 16; ks++) {
            #pragma unroll
            for (int ni = 0; ni < 8; ni++) {
                uint32_t b0 = f2u(Ks[(ni * 8 + g) * KS_STR + ks * 8 + tq]);
                uint32_t b1 = f2u(Ks[(ni * 8 + g) * KS_STR + ks * 8 + tq + 4]);
                mma8(sc[ni], qa[ks][0], qa[ks][1], qa[ks][2], qa[ks][3], b0, b1);
            }
        }
        const float sscale = 0.0883883476483184f;  // 1/sqrt(128)
        #pragma unroll
        for (int ni = 0; ni < 8; ni++)
            #pragma unroll
            for (int c = 0; c < 4; c++) sc[ni][c] *= sscale;

        if (!allv) {  // cold path; mask is all-visible in this problem
            #pragma unroll
            for (int ni = 0; ni < 8; ni++) {
                int kc = j * 64 + ni * 8 + tq * 2;
                int r0 = q0 + g, r1 = q0 + g + 8;
                if (mask[(size_t)r0 * SEQ + kc] == 0)     sc[ni][0] = -1e9f;
                if (mask[(size_t)r0 * SEQ + kc + 1] == 0) sc[ni][1] = -1e9f;
                if (mask[(size_t)r1 * SEQ + kc] == 0)     sc[ni][2] = -1e9f;
                if (mask[(size_t)r1 * SEQ + kc + 1] == 0) sc[ni][3] = -1e9f;
            }
        }

        // online softmax
        float mxA = -1e30f, mxB = -1e30f;
        #pragma unroll
        for (int ni = 0; ni < 8; ni++) {
            mxA = fmaxf(mxA, fmaxf(sc[ni][0], sc[ni][1]));
            mxB = fmaxf(mxB, fmaxf(sc[ni][2], sc[ni][3]));
        }
        mxA = fmaxf(mxA, __shfl_xor_sync(0xffffffffu, mxA, 1));
        mxA = fmaxf(mxA, __shfl_xor_sync(0xffffffffu, mxA, 2));
        mxB = fmaxf(mxB, __shfl_xor_sync(0xffffffffu, mxB, 1));
        mxB = fmaxf(mxB, __shfl_xor_sync(0xffffffffu, mxB, 2));
        float mAn = fmaxf(mA, mxA), mBn = fmaxf(mB, mxB);
        float aA = __expf(mA - mAn), aB = __expf(mB - mBn);
        float sA = 0.f, sB = 0.f;
        #pragma unroll
        for (int ni = 0; ni < 8; ni++) {
            sc[ni][0] = to_tf32(__expf(sc[ni][0] - mAn)); sA += sc[ni][0];
            sc[ni][1] = to_tf32(__expf(sc[ni][1] - mAn)); sA += sc[ni][1];
            sc[ni][2] = to_tf32(__expf(sc[ni][2] - mBn)); sB += sc[ni][2];
            sc[ni][3] = to_tf32(__expf(sc[ni][3] - mBn)); sB += sc[ni][3];
        }
        sA += __shfl_xor_sync(0xffffffffu, sA, 1);
        sA += __shfl_xor_sync(0xffffffffu, sA, 2);
        sB += __shfl_xor_sync(0xffffffffu, sB, 1);
        sB += __shfl_xor_sync(0xffffffffu, sB, 2);
        lA = lA * aA + sA;
        lB = lB * aB + sB;
        mA = mAn; mB = mBn;
        #pragma unroll
        for (int ni = 0; ni < 16; ni++) {
            o[ni][0] *= aA; o[ni][1] *= aA;
            o[ni][2] *= aB; o[ni][3] *= aB;
        }

        // P -> smem (relayout accum -> A-fragment)
        #pragma unroll
        for (int ni = 0; ni < 8; ni++) {
            int c = ni * 8 + tq * 2;
            Pw[g * PS_STR + c]           = sc[ni][0];
            Pw[g * PS_STR + c + 1]       = sc[ni][1];
            Pw[(g + 8) * PS_STR + c]     = sc[ni][2];
            Pw[(g + 8) * PS_STR + c + 1] = sc[ni][3];
        }
        __syncwarp();

        // O += P @ V
        #pragma unroll
        for (int ks = 0; ks < 8; ks++) {
            uint32_t a0 = f2u(Pw[g * PS_STR + ks * 8 + tq]);
            uint32_t a1 = f2u(Pw[(g + 8) * PS_STR + ks * 8 + tq]);
            uint32_t a2 = f2u(Pw[g * PS_STR + ks * 8 + tq + 4]);
            uint32_t a3 = f2u(Pw[(g + 8) * PS_STR + ks * 8 + tq + 4]);
            #pragma unroll
            for (int ni = 0; ni < 16; ni++) {
                uint32_t b0 = f2u(Vs[(ks * 8 + tq) * VS_STR + ni * 8 + g]);
                uint32_t b1 = f2u(Vs[(ks * 8 + tq + 4) * VS_STR + ni * 8 + g]);
                mma8(o[ni], a0, a1, a2, a3, b0, b1);
            }
        }
        __syncthreads();
    }

    float rA = 1.f / lA, rB = 1.f / lB;
    int tok0 = b * SEQ + q0 + g, tok1 = tok0 + 8;
    #pragma unroll
    for (int ni = 0; ni < 16; ni++) {
        int d = ni * 8 + tq * 2;
        size_t i0 = (size_t)tok0 * DMODEL + h * DKH + d;
        size_t i1 = (size_t)tok1 * DMODEL + h * DKH + d;
        ctx[i0]     = o[ni][0] * rA;
        ctx[i0 + 1] = o[ni][1] * rA;
        ctx[i1]     = o[ni][2] * rB;
        ctx[i1 + 1] = o[ni][3] * rB;
    }
}

// ---------------- launch ----------------
extern "C" void kernel_launch(void* const* d_in, const int* in_sizes, int n_in,
                              void* d_out, int out_size) {
    const float* x     = (const float*)d_in[0];
    const int*   mask  = (const int*)d_in[1];
    const float* w_qkv = (const float*)d_in[2];
    const float* w_o   = (const float*)d_in[3];
    const float* ga1   = (const float*)d_in[4];
    const float* be1   = (const float*)d_in[5];
    const float* ga2   = (const float*)d_in[6];
    const float* be2   = (const float*)d_in[7];
    const float* w1    = (const float*)d_in[8];
    const float* b1    = (const float*)d_in[9];
    const float* w2    = (const float*)d_in[10];
    const float* b2    = (const float*)d_in[11];
    const float* ls    = (const float*)d_in[12];
    float* out = (float*)d_out;

    float *ln1, *ln2, *q, *k, *v, *ctx, *hbuf;
    int* flag;
    cudaGetSymbolAddress((void**)&ln1,  g_ln1);
    cudaGetSymbolAddress((void**)&ln2,  g_ln2);
    cudaGetSymbolAddress((void**)&q,    g_q);
    cudaGetSymbolAddress((void**)&k,    g_k);
    cudaGetSymbolAddress((void**)&v,    g_v);
    cudaGetSymbolAddress((void**)&ctx,  g_ctx);
    cudaGetSymbolAddress((void**)&hbuf, g_h);
    cudaGetSymbolAddress((void**)&flag, g_flag);

    cudaFuncSetAttribute(attn_kernel, cudaFuncAttributeMaxDynamicSharedMemorySize, ATTN_SMEM);

    // layernorms (both on x)
    ln_kernel<<<TOKS, 256>>>(x, ga1, be1, ga2, be2, ln1, ln2);

    // mask all-visible flag
    flag_init<<<1, 32>>>(flag);
    mask_reduce<<<256, 256>>>(mask, in_sizes[1], flag);

    // QKV projection: [4096,2048] @ [2048,6144] -> q/k/v head layout
    Epi e1; e1.c0 = nullptr; e1.c1 = nullptr; e1.o0 = q; e1.o1 = k; e1.o2 = v;
    gemm_tf32<0><<<dim3(48, 32), 256>>>(ln1, w_qkv, TOKS, 3 * DMODEL, DMODEL, e1);

    // attention
    attn_kernel<<<dim3(32, 32), 128, ATTN_SMEM>>>(q, k, v, mask, flag, ctx);

    // output projection + residual with x: out = x + ctx @ w_o
    Epi e2; e2.c0 = x; e2.c1 = nullptr; e2.o0 = out; e2.o1 = nullptr; e2.o2 = nullptr;
    gemm_tf32<1><<<dim3(16, 32), 256>>>(ctx, w_o, TOKS, DMODEL, DMODEL, e2);

    // FF1 + exact gelu
    Epi e3; e3.c0 = b1; e3.c1 = nullptr; e3.o0 = hbuf; e3.o1 = nullptr; e3.o2 = nullptr;
    gemm_tf32<2><<<dim3(64, 32), 256>>>(ln2, w1, TOKS, DFF, DMODEL, e3);

    // FF2 + bias + layer_scale, accumulate into out
    Epi e4; e4.c0 = b2; e4.c1 = ls; e4.o0 = out; e4.o1 = nullptr; e4.o2 = nullptr;
    gemm_tf32<3><<<dim3(16, 32), 256>>>(hbuf, w2, TOKS, DMODEL, DFF, e4);
}

// round 2
// speedup vs baseline: 1.0006x; 1.0006x over previous
#include <cuda_runtime.h>
#include <cstdint>
#include <cmath>

// ---------------- problem constants ----------------
#define TOKS 4096      // B*S
#define DMODEL 2048
#define DFF 8192
#define NHEADS 16
#define DKH 128        // head dim
#define SEQ 2048
#define BATCH 2

// ---------------- scratch (device globals; no runtime alloc) ----------------
__device__ float g_ln1[TOKS * DMODEL];
__device__ float g_ln2[TOKS * DMODEL];
__device__ float g_q[TOKS * DMODEL];   // [B*H, S, dk]
__device__ float g_k[TOKS * DMODEL];
__device__ float g_v[TOKS * DMODEL];
__device__ float g_ctx[TOKS * DMODEL]; // [token, H*dk]
__device__ float g_h[TOKS * DFF];
__device__ int   g_flag[1];

// ---------------- helpers ----------------
__device__ __forceinline__ float to_tf32(float x) {
    uint32_t u;
    asm("cvt.rna.tf32.f32 %0, %1;" : "=r"(u) : "f"(x));
    return __uint_as_float(u);
}
__device__ __forceinline__ uint32_t f2u(float x) { return __float_as_uint(x); }

__device__ __forceinline__ void mma8(float* c,
                                     uint32_t a0, uint32_t a1, uint32_t a2, uint32_t a3,
                                     uint32_t b0, uint32_t b1) {
    asm volatile(
        "mma.sync.aligned.m16n8k8.row.col.f32.tf32.tf32.f32 "
        "{%0,%1,%2,%3},{%4,%5,%6,%7},{%8,%9},{%0,%1,%2,%3};"
        : "+f"(c[0]), "+f"(c[1]), "+f"(c[2]), "+f"(c[3])
        : "r"(a0), "r"(a1), "r"(a2), "r"(a3), "r"(b0), "r"(b1));
}

// ---------------- LayerNorm (both norms of same x) ----------------
__global__ void ln_kernel(const float* __restrict__ x,
                          const float* __restrict__ ga1, const float* __restrict__ be1,
                          const float* __restrict__ ga2, const float* __restrict__ be2,
                          float* __restrict__ o1, float* __restrict__ o2) {
    int t = blockIdx.x;
    int tid = threadIdx.x;
    const float4* xr = (const float4*)(x + (size_t)t * DMODEL);
    float4 a = xr[tid];
    float4 bq = xr[tid + 256];
    float s  = a.x + a.y + a.z + a.w + bq.x + bq.y + bq.z + bq.w;
    float s2 = a.x*a.x + a.y*a.y + a.z*a.z + a.w*a.w +
               bq.x*bq.x + bq.y*bq.y + bq.z*bq.z + bq.w*bq.w;
    #pragma unroll
    for (int o = 16; o; o >>= 1) {
        s  += __shfl_xor_sync(0xffffffffu, s,  o);
        s2 += __shfl_xor_sync(0xffffffffu, s2, o);
    }
    __shared__ float rs[8], rs2[8], stats[2];
    if ((tid & 31) == 0) { rs[tid >> 5] = s; rs2[tid >> 5] = s2; }
    __syncthreads();
    if (tid == 0) {
        float S = 0.f, S2 = 0.f;
        for (int i = 0; i < 8; i++) { S += rs[i]; S2 += rs2[i]; }
        float mu = S * (1.0f / DMODEL);
        float var = S2 * (1.0f / DMODEL) - mu * mu;
        stats[0] = mu;
        stats[1] = rsqrtf(var + 1e-5f);
    }
    __syncthreads();
    float mu = stats[0], r = stats[1];
    const float4* G1 = (const float4*)ga1;
    const float4* B1 = (const float4*)be1;
    const float4* G2 = (const float4*)ga2;
    const float4* B2 = (const float4*)be2;
    float4* O1 = (float4*)(o1 + (size_t)t * DMODEL);
    float4* O2 = (float4*)(o2 + (size_t)t * DMODEL);
    #pragma unroll
    for (int i = 0; i < 2; i++) {
        int idx = tid + i * 256;
        float4 v = (i == 0) ? a : bq;
        float nx = (v.x - mu) * r, ny = (v.y - mu) * r, nz = (v.z - mu) * r, nw = (v.w - mu) * r;
        float4 g1v = G1[idx], b1v = B1[idx], g2v = G2[idx], b2v = B2[idx];
        float4 w1o, w2o;
        w1o.x = to_tf32(nx * g1v.x + b1v.x); w1o.y = to_tf32(ny * g1v.y + b1v.y);
        w1o.z = to_tf32(nz * g1v.z + b1v.z); w1o.w = to_tf32(nw * g1v.w + b1v.w);
        w2o.x = to_tf32(nx * g2v.x + b2v.x); w2o.y = to_tf32(ny * g2v.y + b2v.y);
        w2o.z = to_tf32(nz * g2v.z + b2v.z); w2o.w = to_tf32(nw * g2v.w + b2v.w);
        O1[idx] = w1o;
        O2[idx] = w2o;
    }
}

// ---------------- mask flag ----------------
__global__ void flag_init(int* flag) { if (threadIdx.x == 0) flag[0] = 1; }

__global__ void mask_reduce(const int* __restrict__ mask, int n, int* __restrict__ flag) {
    bool bad = false;
    for (int i = blockIdx.x * blockDim.x + threadIdx.x; i < n; i += gridDim.x * blockDim.x)
        if (mask[i] == 0) bad = true;
    if (bad) flag[0] = 0;
}

// ---------------- generic TF32 GEMM with fused epilogues ----------------
struct Epi {
    const float* c0;
    const float* c1;
    float* o0;
    float* o1;
    float* o2;
};

template <int E>
__device__ __forceinline__ void emit(int r, int c, int N, float v, const Epi& e) {
    if (E == 0) {               // QKV head split
        int which = c >> 11, rem = c & 2047, h = rem >> 7, d = rem & 127;
        int b = r >> 11, s = r & 2047;
        float* dst = (which == 0) ? e.o0 : ((which == 1) ? e.o1 : e.o2);
        dst[(size_t)((b << 4) + h) * (SEQ * DKH) + (size_t)s * DKH + d] = v;
    } else if (E == 1) {        // out = x + attn_out
        size_t i = (size_t)r * N + c;
        e.o0[i] = e.c0[i] + v;
    } else if (E == 2) {        // h = gelu(acc + b1), exact erf
        float t = v + e.c0[c];
        e.o0[(size_t)r * N + c] = 0.5f * t * (1.0f + erff(t * 0.70710678118654752f));
    } else {                    // out += layer_scale * (acc + b2)
        size_t i = (size_t)r * N + c;
        e.o0[i] += e.c1[c] * (v + e.c0[c]);
    }
}

template <int E>
__global__ __launch_bounds__(256)
void gemm_tf32(const float* __restrict__ A, const float* __restrict__ B,
               int M, int N, int K, Epi e) {
    __shared__ float As[128][20];    // stride 20 -> conflict-free A fragments
    __shared__ float Bs[16][136];    // stride 136 -> conflict-free B fragments
    int tid = threadIdx.x, warp = tid >> 5, lane = tid & 31;
    int g = lane >> 2, tq = lane & 3;
    int wm = (warp >> 2) * 64, wn = (warp & 3) * 32;
    int bm = blockIdx.y * 128, bn = blockIdx.x * 128;

    float acc[4][4][4];
    #pragma unroll
    for (int i = 0; i < 4; i++)
        #pragma unroll
        for (int j = 0; j < 4; j++)
            #pragma unroll
            for (int k = 0; k < 4; k++) acc[i][j][k] = 0.f;

    for (int k0 = 0; k0 < K; k0 += 16) {
        #pragma unroll
        for (int i = 0; i < 2; i++) {
            int f = tid + i * 256;
            int r = f >> 2, c = (f & 3) << 2;
            const float4 v = *(const float4*)(A + (size_t)(bm + r) * K + k0 + c);
            As[r][c]     = to_tf32(v.x);
            As[r][c + 1] = to_tf32(v.y);
            As[r][c + 2] = to_tf32(v.z);
            As[r][c + 3] = to_tf32(v.w);
        }
        #pragma unroll
        for (int i = 0; i < 2; i++) {
            int f = tid + i * 256;
            int r = f >> 5, c = (f & 31) << 2;
            const float4 v = *(const float4*)(B + (size_t)(k0 + r) * N + bn + c);
            Bs[r][c]     = to_tf32(v.x);
            Bs[r][c + 1] = to_tf32(v.y);
            Bs[r][c + 2] = to_tf32(v.z);
            Bs[r][c + 3] = to_tf32(v.w);
        }
        __syncthreads();
        #pragma unroll
        for (int kk = 0; kk < 2; kk++) {
            int kb = kk * 8;
            uint32_t a[4][4], b[4][2];
            #pragma unroll
            for (int mi = 0; mi < 4; mi++) {
                int r0 = wm + mi * 16 + g;
                a[mi][0] = f2u(As[r0][kb + tq]);
                a[mi][1] = f2u(As[r0 + 8][kb + tq]);
                a[mi][2] = f2u(As[r0][kb + tq + 4]);
                a[mi][3] = f2u(As[r0 + 8][kb + tq + 4]);
            }
            #pragma unroll
            for (int ni = 0; ni < 4; ni++) {
                int cc = wn + ni * 8 + g;
                b[ni][0] = f2u(Bs[kb + tq][cc]);
                b[ni][1] = f2u(Bs[kb + tq + 4][cc]);
            }
            #pragma unroll
            for (int mi = 0; mi < 4; mi++)
                #pragma unroll
                for (int ni = 0; ni < 4; ni++)
                    mma8(acc[mi][ni], a[mi][0], a[mi][1], a[mi][2], a[mi][3],
                         b[ni][0], b[ni][1]);
        }
        __syncthreads();
    }

    #pragma unroll
    for (int mi = 0; mi < 4; mi++) {
        int r0 = bm + wm + mi * 16 + g;
        #pragma unroll
        for (int ni = 0; ni < 4; ni++) {
            int c0 = bn + wn + ni * 8 + tq * 2;
            emit<E>(r0,     c0,     N, acc[mi][ni][0], e);
            emit<E>(r0,     c0 + 1, N, acc[mi][ni][1], e);
            emit<E>(r0 + 8, c0,     N, acc[mi][ni][2], e);
            emit<E>(r0 + 8, c0 + 1, N, acc[mi][ni][3], e);
        }
    }
}

// ---------------- flash attention (64q x 64k tiles, tf32 mma) ----------------
#define KS_STR 132
#define VS_STR 136
#define PS_STR 68
#define ATTN_SMEM ((64 * KS_STR + 64 * VS_STR + 4 * 16 * PS_STR) * 4)

__global__ __launch_bounds__(128, 2)
void attn_kernel(const float* __restrict__ Q, const float* __restrict__ K,
                 const float* __restrict__ V, const int* __restrict__ mask,
                 const int* __restrict__ flag, float* __restrict__ ctx) {
    extern __shared__ float sm[];
    float* Ks = sm;
    float* Vs = sm + 64 * KS_STR;
    float* Ps = Vs + 64 * VS_STR;
    int tid = threadIdx.x, warp = tid >> 5, lane = tid & 31;
    int g = lane >> 2, tq = lane & 3;
    int qt = blockIdx.x, bh = blockIdx.y;
    int b = bh >> 4, h = bh & 15;
    const float* Qb = Q + (size_t)bh * SEQ * DKH;
    const float* Kb = K + (size_t)bh * SEQ * DKH;
    const float* Vb = V + (size_t)bh * SEQ * DKH;
    int q0 = qt * 64 + warp * 16;
    int allv = flag[0];
    float* Pw = Ps + warp * 16 * PS_STR;

    // Q fragments in registers (reused over all 32 KV tiles)
    uint32_t qa[16][4];
    #pragma unroll
    for (int ks = 0; ks < 16; ks++) {
        int kc = ks * 8 + tq;
        qa[ks][0] = f2u(to_tf32(Qb[(size_t)(q0 + g) * DKH + kc]));
        qa[ks][1] = f2u(to_tf32(Qb[(size_t)(q0 + g + 8) * DKH + kc]));
        qa[ks][2] = f2u(to_tf32(Qb[(size_t)(q0 + g) * DKH + kc + 4]));
        qa[ks][3] = f2u(to_tf32(Qb[(size_t)(q0 + g + 8) * DKH + kc + 4]));
    }

    float o[16][4];
    #pragma unroll
    for (int i = 0; i < 16; i++)
        #pragma unroll
        for (int j = 0; j < 4; j++) o[i][j] = 0.f;
    float mA = -1e30f, mB = -1e30f, lA = 0.f, lB = 0.f;

    for (int j = 0; j < 32; j++) {
        // load K/V tiles (tf32-rounded)
        #pragma unroll
        for (int i = 0; i < 16; i++) {
            int f = tid + i * 128;
            int r = f >> 5, c = (f & 31) << 2;
            float4 kv = *(const float4*)(Kb + (size_t)(j * 64 + r) * DKH + c);
            Ks[r * KS_STR + c]     = to_tf32(kv.x);
            Ks[r * KS_STR + c + 1] = to_tf32(kv.y);
            Ks[r * KS_STR + c + 2] = to_tf32(kv.z);
            Ks[r * KS_STR + c + 3] = to_tf32(kv.w);
            float4 vv = *(const float4*)(Vb + (size_t)(j * 64 + r) * DKH + c);
            Vs[r * VS_STR + c]     = to_tf32(vv.x);
            Vs[r * VS_STR + c + 1] = to_tf32(vv.y);
            Vs[r * VS_STR + c + 2] = to_tf32(vv.z);
            Vs[r * VS_STR + c + 3] = to_tf32(vv.w);
        }
        __syncthreads();

        // S = Q @ K^T
        float sc[8][4];
        #pragma unroll
        for (int ni = 0; ni < 8; ni++)
            #pragma unroll
            for (int c = 0; c < 4; c++) sc[ni][c] = 0.f;
        #pragma unroll
        for (int ks = 0; ks < 16; ks++) {
            #pragma unroll
            for (int ni = 0; ni < 8; ni++) {
                uint32_t b0 = f2u(Ks[(ni * 8 + g) * KS_STR + ks * 8 + tq]);
                uint32_t b1 = f2u(Ks[(ni * 8 + g) * KS_STR + ks * 8 + tq + 4]);
                mma8(sc[ni], qa[ks][0], qa[ks][1], qa[ks][2], qa[ks][3], b0, b1);
            }
        }
        const float sscale = 0.0883883476483184f;  // 1/sqrt(128)
        #pragma unroll
        for (int ni = 0; ni < 8; ni++)
            #pragma unroll
            for (int c = 0; c < 4; c++) sc[ni][c] *= sscale;

        if (!allv) {  // cold path; mask is all-visible in this problem
            #pragma unroll
            for (int ni = 0; ni < 8; ni++) {
                int kc = j * 64 + ni * 8 + tq * 2;
                int r0 = q0 + g, r1 = q0 + g + 8;
                if (mask[(size_t)r0 * SEQ + kc] == 0)     sc[ni][0] = -1e9f;
                if (mask[(size_t)r0 * SEQ + kc + 1] == 0) sc[ni][1] = -1e9f;
                if (mask[(size_t)r1 * SEQ + kc] == 0)     sc[ni][2] = -1e9f;
                if (mask[(size_t)r1 * SEQ + kc + 1] == 0) sc[ni][3] = -1e9f;
            }
        }

        // online softmax
        float mxA = -1e30f, mxB = -1e30f;
        #pragma unroll
        for (int ni = 0; ni < 8; ni++) {
            mxA = fmaxf(mxA, fmaxf(sc[ni][0], sc[ni][1]));
            mxB = fmaxf(mxB, fmaxf(sc[ni][2], sc[ni][3]));
        }
        mxA = fmaxf(mxA, __shfl_xor_sync(0xffffffffu, mxA, 1));
        mxA = fmaxf(mxA, __shfl_xor_sync(0xffffffffu, mxA, 2));
        mxB = fmaxf(mxB, __shfl_xor_sync(0xffffffffu, mxB, 1));
        mxB = fmaxf(mxB, __shfl_xor_sync(0xffffffffu, mxB, 2));
        float mAn = fmaxf(mA, mxA), mBn = fmaxf(mB, mxB);
        float aA = __expf(mA - mAn), aB = __expf(mB - mBn);
        float sA = 0.f, sB = 0.f;
        #pragma unroll
        for (int ni = 0; ni < 8; ni++) {
            sc[ni][0] = to_tf32(__expf(sc[ni][0] - mAn)); sA += sc[ni][0];
            sc[ni][1] = to_tf32(__expf(sc[ni][1] - mAn)); sA += sc[ni][1];
            sc[ni][2] = to_tf32(__expf(sc[ni][2] - mBn)); sB += sc[ni][2];
            sc[ni][3] = to_tf32(__expf(sc[ni][3] - mBn)); sB += sc[ni][3];
        }
        sA += __shfl_xor_sync(0xffffffffu, sA, 1);
        sA += __shfl_xor_sync(0xffffffffu, sA, 2);
        sB += __shfl_xor_sync(0xffffffffu, sB, 1);
        sB += __shfl_xor_sync(0xffffffffu, sB, 2);
        lA = lA * aA + sA;
        lB = lB * aB + sB;
        mA = mAn; mB = mBn;
        #pragma unroll
        for (int ni = 0; ni < 16; ni++) {
            o[ni][0] *= aA; o[ni][1] *= aA;
            o[ni][2] *= aB; o[ni][3] *= aB;
        }

        // P -> smem (relayout accum -> A-fragment)
        #pragma unroll
        for (int ni = 0; ni < 8; ni++) {
            int c = ni * 8 + tq * 2;
            Pw[g * PS_STR + c]           = sc[ni][0];
            Pw[g * PS_STR + c + 1]       = sc[ni][1];
            Pw[(g + 8) * PS_STR + c]     = sc[ni][2];
            Pw[(g + 8) * PS_STR + c + 1] = sc[ni][3];
        }
        __syncwarp();

        // O += P @ V
        #pragma unroll
        for (int ks = 0; ks < 8; ks++) {
            uint32_t a0 = f2u(Pw[g * PS_STR + ks * 8 + tq]);
            uint32_t a1 = f2u(Pw[(g + 8) * PS_STR + ks * 8 + tq]);
            uint32_t a2 = f2u(Pw[g * PS_STR + ks * 8 + tq + 4]);
            uint32_t a3 = f2u(Pw[(g + 8) * PS_STR + ks * 8 + tq + 4]);
            #pragma unroll
            for (int ni = 0; ni < 16; ni++) {
                uint32_t b0 = f2u(Vs[(ks * 8 + tq) * VS_STR + ni * 8 + g]);
                uint32_t b1 = f2u(Vs[(ks * 8 + tq + 4) * VS_STR + ni * 8 + g]);
                mma8(o[ni], a0, a1, a2, a3, b0, b1);
            }
        }
        __syncthreads();
    }

    float rA = 1.f / lA, rB = 1.f / lB;
    int tok0 = b * SEQ + q0 + g, tok1 = tok0 + 8;
    #pragma unroll
    for (int ni = 0; ni < 16; ni++) {
        int d = ni * 8 + tq * 2;
        size_t i0 = (size_t)tok0 * DMODEL + h * DKH + d;
        size_t i1 = (size_t)tok1 * DMODEL + h * DKH + d;
        ctx[i0]     = o[ni][0] * rA;
        ctx[i0 + 1] = o[ni][1] * rA;
        ctx[i1]     = o[ni][2] * rB;
        ctx[i1 + 1] = o[ni][3] * rB;
    }
}

// ---------------- launch ----------------
extern "C" void kernel_launch(void* const* d_in, const int* in_sizes, int n_in,
                              void* d_out, int out_size) {
    const float* x     = (const float*)d_in[0];
    const int*   mask  = (const int*)d_in[1];
    const float* w_qkv = (const float*)d_in[2];
    const float* w_o   = (const float*)d_in[3];
    const float* ga1   = (const float*)d_in[4];
    const float* be1   = (const float*)d_in[5];
    const float* ga2   = (const float*)d_in[6];
    const float* be2   = (const float*)d_in[7];
    const float* w1    = (const float*)d_in[8];
    const float* b1    = (const float*)d_in[9];
    const float* w2    = (const float*)d_in[10];
    const float* b2    = (const float*)d_in[11];
    const float* ls    = (const float*)d_in[12];
    float* out = (float*)d_out;

    float *ln1, *ln2, *q, *k, *v, *ctx, *hbuf;
    int* flag;
    cudaGetSymbolAddress((void**)&ln1,  g_ln1);
    cudaGetSymbolAddress((void**)&ln2,  g_ln2);
    cudaGetSymbolAddress((void**)&q,    g_q);
    cudaGetSymbolAddress((void**)&k,    g_k);
    cudaGetSymbolAddress((void**)&v,    g_v);
    cudaGetSymbolAddress((void**)&ctx,  g_ctx);
    cudaGetSymbolAddress((void**)&hbuf, g_h);
    cudaGetSymbolAddress((void**)&flag, g_flag);

    cudaFuncSetAttribute(attn_kernel, cudaFuncAttributeMaxDynamicSharedMemorySize, ATTN_SMEM);

    // layernorms (both on x)
    ln_kernel<<<TOKS, 256>>>(x, ga1, be1, ga2, be2, ln1, ln2);

    // mask all-visible flag
    flag_init<<<1, 32>>>(flag);
    mask_reduce<<<256, 256>>>(mask, in_sizes[1], flag);

    // QKV projection: [4096,2048] @ [2048,6144] -> q/k/v head layout
    Epi e1; e1.c0 = nullptr; e1.c1 = nullptr; e1.o0 = q; e1.o1 = k; e1.o2 = v;
    gemm_tf32<0><<<dim3(48, 32), 256>>>(ln1, w_qkv, TOKS, 3 * DMODEL, DMODEL, e1);

    // attention
    attn_kernel<<<dim3(32, 32), 128, ATTN_SMEM>>>(q, k, v, mask, flag, ctx);

    // output projection + residual with x: out = x + ctx @ w_o
    Epi e2; e2.c0 = x; e2.c1 = nullptr; e2.o0 = out; e2.o1 = nullptr; e2.o2 = nullptr;
    gemm_tf32<1><<<dim3(16, 32), 256>>>(ctx, w_o, TOKS, DMODEL, DMODEL, e2);

    // FF1 + exact gelu
    Epi e3; e3.c0 = b1; e3.c1 = nullptr; e3.o0 = hbuf; e3.o1 = nullptr; e3.o2 = nullptr;
    gemm_tf32<2><<<dim3(64, 32), 256>>>(ln2, w1, TOKS, DFF, DMODEL, e3);

    // FF2 + bias + layer_scale, accumulate into out
    Epi e4; e4.c0 = b2; e4.c1 = ls; e4.o0 = out; e4.o1 = nullptr; e4.o2 = nullptr;
    gemm_tf32<3><<<dim3(16, 32), 256>>>(hbuf, w2, TOKS, DMODEL, DFF, e4);
}

// round 4
// speedup vs baseline: 1.8260x; 1.8249x over previous
#include <cuda_runtime.h>
#include <cuda_bf16.h>
#include <cstdint>
#include <cmath>

// ---------------- problem constants ----------------
#define TOKS 4096
#define DMODEL 2048
#define DFF 8192
#define NHEADS 16
#define DKH 128
#define SEQ 2048
#define BATCH 2

// ---------------- scratch (device globals) ----------------
__device__ __align__(128) __nv_bfloat16 g_ln1[TOKS * DMODEL];
__device__ __align__(128) __nv_bfloat16 g_ln2[TOKS * DMODEL];
__device__ __align__(128) __nv_bfloat16 g_q[TOKS * DMODEL];
__device__ __align__(128) __nv_bfloat16 g_k[TOKS * DMODEL];
__device__ __align__(128) __nv_bfloat16 g_v[TOKS * DMODEL];
__device__ __align__(128) __nv_bfloat16 g_ctx[TOKS * DMODEL];
__device__ __align__(128) __nv_bfloat16 g_h[TOKS * DFF];
__device__ __align__(128) __nv_bfloat16 g_wqkv[DMODEL * 3 * DMODEL];
__device__ __align__(128) __nv_bfloat16 g_wo[DMODEL * DMODEL];
__device__ __align__(128) __nv_bfloat16 g_w1[DMODEL * DFF];
__device__ __align__(128) __nv_bfloat16 g_w2[DFF * DMODEL];
__device__ int g_flag[1];

// ---------------- helpers ----------------
__device__ __forceinline__ float to_tf32(float x) {
    uint32_t u;
    asm("cvt.rna.tf32.f32 %0, %1;" : "=r"(u) : "f"(x));
    return __uint_as_float(u);
}
__device__ __forceinline__ uint32_t f2u(float x) { return __float_as_uint(x); }

__device__ __forceinline__ uint32_t smem_u32(const void* p) {
    uint32_t a;
    asm("{ .reg .u64 t; cvta.to.shared.u64 t, %1; cvt.u32.u64 %0, t; }"
        : "=r"(a) : "l"(p));
    return a;
}

#define CP16(dst, src) \
    asm volatile("cp.async.cg.shared.global [%0], [%1], 16;" \
                 :: "r"(dst), "l"(src) : "memory")
#define CP_COMMIT() asm volatile("cp.async.commit_group;" ::: "memory")
#define CP_WAIT1()  asm volatile("cp.async.wait_group 1;" ::: "memory")

#define LDSM_X4(r, addr) \
    asm volatile("ldmatrix.sync.aligned.m8n8.x4.shared.b16 {%0,%1,%2,%3}, [%4];" \
        : "=r"((r)[0]), "=r"((r)[1]), "=r"((r)[2]), "=r"((r)[3]) : "r"(addr))
#define LDSM_X4T(r, addr) \
    asm volatile("ldmatrix.sync.aligned.m8n8.x4.trans.shared.b16 {%0,%1,%2,%3}, [%4];" \
        : "=r"((r)[0]), "=r"((r)[1]), "=r"((r)[2]), "=r"((r)[3]) : "r"(addr))

__device__ __forceinline__ void mma16(float* c, const uint32_t* a, uint32_t b0, uint32_t b1) {
    asm volatile(
        "mma.sync.aligned.m16n8k16.row.col.f32.bf16.bf16.f32 "
        "{%0,%1,%2,%3},{%4,%5,%6,%7},{%8,%9},{%0,%1,%2,%3};"
        : "+f"(c[0]), "+f"(c[1]), "+f"(c[2]), "+f"(c[3])
        : "r"(a[0]), "r"(a[1]), "r"(a[2]), "r"(a[3]), "r"(b0), "r"(b1));
}

__device__ __forceinline__ void mma8(float* c,
                                     uint32_t a0, uint32_t a1, uint32_t a2, uint32_t a3,
                                     uint32_t b0, uint32_t b1) {
    asm volatile(
        "mma.sync.aligned.m16n8k8.row.col.f32.tf32.tf32.f32 "
        "{%0,%1,%2,%3},{%4,%5,%6,%7},{%8,%9},{%0,%1,%2,%3};"
        : "+f"(c[0]), "+f"(c[1]), "+f"(c[2]), "+f"(c[3])
        : "r"(a0), "r"(a1), "r"(a2), "r"(a3), "r"(b0), "r"(b1));
}

// ---------------- fp32 -> bf16 converter ----------------
__global__ void cvt_kernel(const float* __restrict__ in, __nv_bfloat16* __restrict__ out, int n) {
    int i = (blockIdx.x * blockDim.x + threadIdx.x) * 4;
    if (i < n) {
        float4 v = *(const float4*)(in + i);
        *(__nv_bfloat162*)(out + i)     = __floats2bfloat162_rn(v.x, v.y);
        *(__nv_bfloat162*)(out + i + 2) = __floats2bfloat162_rn(v.z, v.w);
    }
}

// ---------------- LayerNorm: fp32 x -> bf16 ln1, ln2 ----------------
__global__ void ln_kernel(const float* __restrict__ x,
                          const float* __restrict__ ga1, const float* __restrict__ be1,
                          const float* __restrict__ ga2, const float* __restrict__ be2,
                          __nv_bfloat16* __restrict__ o1, __nv_bfloat16* __restrict__ o2) {
    int t = blockIdx.x;
    int tid = threadIdx.x;
    const float4* xr = (const float4*)(x + (size_t)t * DMODEL);
    float4 a = xr[tid];
    float4 bq = xr[tid + 256];
    float s  = a.x + a.y + a.z + a.w + bq.x + bq.y + bq.z + bq.w;
    float s2 = a.x*a.x + a.y*a.y + a.z*a.z + a.w*a.w +
               bq.x*bq.x + bq.y*bq.y + bq.z*bq.z + bq.w*bq.w;
    #pragma unroll
    for (int o = 16; o; o >>= 1) {
        s  += __shfl_xor_sync(0xffffffffu, s,  o);
        s2 += __shfl_xor_sync(0xffffffffu, s2, o);
    }
    __shared__ float rs[8], rs2[8], stats[2];
    if ((tid & 31) == 0) { rs[tid >> 5] = s; rs2[tid >> 5] = s2; }
    __syncthreads();
    if (tid == 0) {
        float S = 0.f, S2 = 0.f;
        for (int i = 0; i < 8; i++) { S += rs[i]; S2 += rs2[i]; }
        float mu = S * (1.0f / DMODEL);
        float var = S2 * (1.0f / DMODEL) - mu * mu;
        stats[0] = mu;
        stats[1] = rsqrtf(var + 1e-5f);
    }
    __syncthreads();
    float mu = stats[0], r = stats[1];
    const float4* G1 = (const float4*)ga1;
    const float4* B1 = (const float4*)be1;
    const float4* G2 = (const float4*)ga2;
    const float4* B2 = (const float4*)be2;
    __nv_bfloat162* O1 = (__nv_bfloat162*)(o1 + (size_t)t * DMODEL);
    __nv_bfloat162* O2 = (__nv_bfloat162*)(o2 + (size_t)t * DMODEL);
    #pragma unroll
    for (int i = 0; i < 2; i++) {
        int idx = tid + i * 256;
        float4 v = (i == 0) ? a : bq;
        float nx = (v.x - mu) * r, ny = (v.y - mu) * r, nz = (v.z - mu) * r, nw = (v.w - mu) * r;
        float4 g1v = G1[idx], b1v = B1[idx], g2v = G2[idx], b2v = B2[idx];
        O1[idx * 2]     = __floats2bfloat162_rn(nx * g1v.x + b1v.x, ny * g1v.y + b1v.y);
        O1[idx * 2 + 1] = __floats2bfloat162_rn(nz * g1v.z + b1v.z, nw * g1v.w + b1v.w);
        O2[idx * 2]     = __floats2bfloat162_rn(nx * g2v.x + b2v.x, ny * g2v.y + b2v.y);
        O2[idx * 2 + 1] = __floats2bfloat162_rn(nz * g2v.z + b2v.z, nw * g2v.w + b2v.w);
    }
}

// ---------------- mask flag ----------------
__global__ void flag_init(int* flag) { if (threadIdx.x == 0) flag[0] = 1; }

__global__ void mask_reduce(const int* __restrict__ mask, int n, int* __restrict__ flag) {
    bool bad = false;
    for (int i = blockIdx.x * blockDim.x + threadIdx.x; i < n; i += gridDim.x * blockDim.x)
        if (mask[i] == 0) bad = true;
    if (bad) flag[0] = 0;
}

// ================= bf16 GEMM: 128x256x32 tiles, ldmatrix + cp.async =================
// A [M,K] bf16 row-major; B [K,N] bf16 row-major.
// smem: A rows padded to 40 b16 (80B), B rows padded to 264 b16 (528B).
#define A_BYTES 10240            // 128 * 80
#define B_BYTES 16896            // 32 * 528
#define STAGE   27136
#define NSTAGE  3
#define SMEM_GEMM (STAGE * NSTAGE)

struct Epi {
    const float* c0;
    const float* c1;
    float* o0;
    __nv_bfloat16* bo0;
    __nv_bfloat16* bo1;
    __nv_bfloat16* bo2;
};

template <int E>
__device__ __forceinline__ void emit2(int r, int c, int N, float v0, float v1, const Epi& e) {
    if (E == 0) {               // QKV head split -> bf16 [B*H, S, dk]
        int which = c >> 11, hh = (c >> 7) & 15, d0 = c & 127;
        __nv_bfloat16* dst = (which == 0) ? e.bo0 : ((which == 1) ? e.bo1 : e.bo2);
        int b = r >> 11, s = r & 2047;
        __nv_bfloat16* p = dst + (size_t)((b << 4) + hh) * (SEQ * DKH) + (size_t)s * DKH + d0;
        *(__nv_bfloat162*)p = __floats2bfloat162_rn(v0, v1);
    } else if (E == 1) {        // out = x + attn_out (fp32)
        size_t i = (size_t)r * N + c;
        float2 xv = *(const float2*)(e.c0 + i);
        float2 o;
        o.x = xv.x + v0;
        o.y = xv.y + v1;
        *(float2*)(e.o0 + i) = o;
    } else if (E == 2) {        // h = bf16(gelu(acc + b1)), exact erf
        const float is2 = 0.70710678118654752f;
        float t0 = v0 + e.c0[c], t1 = v1 + e.c0[c + 1];
        float g0 = 0.5f * t0 * (1.0f + erff(t0 * is2));
        float g1 = 0.5f * t1 * (1.0f + erff(t1 * is2));
        __nv_bfloat16* p = e.bo0 + (size_t)r * N + c;
        *(__nv_bfloat162*)p = __floats2bfloat162_rn(g0, g1);
    } else {                    // out += layer_scale * (acc + b2)  (fp32 RMW)
        size_t i = (size_t)r * N + c;
        float2 bb = *(const float2*)(e.c0 + c);
        float2 ls = *(const float2*)(e.c1 + c);
        float2 o  = *(const float2*)(e.o0 + i);
        o.x += ls.x * (v0 + bb.x);
        o.y += ls.y * (v1 + bb.y);
        *(float2*)(e.o0 + i) = o;
    }
}

__device__ __forceinline__ void gemm_load_stage(const __nv_bfloat16* A, const __nv_bfloat16* B,
                                                int K, int N, int bm, int bn, int kt,
                                                uint32_t base, int tid) {
    #pragma unroll
    for (int t = 0; t < 2; t++) {
        int c = tid + t * 256;
        int row = c >> 2, k8 = c & 3;
        const __nv_bfloat16* src = A + (size_t)(bm + row) * K + kt * 32 + k8 * 8;
        CP16(base + (uint32_t)row * 80 + (uint32_t)k8 * 16, src);
    }
    #pragma unroll
    for (int t = 0; t < 4; t++) {
        int c = tid + t * 256;
        int row = c >> 5, n8 = c & 31;
        const __nv_bfloat16* src = B + (size_t)(kt * 32 + row) * N + bn + n8 * 8;
        CP16(base + A_BYTES + (uint32_t)row * 528 + (uint32_t)n8 * 16, src);
    }
    CP_COMMIT();
}

template <int E>
__global__ __launch_bounds__(256, 1)
void gemm_bf16(const __nv_bfloat16* __restrict__ A, const __nv_bfloat16* __restrict__ B,
               int M, int N, int K, Epi e) {
    extern __shared__ __align__(128) char smc[];
    uint32_t smb = smem_u32(smc);
    int tid = threadIdx.x, warp = tid >> 5, lane = tid & 31;
    int bm = blockIdx.y * 128, bn = blockIdx.x * 256;
    int wm = (warp >> 2) * 64, wn = (warp & 3) * 64;
    const int nt = K >> 5;

    float acc[4][8][4];
    #pragma unroll
    for (int i = 0; i < 4; i++)
        #pragma unroll
        for (int j = 0; j < 8; j++)
            #pragma unroll
            for (int k = 0; k < 4; k++) acc[i][j][k] = 0.f;

    // prologue: stages 0 and 1
    gemm_load_stage(A, B, K, N, bm, bn, 0, smb, tid);
    gemm_load_stage(A, B, K, N, bm, bn, 1, smb + STAGE, tid);

    int frow = (lane & 7) + ((lane >> 3) & 1) * 8;   // row-within-16 for ldmatrix
    int hi = lane >> 4;                               // 0/1: second 8-col group

    for (int i = 0; i < nt; i++) {
        CP_WAIT1();
        __syncthreads();
        if (i + 2 < nt)
            gemm_load_stage(A, B, K, N, bm, bn, i + 2, smb + (uint32_t)((i + 2) % 3) * STAGE, tid);

        uint32_t abase = smb + (uint32_t)(i % 3) * STAGE;
        uint32_t bbase = abase + A_BYTES;
        #pragma unroll
        for (int k16 = 0; k16 < 2; k16++) {
            uint32_t a[4][4], bf[4][4];
            #pragma unroll
            for (int mt = 0; mt < 4; mt++) {
                uint32_t ad = abase + (uint32_t)(wm + mt * 16 + frow) * 80
                            + (uint32_t)(k16 * 2 + hi) * 16;
                LDSM_X4(a[mt], ad);
            }
            #pragma unroll
            for (int nt16 = 0; nt16 < 4; nt16++) {
                uint32_t bd = bbase + (uint32_t)(k16 * 16 + frow) * 528
                            + (uint32_t)(((wn + nt16 * 16) >> 3) + hi) * 16;
                LDSM_X4T(bf[nt16], bd);
            }
            #pragma unroll
            for (int mt = 0; mt < 4; mt++)
                #pragma unroll
                for (int n8 = 0; n8 < 8; n8++)
                    mma16(acc[mt][n8], a[mt], bf[n8 >> 1][(n8 & 1) * 2], bf[n8 >> 1][(n8 & 1) * 2 + 1]);
        }
    }

    int g = lane >> 2, tq = lane & 3;
    #pragma unroll
    for (int mt = 0; mt < 4; mt++) {
        int r0 = bm + wm + mt * 16 + g;
        #pragma unroll
        for (int n8 = 0; n8 < 8; n8++) {
            int c0 = bn + wn + n8 * 8 + tq * 2;
            emit2<E>(r0,     c0, N, acc[mt][n8][0], acc[mt][n8][1], e);
            emit2<E>(r0 + 8, c0, N, acc[mt][n8][2], acc[mt][n8][3], e);
        }
    }
}

// ---------------- flash attention (bf16 in, tf32 mma, bf16 ctx out) ----------------
#define KS_STR 132
#define VS_STR 136
#define PS_STR 68
#define ATTN_SMEM ((64 * KS_STR + 64 * VS_STR + 4 * 16 * PS_STR) * 4)

__global__ __launch_bounds__(128, 2)
void attn_kernel(const __nv_bfloat16* __restrict__ Q, const __nv_bfloat16* __restrict__ K,
                 const __nv_bfloat16* __restrict__ V, const int* __restrict__ mask,
                 const int* __restrict__ flag, __nv_bfloat16* __restrict__ ctx) {
    extern __shared__ float sm[];
    float* Ks = sm;
    float* Vs = sm + 64 * KS_STR;
    float* Ps = Vs + 64 * VS_STR;
    int tid = threadIdx.x, warp = tid >> 5, lane = tid & 31;
    int g = lane >> 2, tq = lane & 3;
    int qt = blockIdx.x, bh = blockIdx.y;
    int b = bh >> 4, h = bh & 15;
    const __nv_bfloat16* Qb = Q + (size_t)bh * SEQ * DKH;
    const __nv_bfloat16* Kb = K + (size_t)bh * SEQ * DKH;
    const __nv_bfloat16* Vb = V + (size_t)bh * SEQ * DKH;
    int q0 = qt * 64 + warp * 16;
    int allv = flag[0];
    float* Pw = Ps + warp * 16 * PS_STR;

    uint32_t qa[16][4];
    #pragma unroll
    for (int ks = 0; ks < 16; ks++) {
        int kc = ks * 8 + tq;
        qa[ks][0] = f2u(__bfloat162float(Qb[(size_t)(q0 + g) * DKH + kc]));
        qa[ks][1] = f2u(__bfloat162float(Qb[(size_t)(q0 + g + 8) * DKH + kc]));
        qa[ks][2] = f2u(__bfloat162float(Qb[(size_t)(q0 + g) * DKH + kc + 4]));
        qa[ks][3] = f2u(__bfloat162float(Qb[(size_t)(q0 + g + 8) * DKH + kc + 4]));
    }

    float o[16][4];
    #pragma unroll
    for (int i = 0; i < 16; i++)
        #pragma unroll
        for (int j = 0; j < 4; j++) o[i][j] = 0.f;
    float mA = -1e30f, mB = -1e30f, lA = 0.f, lB = 0.f;

    for (int j = 0; j < 32; j++) {
        #pragma unroll
        for (int i = 0; i < 16; i++) {
            int f = tid + i * 128;
            int r = f >> 5, c = (f & 31) << 2;
            const __nv_bfloat162* kp = (const __nv_bfloat162*)(Kb + (size_t)(j * 64 + r) * DKH + c);
            float2 k01 = __bfloat1622float2(kp[0]);
            float2 k23 = __bfloat1622float2(kp[1]);
            Ks[r * KS_STR + c]     = k01.x;
            Ks[r * KS_STR + c + 1] = k01.y;
            Ks[r * KS_STR + c + 2] = k23.x;
            Ks[r * KS_STR + c + 3] = k23.y;
            const __nv_bfloat162* vp = (const __nv_bfloat162*)(Vb + (size_t)(j * 64 + r) * DKH + c);
            float2 v01 = __bfloat1622float2(vp[0]);
            float2 v23 = __bfloat1622float2(vp[1]);
            Vs[r * VS_STR + c]     = v01.x;
            Vs[r * VS_STR + c + 1] = v01.y;
            Vs[r * VS_STR + c + 2] = v23.x;
            Vs[r * VS_STR + c + 3] = v23.y;
        }
        __syncthreads();

        float sc[8][4];
        #pragma unroll
        for (int ni = 0; ni < 8; ni++)
            #pragma unroll
            for (int c = 0; c < 4; c++) sc[ni][c] = 0.f;
        #pragma unroll
        for (int ks = 0; ks < 16; ks++) {
            #pragma unroll
            for (int ni = 0; ni < 8; ni++) {
                uint32_t b0 = f2u(Ks[(ni * 8 + g) * KS_STR + ks * 8 + tq]);
                uint32_t b1 = f2u(Ks[(ni * 8 + g) * KS_STR + ks * 8 + tq + 4]);
                mma8(sc[ni], qa[ks][0], qa[ks][1], qa[ks][2], qa[ks][3], b0, b1);
            }
        }
        const float sscale = 0.0883883476483184f;
        #pragma unroll
        for (int ni = 0; ni < 8; ni++)
            #pragma unroll
            for (int c = 0; c < 4; c++) sc[ni][c] *= sscale;

        if (!allv) {
            #pragma unroll
            for (int ni = 0; ni < 8; ni++) {
                int kc = j * 64 + ni * 8 + tq * 2;
                int r0 = q0 + g, r1 = q0 + g + 8;
                if (mask[(size_t)r0 * SEQ + kc] == 0)     sc[ni][0] = -1e9f;
                if (mask[(size_t)r0 * SEQ + kc + 1] == 0) sc[ni][1] = -1e9f;
                if (mask[(size_t)r1 * SEQ + kc] == 0)     sc[ni][2] = -1e9f;
                if (mask[(size_t)r1 * SEQ + kc + 1] == 0) sc[ni][3] = -1e9f;
            }
        }

        float mxA = -1e30f, mxB = -1e30f;
        #pragma unroll
        for (int ni = 0; ni < 8; ni++) {
            mxA = fmaxf(mxA, fmaxf(sc[ni][0], sc[ni][1]));
            mxB = fmaxf(mxB, fmaxf(sc[ni][2], sc[ni][3]));
        }
        mxA = fmaxf(mxA, __shfl_xor_sync(0xffffffffu, mxA, 1));
        mxA = fmaxf(mxA, __shfl_xor_sync(0xffffffffu, mxA, 2));
        mxB = fmaxf(mxB, __shfl_xor_sync(0xffffffffu, mxB, 1));
        mxB = fmaxf(mxB, __shfl_xor_sync(0xffffffffu, mxB, 2));
        float mAn = fmaxf(mA, mxA), mBn = fmaxf(mB, mxB);
        float aA = __expf(mA - mAn), aB = __expf(mB - mBn);
        float sA = 0.f, sB = 0.f;
        #pragma unroll
        for (int ni = 0; ni < 8; ni++) {
            sc[ni][0] = to_tf32(__expf(sc[ni][0] - mAn)); sA += sc[ni][0];
            sc[ni][1] = to_tf32(__expf(sc[ni][1] - mAn)); sA += sc[ni][1];
            sc[ni][2] = to_tf32(__expf(sc[ni][2] - mBn)); sB += sc[ni][2];
            sc[ni][3] = to_tf32(__expf(sc[ni][3] - mBn)); sB += sc[ni][3];
        }
        sA += __shfl_xor_sync(0xffffffffu, sA, 1);
        sA += __shfl_xor_sync(0xffffffffu, sA, 2);
        sB += __shfl_xor_sync(0xffffffffu, sB, 1);
        sB += __shfl_xor_sync(0xffffffffu, sB, 2);
        lA = lA * aA + sA;
        lB = lB * aB + sB;
        mA = mAn; mB = mBn;
        #pragma unroll
        for (int ni = 0; ni < 16; ni++) {
            o[ni][0] *= aA; o[ni][1] *= aA;
            o[ni][2] *= aB; o[ni][3] *= aB;
        }

        #pragma unroll
        for (int ni = 0; ni < 8; ni++) {
            int c = ni * 8 + tq * 2;
            Pw[g * PS_STR + c]           = sc[ni][0];
            Pw[g * PS_STR + c + 1]       = sc[ni][1];
            Pw[(g + 8) * PS_STR + c]     = sc[ni][2];
            Pw[(g + 8) * PS_STR + c + 1] = sc[ni][3];
        }
        __syncwarp();

        #pragma unroll
        for (int ks = 0; ks < 8; ks++) {
            uint32_t a0 = f2u(Pw[g * PS_STR + ks * 8 + tq]);
            uint32_t a1 = f2u(Pw[(g + 8) * PS_STR + ks * 8 + tq]);
            uint32_t a2 = f2u(Pw[g * PS_STR + ks * 8 + tq + 4]);
            uint32_t a3 = f2u(Pw[(g + 8) * PS_STR + ks * 8 + tq + 4]);
            #pragma unroll
            for (int ni = 0; ni < 16; ni++) {
                uint32_t b0 = f2u(Vs[(ks * 8 + tq) * VS_STR + ni * 8 + g]);
                uint32_t b1 = f2u(Vs[(ks * 8 + tq + 4) * VS_STR + ni * 8 + g]);
                mma8(o[ni], a0, a1, a2, a3, b0, b1);
            }
        }
        __syncthreads();
    }

    float rA = 1.f / lA, rB = 1.f / lB;
    int tok0 = b * SEQ + q0 + g, tok1 = tok0 + 8;
    #pragma unroll
    for (int ni = 0; ni < 16; ni++) {
        int d = ni * 8 + tq * 2;
        __nv_bfloat16* p0 = ctx + (size_t)tok0 * DMODEL + h * DKH + d;
        __nv_bfloat16* p1 = ctx + (size_t)tok1 * DMODEL + h * DKH + d;
        *(__nv_bfloat162*)p0 = __floats2bfloat162_rn(o[ni][0] * rA, o[ni][1] * rA);
        *(__nv_bfloat162*)p1 = __floats2bfloat162_rn(o[ni][2] * rB, o[ni][3] * rB);
    }
}

// ---------------- launch ----------------
extern "C" void kernel_launch(void* const* d_in, const int* in_sizes, int n_in,
                              void* d_out, int out_size) {
    const float* x     = (const float*)d_in[0];
    const int*   mask  = (const int*)d_in[1];
    const float* w_qkv = (const float*)d_in[2];
    const float* w_o   = (const float*)d_in[3];
    const float* ga1   = (const float*)d_in[4];
    const float* be1   = (const float*)d_in[5];
    const float* ga2   = (const float*)d_in[6];
    const float* be2   = (const float*)d_in[7];
    const float* w1    = (const float*)d_in[8];
    const float* b1    = (const float*)d_in[9];
    const float* w2    = (const float*)d_in[10];
    const float* b2    = (const float*)d_in[11];
    const float* ls    = (const float*)d_in[12];
    float* out = (float*)d_out;

    __nv_bfloat16 *ln1, *ln2, *q, *k, *v, *ctx, *hbuf, *wqkvb, *wob, *w1b, *w2b;
    int* flag;
    cudaGetSymbolAddress((void**)&ln1,   g_ln1);
    cudaGetSymbolAddress((void**)&ln2,   g_ln2);
    cudaGetSymbolAddress((void**)&q,     g_q);
    cudaGetSymbolAddress((void**)&k,     g_k);
    cudaGetSymbolAddress((void**)&v,     g_v);
    cudaGetSymbolAddress((void**)&ctx,   g_ctx);
    cudaGetSymbolAddress((void**)&hbuf,  g_h);
    cudaGetSymbolAddress((void**)&wqkvb, g_wqkv);
    cudaGetSymbolAddress((void**)&wob,   g_wo);
    cudaGetSymbolAddress((void**)&w1b,   g_w1);
    cudaGetSymbolAddress((void**)&w2b,   g_w2);
    cudaGetSymbolAddress((void**)&flag,  g_flag);

    cudaFuncSetAttribute(attn_kernel, cudaFuncAttributeMaxDynamicSharedMemorySize, ATTN_SMEM);
    cudaFuncSetAttribute(gemm_bf16<0>, cudaFuncAttributeMaxDynamicSharedMemorySize, SMEM_GEMM);
    cudaFuncSetAttribute(gemm_bf16<1>, cudaFuncAttributeMaxDynamicSharedMemorySize, SMEM_GEMM);
    cudaFuncSetAttribute(gemm_bf16<2>, cudaFuncAttributeMaxDynamicSharedMemorySize, SMEM_GEMM);
    cudaFuncSetAttribute(gemm_bf16<3>, cudaFuncAttributeMaxDynamicSharedMemorySize, SMEM_GEMM);

    // weight conversions (fp32 -> bf16)
    cvt_kernel<<<(DMODEL * 3 * DMODEL) / 4 / 256, 256>>>(w_qkv, wqkvb, DMODEL * 3 * DMODEL);
    cvt_kernel<<<(DMODEL * DMODEL) / 4 / 256, 256>>>(w_o, wob, DMODEL * DMODEL);
    cvt_kernel<<<(DMODEL * DFF) / 4 / 256, 256>>>(w1, w1b, DMODEL * DFF);
    cvt_kernel<<<(DFF * DMODEL) / 4 / 256, 256>>>(w2, w2b, DFF * DMODEL);

    // layernorms (both on x) -> bf16
    ln_kernel<<<TOKS, 256>>>(x, ga1, be1, ga2, be2, ln1, ln2);

    // mask all-visible flag
    flag_init<<<1, 32>>>(flag);
    mask_reduce<<<256, 256>>>(mask, in_sizes[1], flag);

    // QKV projection -> bf16 q/k/v in head layout
    Epi e1 = {nullptr, nullptr, nullptr, q, k, v};
    gemm_bf16<0><<<dim3(24, 32), 256, SMEM_GEMM>>>(ln1, wqkvb, TOKS, 3 * DMODEL, DMODEL, e1);

    // attention -> bf16 ctx
    attn_kernel<<<dim3(32, 32), 128, ATTN_SMEM>>>(q, k, v, mask, flag, ctx);

    // output projection + residual with fp32 x: out = x + ctx @ w_o
    Epi e2 = {x, nullptr, out, nullptr, nullptr, nullptr};
    gemm_bf16<1><<<dim3(8, 32), 256, SMEM_GEMM>>>(ctx, wob, TOKS, DMODEL, DMODEL, e2);

    // FF1 + exact gelu -> bf16 h
    Epi e3 = {b1, nullptr, nullptr, hbuf, nullptr, nullptr};
    gemm_bf16<2><<<dim3(32, 32), 256, SMEM_GEMM>>>(ln2, w1b, TOKS, DFF, DMODEL, e3);

    // FF2 + bias + layer_scale, accumulate into out (fp32)
    Epi e4 = {b2, ls, out, nullptr, nullptr, nullptr};
    gemm_bf16<3><<<dim3(8, 32), 256, SMEM_GEMM>>>(hbuf, w2b, TOKS, DMODEL, DFF, e4);
}

// round 5
// speedup vs baseline: 2.1097x; 1.1554x over previous
#include <cuda_runtime.h>
#include <cuda_bf16.h>
#include <cstdint>
#include <cmath>

// ---------------- problem constants ----------------
#define TOKS 4096
#define DMODEL 2048
#define DFF 8192
#define NHEADS 16
#define DKH 128
#define SEQ 2048
#define BATCH 2

// ---------------- scratch (device globals) ----------------
__device__ __align__(128) __nv_bfloat16 g_ln1[TOKS * DMODEL];
__device__ __align__(128) __nv_bfloat16 g_ln2[TOKS * DMODEL];
__device__ __align__(128) __nv_bfloat16 g_q[TOKS * DMODEL];
__device__ __align__(128) __nv_bfloat16 g_k[TOKS * DMODEL];
__device__ __align__(128) __nv_bfloat16 g_v[TOKS * DMODEL];
__device__ __align__(128) __nv_bfloat16 g_ctx[TOKS * DMODEL];
__device__ __align__(128) __nv_bfloat16 g_h[TOKS * DFF];
__device__ __align__(128) __nv_bfloat16 g_wqkv[DMODEL * 3 * DMODEL];
__device__ __align__(128) __nv_bfloat16 g_wo[DMODEL * DMODEL];
__device__ __align__(128) __nv_bfloat16 g_w1[DMODEL * DFF];
__device__ __align__(128) __nv_bfloat16 g_w2[DFF * DMODEL];
__device__ int g_flag[1];

// ---------------- helpers ----------------
__device__ __forceinline__ uint32_t f2u(float x) { return __float_as_uint(x); }

__device__ __forceinline__ uint32_t smem_u32(const void* p) {
    uint32_t a;
    asm("{ .reg .u64 t; cvta.to.shared.u64 t, %1; cvt.u32.u64 %0, t; }"
        : "=r"(a) : "l"(p));
    return a;
}

#define CP16(dst, src) \
    asm volatile("cp.async.cg.shared.global [%0], [%1], 16;" \
                 :: "r"(dst), "l"(src) : "memory")
#define CP_COMMIT() asm volatile("cp.async.commit_group;" ::: "memory")
#define CP_WAIT1()  asm volatile("cp.async.wait_group 1;" ::: "memory")

#define LDSM_X4(r, addr) \
    asm volatile("ldmatrix.sync.aligned.m8n8.x4.shared.b16 {%0,%1,%2,%3}, [%4];" \
        : "=r"((r)[0]), "=r"((r)[1]), "=r"((r)[2]), "=r"((r)[3]) : "r"(addr))
#define LDSM_X4T(r, addr) \
    asm volatile("ldmatrix.sync.aligned.m8n8.x4.trans.shared.b16 {%0,%1,%2,%3}, [%4];" \
        : "=r"((r)[0]), "=r"((r)[1]), "=r"((r)[2]), "=r"((r)[3]) : "r"(addr))

__device__ __forceinline__ void mma16(float* c, const uint32_t* a, uint32_t b0, uint32_t b1) {
    asm volatile(
        "mma.sync.aligned.m16n8k16.row.col.f32.bf16.bf16.f32 "
        "{%0,%1,%2,%3},{%4,%5,%6,%7},{%8,%9},{%0,%1,%2,%3};"
        : "+f"(c[0]), "+f"(c[1]), "+f"(c[2]), "+f"(c[3])
        : "r"(a[0]), "r"(a[1]), "r"(a[2]), "r"(a[3]), "r"(b0), "r"(b1));
}

__device__ __forceinline__ uint32_t pack_bf2(float x, float y) {
    __nv_bfloat162 t = __floats2bfloat162_rn(x, y);
    return *(uint32_t*)&t;
}

// ---------------- fp32 -> bf16 converter ----------------
__global__ void cvt_kernel(const float* __restrict__ in, __nv_bfloat16* __restrict__ out, int n) {
    int i = (blockIdx.x * blockDim.x + threadIdx.x) * 4;
    if (i < n) {
        float4 v = *(const float4*)(in + i);
        *(__nv_bfloat162*)(out + i)     = __floats2bfloat162_rn(v.x, v.y);
        *(__nv_bfloat162*)(out + i + 2) = __floats2bfloat162_rn(v.z, v.w);
    }
}

// ---------------- LayerNorm: fp32 x -> bf16 ln1, ln2 ----------------
__global__ void ln_kernel(const float* __restrict__ x,
                          const float* __restrict__ ga1, const float* __restrict__ be1,
                          const float* __restrict__ ga2, const float* __restrict__ be2,
                          __nv_bfloat16* __restrict__ o1, __nv_bfloat16* __restrict__ o2) {
    int t = blockIdx.x;
    int tid = threadIdx.x;
    const float4* xr = (const float4*)(x + (size_t)t * DMODEL);
    float4 a = xr[tid];
    float4 bq = xr[tid + 256];
    float s  = a.x + a.y + a.z + a.w + bq.x + bq.y + bq.z + bq.w;
    float s2 = a.x*a.x + a.y*a.y + a.z*a.z + a.w*a.w +
               bq.x*bq.x + bq.y*bq.y + bq.z*bq.z + bq.w*bq.w;
    #pragma unroll
    for (int o = 16; o; o >>= 1) {
        s  += __shfl_xor_sync(0xffffffffu, s,  o);
        s2 += __shfl_xor_sync(0xffffffffu, s2, o);
    }
    __shared__ float rs[8], rs2[8], stats[2];
    if ((tid & 31) == 0) { rs[tid >> 5] = s; rs2[tid >> 5] = s2; }
    __syncthreads();
    if (tid == 0) {
        float S = 0.f, S2 = 0.f;
        for (int i = 0; i < 8; i++) { S += rs[i]; S2 += rs2[i]; }
        float mu = S * (1.0f / DMODEL);
        float var = S2 * (1.0f / DMODEL) - mu * mu;
        stats[0] = mu;
        stats[1] = rsqrtf(var + 1e-5f);
    }
    __syncthreads();
    float mu = stats[0], r = stats[1];
    const float4* G1 = (const float4*)ga1;
    const float4* B1 = (const float4*)be1;
    const float4* G2 = (const float4*)ga2;
    const float4* B2 = (const float4*)be2;
    __nv_bfloat162* O1 = (__nv_bfloat162*)(o1 + (size_t)t * DMODEL);
    __nv_bfloat162* O2 = (__nv_bfloat162*)(o2 + (size_t)t * DMODEL);
    #pragma unroll
    for (int i = 0; i < 2; i++) {
        int idx = tid + i * 256;
        float4 v = (i == 0) ? a : bq;
        float nx = (v.x - mu) * r, ny = (v.y - mu) * r, nz = (v.z - mu) * r, nw = (v.w - mu) * r;
        float4 g1v = G1[idx], b1v = B1[idx], g2v = G2[idx], b2v = B2[idx];
        O1[idx * 2]     = __floats2bfloat162_rn(nx * g1v.x + b1v.x, ny * g1v.y + b1v.y);
        O1[idx * 2 + 1] = __floats2bfloat162_rn(nz * g1v.z + b1v.z, nw * g1v.w + b1v.w);
        O2[idx * 2]     = __floats2bfloat162_rn(nx * g2v.x + b2v.x, ny * g2v.y + b2v.y);
        O2[idx * 2 + 1] = __floats2bfloat162_rn(nz * g2v.z + b2v.z, nw * g2v.w + b2v.w);
    }
}

// ---------------- mask flag ----------------
__global__ void flag_init(int* flag) { if (threadIdx.x == 0) flag[0] = 1; }

__global__ void mask_reduce(const int* __restrict__ mask, int n, int* __restrict__ flag) {
    bool bad = false;
    for (int i = blockIdx.x * blockDim.x + threadIdx.x; i < n; i += gridDim.x * blockDim.x)
        if (mask[i] == 0) bad = true;
    if (bad) flag[0] = 0;
}

// ================= bf16 GEMM: 128x256x32 tiles (unchanged from R4) =================
#define A_BYTES 10240
#define B_BYTES 16896
#define STAGE   27136
#define NSTAGE  3
#define SMEM_GEMM (STAGE * NSTAGE)

struct Epi {
    const float* c0;
    const float* c1;
    float* o0;
    __nv_bfloat16* bo0;
    __nv_bfloat16* bo1;
    __nv_bfloat16* bo2;
};

template <int E>
__device__ __forceinline__ void emit2(int r, int c, int N, float v0, float v1, const Epi& e) {
    if (E == 0) {
        int which = c >> 11, hh = (c >> 7) & 15, d0 = c & 127;
        __nv_bfloat16* dst = (which == 0) ? e.bo0 : ((which == 1) ? e.bo1 : e.bo2);
        int b = r >> 11, s = r & 2047;
        __nv_bfloat16* p = dst + (size_t)((b << 4) + hh) * (SEQ * DKH) + (size_t)s * DKH + d0;
        *(__nv_bfloat162*)p = __floats2bfloat162_rn(v0, v1);
    } else if (E == 1) {
        size_t i = (size_t)r * N + c;
        float2 xv = *(const float2*)(e.c0 + i);
        float2 o;
        o.x = xv.x + v0;
        o.y = xv.y + v1;
        *(float2*)(e.o0 + i) = o;
    } else if (E == 2) {
        const float is2 = 0.70710678118654752f;
        float t0 = v0 + e.c0[c], t1 = v1 + e.c0[c + 1];
        float g0 = 0.5f * t0 * (1.0f + erff(t0 * is2));
        float g1 = 0.5f * t1 * (1.0f + erff(t1 * is2));
        __nv_bfloat16* p = e.bo0 + (size_t)r * N + c;
        *(__nv_bfloat162*)p = __floats2bfloat162_rn(g0, g1);
    } else {
        size_t i = (size_t)r * N + c;
        float2 bb = *(const float2*)(e.c0 + c);
        float2 ls = *(const float2*)(e.c1 + c);
        float2 o  = *(const float2*)(e.o0 + i);
        o.x += ls.x * (v0 + bb.x);
        o.y += ls.y * (v1 + bb.y);
        *(float2*)(e.o0 + i) = o;
    }
}

__device__ __forceinline__ void gemm_load_stage(const __nv_bfloat16* A, const __nv_bfloat16* B,
                                                int K, int N, int bm, int bn, int kt,
                                                uint32_t base, int tid) {
    #pragma unroll
    for (int t = 0; t < 2; t++) {
        int c = tid + t * 256;
        int row = c >> 2, k8 = c & 3;
        const __nv_bfloat16* src = A + (size_t)(bm + row) * K + kt * 32 + k8 * 8;
        CP16(base + (uint32_t)row * 80 + (uint32_t)k8 * 16, src);
    }
    #pragma unroll
    for (int t = 0; t < 4; t++) {
        int c = tid + t * 256;
        int row = c >> 5, n8 = c & 31;
        const __nv_bfloat16* src = B + (size_t)(kt * 32 + row) * N + bn + n8 * 8;
        CP16(base + A_BYTES + (uint32_t)row * 528 + (uint32_t)n8 * 16, src);
    }
    CP_COMMIT();
}

template <int E>
__global__ __launch_bounds__(256, 1)
void gemm_bf16(const __nv_bfloat16* __restrict__ A, const __nv_bfloat16* __restrict__ B,
               int M, int N, int K, Epi e) {
    extern __shared__ __align__(128) char smc[];
    uint32_t smb = smem_u32(smc);
    int tid = threadIdx.x, warp = tid >> 5, lane = tid & 31;
    int bm = blockIdx.y * 128, bn = blockIdx.x * 256;
    int wm = (warp >> 2) * 64, wn = (warp & 3) * 64;
    const int nt = K >> 5;

    float acc[4][8][4];
    #pragma unroll
    for (int i = 0; i < 4; i++)
        #pragma unroll
        for (int j = 0; j < 8; j++)
            #pragma unroll
            for (int k = 0; k < 4; k++) acc[i][j][k] = 0.f;

    gemm_load_stage(A, B, K, N, bm, bn, 0, smb, tid);
    gemm_load_stage(A, B, K, N, bm, bn, 1, smb + STAGE, tid);

    int frow = (lane & 7) + ((lane >> 3) & 1) * 8;
    int hi = lane >> 4;

    for (int i = 0; i < nt; i++) {
        CP_WAIT1();
        __syncthreads();
        if (i + 2 < nt)
            gemm_load_stage(A, B, K, N, bm, bn, i + 2, smb + (uint32_t)((i + 2) % 3) * STAGE, tid);

        uint32_t abase = smb + (uint32_t)(i % 3) * STAGE;
        uint32_t bbase = abase + A_BYTES;
        #pragma unroll
        for (int k16 = 0; k16 < 2; k16++) {
            uint32_t a[4][4], bf[4][4];
            #pragma unroll
            for (int mt = 0; mt < 4; mt++) {
                uint32_t ad = abase + (uint32_t)(wm + mt * 16 + frow) * 80
                            + (uint32_t)(k16 * 2 + hi) * 16;
                LDSM_X4(a[mt], ad);
            }
            #pragma unroll
            for (int nt16 = 0; nt16 < 4; nt16++) {
                uint32_t bd = bbase + (uint32_t)(k16 * 16 + frow) * 528
                            + (uint32_t)(((wn + nt16 * 16) >> 3) + hi) * 16;
                LDSM_X4T(bf[nt16], bd);
            }
            #pragma unroll
            for (int mt = 0; mt < 4; mt++)
                #pragma unroll
                for (int n8 = 0; n8 < 8; n8++)
                    mma16(acc[mt][n8], a[mt], bf[n8 >> 1][(n8 & 1) * 2], bf[n8 >> 1][(n8 & 1) * 2 + 1]);
        }
    }

    int g = lane >> 2, tq = lane & 3;
    #pragma unroll
    for (int mt = 0; mt < 4; mt++) {
        int r0 = bm + wm + mt * 16 + g;
        #pragma unroll
        for (int n8 = 0; n8 < 8; n8++) {
            int c0 = bn + wn + n8 * 8 + tq * 2;
            emit2<E>(r0,     c0, N, acc[mt][n8][0], acc[mt][n8][1], e);
            emit2<E>(r0 + 8, c0, N, acc[mt][n8][2], acc[mt][n8][3], e);
        }
    }
}

// ======== flash attention: bf16 mma16 + ldmatrix, P in registers (hi+lo) ========
// smem bytes: Q tile 64x128 (rows padded to 272B) = 17408
//             K/V double-buffered: 4 * 17408
#define AKV_ROWB 272
#define AKV_MATB 17408
#define ATTN_SMEM (AKV_MATB * 5)

__global__ __launch_bounds__(128, 2)
void attn_bf16(const __nv_bfloat16* __restrict__ Q, const __nv_bfloat16* __restrict__ K,
               const __nv_bfloat16* __restrict__ V, const int* __restrict__ mask,
               const int* __restrict__ flag, __nv_bfloat16* __restrict__ ctx) {
    extern __shared__ __align__(128) char sma[];
    uint32_t smb = smem_u32(sma);
    int tid = threadIdx.x, warp = tid >> 5, lane = tid & 31;
    int g = lane >> 2, tq = lane & 3;
    int frow = (lane & 7) + ((lane >> 3) & 1) * 8;
    int hi = lane >> 4;
    int qt = blockIdx.x, bh = blockIdx.y;
    int b = bh >> 4, h = bh & 15;
    const __nv_bfloat16* Qg = Q + (size_t)bh * SEQ * DKH + (size_t)(qt * 64) * DKH;
    const __nv_bfloat16* Kg = K + (size_t)bh * SEQ * DKH;
    const __nv_bfloat16* Vg = V + (size_t)bh * SEQ * DKH;
    int q0 = qt * 64 + warp * 16;
    int allv = flag[0];

    // load Q tile + KV tile0 (group 0), KV tile1 (group 1)
    {
        int row = tid >> 1, c16b = (tid & 1) * 8;   // 128 thr: 64 rows x 2 halves
        #pragma unroll
        for (int t = 0; t < 8; t++) {
            CP16(smb + (uint32_t)row * AKV_ROWB + (uint32_t)(c16b + t) * 16,
                 Qg + (size_t)row * DKH + (c16b + t) * 8);
        }
        #pragma unroll
        for (int t = 0; t < 8; t++) {
            CP16(smb + AKV_MATB + (uint32_t)row * AKV_ROWB + (uint32_t)(c16b + t) * 16,
                 Kg + (size_t)row * DKH + (c16b + t) * 8);
            CP16(smb + AKV_MATB + AKV_MATB + (uint32_t)row * AKV_ROWB + (uint32_t)(c16b + t) * 16,
                 Vg + (size_t)row * DKH + (c16b + t) * 8);
        }
        CP_COMMIT();
        #pragma unroll
        for (int t = 0; t < 8; t++) {
            CP16(smb + AKV_MATB * 3 + (uint32_t)row * AKV_ROWB + (uint32_t)(c16b + t) * 16,
                 Kg + (size_t)(64 + row) * DKH + (c16b + t) * 8);
            CP16(smb + AKV_MATB * 4 + (uint32_t)row * AKV_ROWB + (uint32_t)(c16b + t) * 16,
                 Vg + (size_t)(64 + row) * DKH + (c16b + t) * 8);
        }
        CP_COMMIT();
    }

    CP_WAIT1();
    __syncthreads();

    // Q fragments (16 rows x 128 k) in registers
    uint32_t qa[8][4];
    #pragma unroll
    for (int k16 = 0; k16 < 8; k16++)
        LDSM_X4(qa[k16], smb + (uint32_t)(warp * 16 + frow) * AKV_ROWB
                             + (uint32_t)(k16 * 2 + hi) * 16);

    float o[16][4];
    #pragma unroll
    for (int i = 0; i < 16; i++)
        #pragma unroll
        for (int j = 0; j < 4; j++) o[i][j] = 0.f;
    float mA = -1e30f, mB = -1e30f, lA = 0.f, lB = 0.f;

    for (int j = 0; j < 32; j++) {
        if (j > 0) { CP_WAIT1(); __syncthreads(); }
        int buf = j & 1;
        uint32_t kbase = smb + AKV_MATB + (uint32_t)buf * (2 * AKV_MATB);
        uint32_t vbase = kbase + AKV_MATB;

        // ---- S = Q @ K^T ----
        float sc[8][4];
        #pragma unroll
        for (int ni = 0; ni < 8; ni++)
            #pragma unroll
            for (int c = 0; c < 4; c++) sc[ni][c] = 0.f;
        #pragma unroll
        for (int k16 = 0; k16 < 8; k16++) {
            #pragma unroll
            for (int n16 = 0; n16 < 4; n16++) {
                uint32_t kb[4];
                LDSM_X4(kb, kbase + (uint32_t)(n16 * 16 + frow) * AKV_ROWB
                                  + (uint32_t)(k16 * 2 + hi) * 16);
                mma16(sc[n16 * 2],     qa[k16], kb[0], kb[2]);
                mma16(sc[n16 * 2 + 1], qa[k16], kb[1], kb[3]);
            }
        }
        const float sscale = 0.0883883476483184f;  // 1/sqrt(128)
        #pragma unroll
        for (int ni = 0; ni < 8; ni++)
            #pragma unroll
            for (int c = 0; c < 4; c++) sc[ni][c] *= sscale;

        if (!allv) {
            #pragma unroll
            for (int ni = 0; ni < 8; ni++) {
                int kc = j * 64 + ni * 8 + tq * 2;
                int r0 = q0 + g, r1 = q0 + g + 8;
                if (mask[(size_t)r0 * SEQ + kc] == 0)     sc[ni][0] = -1e9f;
                if (mask[(size_t)r0 * SEQ + kc + 1] == 0) sc[ni][1] = -1e9f;
                if (mask[(size_t)r1 * SEQ + kc] == 0)     sc[ni][2] = -1e9f;
                if (mask[(size_t)r1 * SEQ + kc + 1] == 0) sc[ni][3] = -1e9f;
            }
        }

        // ---- online softmax ----
        float mxA = -1e30f, mxB = -1e30f;
        #pragma unroll
        for (int ni = 0; ni < 8; ni++) {
            mxA = fmaxf(mxA, fmaxf(sc[ni][0], sc[ni][1]));
            mxB = fmaxf(mxB, fmaxf(sc[ni][2], sc[ni][3]));
        }
        mxA = fmaxf(mxA, __shfl_xor_sync(0xffffffffu, mxA, 1));
        mxA = fmaxf(mxA, __shfl_xor_sync(0xffffffffu, mxA, 2));
        mxB = fmaxf(mxB, __shfl_xor_sync(0xffffffffu, mxB, 1));
        mxB = fmaxf(mxB, __shfl_xor_sync(0xffffffffu, mxB, 2));
        float mAn = fmaxf(mA, mxA), mBn = fmaxf(mB, mxB);
        float aA = __expf(mA - mAn), aB = __expf(mB - mBn);
        float sA = 0.f, sB = 0.f;
        #pragma unroll
        for (int ni = 0; ni < 8; ni++) {
            sc[ni][0] = __expf(sc[ni][0] - mAn); sA += sc[ni][0];
            sc[ni][1] = __expf(sc[ni][1] - mAn); sA += sc[ni][1];
            sc[ni][2] = __expf(sc[ni][2] - mBn); sB += sc[ni][2];
            sc[ni][3] = __expf(sc[ni][3] - mBn); sB += sc[ni][3];
        }
        sA += __shfl_xor_sync(0xffffffffu, sA, 1);
        sA += __shfl_xor_sync(0xffffffffu, sA, 2);
        sB += __shfl_xor_sync(0xffffffffu, sB, 1);
        sB += __shfl_xor_sync(0xffffffffu, sB, 2);
        lA = lA * aA + sA;
        lB = lB * aB + sB;
        mA = mAn; mB = mBn;
        #pragma unroll
        for (int ni = 0; ni < 16; ni++) {
            o[ni][0] *= aA; o[ni][1] *= aA;
            o[ni][2] *= aB; o[ni][3] *= aB;
        }

        // ---- P -> bf16 hi/lo A-fragments (registers only) ----
        uint32_t pa[4][4], pl[4][4];
        #pragma unroll
        for (int jj = 0; jj < 4; jj++) {
            float* e0 = sc[2 * jj];
            float* e1 = sc[2 * jj + 1];
            float h00 = __bfloat162float(__float2bfloat16_rn(e0[0]));
            float h01 = __bfloat162float(__float2bfloat16_rn(e0[1]));
            float h02 = __bfloat162float(__float2bfloat16_rn(e0[2]));
            float h03 = __bfloat162float(__float2bfloat16_rn(e0[3]));
            float h10 = __bfloat162float(__float2bfloat16_rn(e1[0]));
            float h11 = __bfloat162float(__float2bfloat16_rn(e1[1]));
            float h12 = __bfloat162float(__float2bfloat16_rn(e1[2]));
            float h13 = __bfloat162float(__float2bfloat16_rn(e1[3]));
            pa[jj][0] = pack_bf2(h00, h01);
            pa[jj][1] = pack_bf2(h02, h03);
            pa[jj][2] = pack_bf2(h10, h11);
            pa[jj][3] = pack_bf2(h12, h13);
            pl[jj][0] = pack_bf2(e0[0] - h00, e0[1] - h01);
            pl[jj][1] = pack_bf2(e0[2] - h02, e0[3] - h03);
            pl[jj][2] = pack_bf2(e1[0] - h10, e1[1] - h11);
            pl[jj][3] = pack_bf2(e1[2] - h12, e1[3] - h13);
        }

        // ---- O += P @ V ----
        #pragma unroll
        for (int k16 = 0; k16 < 4; k16++) {
            #pragma unroll
            for (int n16 = 0; n16 < 8; n16++) {
                uint32_t vb4[4];
                LDSM_X4T(vb4, vbase + (uint32_t)(k16 * 16 + frow) * AKV_ROWB
                                    + (uint32_t)(n16 * 2 + hi) * 16);
                mma16(o[n16 * 2],     pa[k16], vb4[0], vb4[1]);
                mma16(o[n16 * 2 + 1], pa[k16], vb4[2], vb4[3]);
                mma16(o[n16 * 2],     pl[k16], vb4[0], vb4[1]);
                mma16(o[n16 * 2 + 1], pl[k16], vb4[2], vb4[3]);
            }
        }

        // prefetch tile j+2 into this buffer (after everyone is done reading it)
        __syncthreads();
        if (j + 2 < 32) {
            int row = tid >> 1, c16b = (tid & 1) * 8;
            uint32_t kd = smb + AKV_MATB + (uint32_t)buf * (2 * AKV_MATB);
            const __nv_bfloat16* ks = Kg + (size_t)((j + 2) * 64 + row) * DKH;
            const __nv_bfloat16* vs = Vg + (size_t)((j + 2) * 64 + row) * DKH;
            #pragma unroll
            for (int t = 0; t < 8; t++) {
                CP16(kd + (uint32_t)row * AKV_ROWB + (uint32_t)(c16b + t) * 16,
                     ks + (c16b + t) * 8);
                CP16(kd + AKV_MATB + (uint32_t)row * AKV_ROWB + (uint32_t)(c16b + t) * 16,
                     vs + (c16b + t) * 8);
            }
            CP_COMMIT();
        }
    }

    float rA = 1.f / lA, rB = 1.f / lB;
    int tok0 = b * SEQ + q0 + g, tok1 = tok0 + 8;
    #pragma unroll
    for (int ni = 0; ni < 16; ni++) {
        int d = ni * 8 + tq * 2;
        __nv_bfloat16* p0 = ctx + (size_t)tok0 * DMODEL + h * DKH + d;
        __nv_bfloat16* p1 = ctx + (size_t)tok1 * DMODEL + h * DKH + d;
        *(__nv_bfloat162*)p0 = __floats2bfloat162_rn(o[ni][0] * rA, o[ni][1] * rA);
        *(__nv_bfloat162*)p1 = __floats2bfloat162_rn(o[ni][2] * rB, o[ni][3] * rB);
    }
}

// ---------------- launch ----------------
extern "C" void kernel_launch(void* const* d_in, const int* in_sizes, int n_in,
                              void* d_out, int out_size) {
    const float* x     = (const float*)d_in[0];
    const int*   mask  = (const int*)d_in[1];
    const float* w_qkv = (const float*)d_in[2];
    const float* w_o   = (const float*)d_in[3];
    const float* ga1   = (const float*)d_in[4];
    const float* be1   = (const float*)d_in[5];
    const float* ga2   = (const float*)d_in[6];
    const float* be2   = (const float*)d_in[7];
    const float* w1    = (const float*)d_in[8];
    const float* b1    = (const float*)d_in[9];
    const float* w2    = (const float*)d_in[10];
    const float* b2    = (const float*)d_in[11];
    const float* ls    = (const float*)d_in[12];
    float* out = (float*)d_out;

    __nv_bfloat16 *ln1, *ln2, *q, *k, *v, *ctx, *hbuf, *wqkvb, *wob, *w1b, *w2b;
    int* flag;
    cudaGetSymbolAddress((void**)&ln1,   g_ln1);
    cudaGetSymbolAddress((void**)&ln2,   g_ln2);
    cudaGetSymbolAddress((void**)&q,     g_q);
    cudaGetSymbolAddress((void**)&k,     g_k);
    cudaGetSymbolAddress((void**)&v,     g_v);
    cudaGetSymbolAddress((void**)&ctx,   g_ctx);
    cudaGetSymbolAddress((void**)&hbuf,  g_h);
    cudaGetSymbolAddress((void**)&wqkvb, g_wqkv);
    cudaGetSymbolAddress((void**)&wob,   g_wo);
    cudaGetSymbolAddress((void**)&w1b,   g_w1);
    cudaGetSymbolAddress((void**)&w2b,   g_w2);
    cudaGetSymbolAddress((void**)&flag,  g_flag);

    cudaFuncSetAttribute(attn_bf16, cudaFuncAttributeMaxDynamicSharedMemorySize, ATTN_SMEM);
    cudaFuncSetAttribute(gemm_bf16<0>, cudaFuncAttributeMaxDynamicSharedMemorySize, SMEM_GEMM);
    cudaFuncSetAttribute(gemm_bf16<1>, cudaFuncAttributeMaxDynamicSharedMemorySize, SMEM_GEMM);
    cudaFuncSetAttribute(gemm_bf16<2>, cudaFuncAttributeMaxDynamicSharedMemorySize, SMEM_GEMM);
    cudaFuncSetAttribute(gemm_bf16<3>, cudaFuncAttributeMaxDynamicSharedMemorySize, SMEM_GEMM);

    // weight conversions (fp32 -> bf16)
    cvt_kernel<<<(DMODEL * 3 * DMODEL) / 4 / 256, 256>>>(w_qkv, wqkvb, DMODEL * 3 * DMODEL);
    cvt_kernel<<<(DMODEL * DMODEL) / 4 / 256, 256>>>(w_o, wob, DMODEL * DMODEL);
    cvt_kernel<<<(DMODEL * DFF) / 4 / 256, 256>>>(w1, w1b, DMODEL * DFF);
    cvt_kernel<<<(DFF * DMODEL) / 4 / 256, 256>>>(w2, w2b, DFF * DMODEL);

    // layernorms (both on x) -> bf16
    ln_kernel<<<TOKS, 256>>>(x, ga1, be1, ga2, be2, ln1, ln2);

    // mask all-visible flag
    flag_init<<<1, 32>>>(flag);
    mask_reduce<<<256, 256>>>(mask, in_sizes[1], flag);

    // QKV projection -> bf16 q/k/v in head layout
    Epi e1 = {nullptr, nullptr, nullptr, q, k, v};
    gemm_bf16<0><<<dim3(24, 32), 256, SMEM_GEMM>>>(ln1, wqkvb, TOKS, 3 * DMODEL, DMODEL, e1);

    // attention -> bf16 ctx
    attn_bf16<<<dim3(32, 32), 128, ATTN_SMEM>>>(q, k, v, mask, flag, ctx);

    // output projection + residual with fp32 x: out = x + ctx @ w_o
    Epi e2 = {x, nullptr, out, nullptr, nullptr, nullptr};
    gemm_bf16<1><<<dim3(8, 32), 256, SMEM_GEMM>>>(ctx, wob, TOKS, DMODEL, DMODEL, e2);

    // FF1 + exact gelu -> bf16 h
    Epi e3 = {b1, nullptr, nullptr, hbuf, nullptr, nullptr};
    gemm_bf16<2><<<dim3(32, 32), 256, SMEM_GEMM>>>(ln2, w1b, TOKS, DFF, DMODEL, e3);

    // FF2 + bias + layer_scale, accumulate into out (fp32)
    Epi e4 = {b2, ls, out, nullptr, nullptr, nullptr};
    gemm_bf16<3><<<dim3(8, 32), 256, SMEM_GEMM>>>(hbuf, w2b, TOKS, DMODEL, DFF, e4);
}

// round 6
// speedup vs baseline: 2.1670x; 1.0272x over previous
#include <cuda_runtime.h>
#include <cuda_bf16.h>
#include <cstdint>
#include <cmath>

// ---------------- problem constants ----------------
#define TOKS 4096
#define DMODEL 2048
#define DFF 8192
#define NHEADS 16
#define DKH 128
#define SEQ 2048
#define BATCH 2

// ---------------- scratch (device globals) ----------------
__device__ __align__(128) __nv_bfloat16 g_ln1[TOKS * DMODEL];
__device__ __align__(128) __nv_bfloat16 g_ln2[TOKS * DMODEL];
__device__ __align__(128) __nv_bfloat16 g_q[TOKS * DMODEL];
__device__ __align__(128) __nv_bfloat16 g_k[TOKS * DMODEL];
__device__ __align__(128) __nv_bfloat16 g_v[TOKS * DMODEL];
__device__ __align__(128) __nv_bfloat16 g_ctx[TOKS * DMODEL];
__device__ __align__(128) __nv_bfloat16 g_h[TOKS * DFF];
__device__ __align__(128) __nv_bfloat16 g_wqkv[DMODEL * 3 * DMODEL];
__device__ __align__(128) __nv_bfloat16 g_wo[DMODEL * DMODEL];
__device__ __align__(128) __nv_bfloat16 g_w1[DMODEL * DFF];
__device__ __align__(128) __nv_bfloat16 g_w2[DFF * DMODEL];
__device__ int g_flag[1];

// ---------------- helpers ----------------
__device__ __forceinline__ uint32_t f2u(float x) { return __float_as_uint(x); }

__device__ __forceinline__ uint32_t smem_u32(const void* p) {
    uint32_t a;
    asm("{ .reg .u64 t; cvta.to.shared.u64 t, %1; cvt.u32.u64 %0, t; }"
        : "=r"(a) : "l"(p));
    return a;
}

#define CP16(dst, src) \
    asm volatile("cp.async.cg.shared.global [%0], [%1], 16;" \
                 :: "r"(dst), "l"(src) : "memory")
#define CP_COMMIT() asm volatile("cp.async.commit_group;" ::: "memory")
#define CP_WAIT1()  asm volatile("cp.async.wait_group 1;" ::: "memory")

#define LDSM_X4(r, addr) \
    asm volatile("ldmatrix.sync.aligned.m8n8.x4.shared.b16 {%0,%1,%2,%3}, [%4];" \
        : "=r"((r)[0]), "=r"((r)[1]), "=r"((r)[2]), "=r"((r)[3]) : "r"(addr))
#define LDSM_X4T(r, addr) \
    asm volatile("ldmatrix.sync.aligned.m8n8.x4.trans.shared.b16 {%0,%1,%2,%3}, [%4];" \
        : "=r"((r)[0]), "=r"((r)[1]), "=r"((r)[2]), "=r"((r)[3]) : "r"(addr))

__device__ __forceinline__ void mma16(float* c, const uint32_t* a, uint32_t b0, uint32_t b1) {
    asm volatile(
        "mma.sync.aligned.m16n8k16.row.col.f32.bf16.bf16.f32 "
        "{%0,%1,%2,%3},{%4,%5,%6,%7},{%8,%9},{%0,%1,%2,%3};"
        : "+f"(c[0]), "+f"(c[1]), "+f"(c[2]), "+f"(c[3])
        : "r"(a[0]), "r"(a[1]), "r"(a[2]), "r"(a[3]), "r"(b0), "r"(b1));
}

__device__ __forceinline__ uint32_t pack_bf2(float x, float y) {
    __nv_bfloat162 t = __floats2bfloat162_rn(x, y);
    return *(uint32_t*)&t;
}

// ---------------- fp32 -> bf16 converter ----------------
__global__ void cvt_kernel(const float* __restrict__ in, __nv_bfloat16* __restrict__ out, int n) {
    int i = (blockIdx.x * blockDim.x + threadIdx.x) * 4;
    if (i < n) {
        float4 v = *(const float4*)(in + i);
        *(__nv_bfloat162*)(out + i)     = __floats2bfloat162_rn(v.x, v.y);
        *(__nv_bfloat162*)(out + i + 2) = __floats2bfloat162_rn(v.z, v.w);
    }
}

// ---------------- LayerNorm: fp32 x -> bf16 ln1, ln2 ----------------
__global__ void ln_kernel(const float* __restrict__ x,
                          const float* __restrict__ ga1, const float* __restrict__ be1,
                          const float* __restrict__ ga2, const float* __restrict__ be2,
                          __nv_bfloat16* __restrict__ o1, __nv_bfloat16* __restrict__ o2) {
    int t = blockIdx.x;
    int tid = threadIdx.x;
    const float4* xr = (const float4*)(x + (size_t)t * DMODEL);
    float4 a = xr[tid];
    float4 bq = xr[tid + 256];
    float s  = a.x + a.y + a.z + a.w + bq.x + bq.y + bq.z + bq.w;
    float s2 = a.x*a.x + a.y*a.y + a.z*a.z + a.w*a.w +
               bq.x*bq.x + bq.y*bq.y + bq.z*bq.z + bq.w*bq.w;
    #pragma unroll
    for (int o = 16; o; o >>= 1) {
        s  += __shfl_xor_sync(0xffffffffu, s,  o);
        s2 += __shfl_xor_sync(0xffffffffu, s2, o);
    }
    __shared__ float rs[8], rs2[8], stats[2];
    if ((tid & 31) == 0) { rs[tid >> 5] = s; rs2[tid >> 5] = s2; }
    __syncthreads();
    if (tid == 0) {
        float S = 0.f, S2 = 0.f;
        for (int i = 0; i < 8; i++) { S += rs[i]; S2 += rs2[i]; }
        float mu = S * (1.0f / DMODEL);
        float var = S2 * (1.0f / DMODEL) - mu * mu;
        stats[0] = mu;
        stats[1] = rsqrtf(var + 1e-5f);
    }
    __syncthreads();
    float mu = stats[0], r = stats[1];
    const float4* G1 = (const float4*)ga1;
    const float4* B1 = (const float4*)be1;
    const float4* G2 = (const float4*)ga2;
    const float4* B2 = (const float4*)be2;
    __nv_bfloat162* O1 = (__nv_bfloat162*)(o1 + (size_t)t * DMODEL);
    __nv_bfloat162* O2 = (__nv_bfloat162*)(o2 + (size_t)t * DMODEL);
    #pragma unroll
    for (int i = 0; i < 2; i++) {
        int idx = tid + i * 256;
        float4 v = (i == 0) ? a : bq;
        float nx = (v.x - mu) * r, ny = (v.y - mu) * r, nz = (v.z - mu) * r, nw = (v.w - mu) * r;
        float4 g1v = G1[idx], b1v = B1[idx], g2v = G2[idx], b2v = B2[idx];
        O1[idx * 2]     = __floats2bfloat162_rn(nx * g1v.x + b1v.x, ny * g1v.y + b1v.y);
        O1[idx * 2 + 1] = __floats2bfloat162_rn(nz * g1v.z + b1v.z, nw * g1v.w + b1v.w);
        O2[idx * 2]     = __floats2bfloat162_rn(nx * g2v.x + b2v.x, ny * g2v.y + b2v.y);
        O2[idx * 2 + 1] = __floats2bfloat162_rn(nz * g2v.z + b2v.z, nw * g2v.w + b2v.w);
    }
}

// ---------------- mask flag ----------------
__global__ void flag_init(int* flag) { if (threadIdx.x == 0) flag[0] = 1; }

__global__ void mask_reduce(const int* __restrict__ mask, int n, int* __restrict__ flag) {
    bool bad = false;
    for (int i = blockIdx.x * blockDim.x + threadIdx.x; i < n; i += gridDim.x * blockDim.x)
        if (mask[i] == 0) bad = true;
    if (bad) flag[0] = 0;
}

// ================= bf16 GEMM: 128x256x32 tiles, 512 threads (16 warps) =================
#define A_BYTES 10240
#define B_BYTES 16896
#define STAGE   27136
#define NSTAGE  3
#define SMEM_GEMM (STAGE * NSTAGE)

struct Epi {
    const float* c0;
    const float* c1;
    float* o0;
    __nv_bfloat16* bo0;
    __nv_bfloat16* bo1;
    __nv_bfloat16* bo2;
};

template <int E>
__device__ __forceinline__ void emit2(int r, int c, int N, float v0, float v1, const Epi& e) {
    if (E == 0) {
        int which = c >> 11, hh = (c >> 7) & 15, d0 = c & 127;
        __nv_bfloat16* dst = (which == 0) ? e.bo0 : ((which == 1) ? e.bo1 : e.bo2);
        int b = r >> 11, s = r & 2047;
        __nv_bfloat16* p = dst + (size_t)((b << 4) + hh) * (SEQ * DKH) + (size_t)s * DKH + d0;
        *(__nv_bfloat162*)p = __floats2bfloat162_rn(v0, v1);
    } else if (E == 1) {
        size_t i = (size_t)r * N + c;
        float2 xv = *(const float2*)(e.c0 + i);
        float2 o;
        o.x = xv.x + v0;
        o.y = xv.y + v1;
        *(float2*)(e.o0 + i) = o;
    } else if (E == 2) {
        const float is2 = 0.70710678118654752f;
        float t0 = v0 + e.c0[c], t1 = v1 + e.c0[c + 1];
        float g0 = 0.5f * t0 * (1.0f + erff(t0 * is2));
        float g1 = 0.5f * t1 * (1.0f + erff(t1 * is2));
        __nv_bfloat16* p = e.bo0 + (size_t)r * N + c;
        *(__nv_bfloat162*)p = __floats2bfloat162_rn(g0, g1);
    } else {
        size_t i = (size_t)r * N + c;
        float2 bb = *(const float2*)(e.c0 + c);
        float2 ls = *(const float2*)(e.c1 + c);
        float2 o  = *(const float2*)(e.o0 + i);
        o.x += ls.x * (v0 + bb.x);
        o.y += ls.y * (v1 + bb.y);
        *(float2*)(e.o0 + i) = o;
    }
}

__device__ __forceinline__ void gemm_load_stage(const __nv_bfloat16* A, const __nv_bfloat16* B,
                                                int K, int N, int bm, int bn, int kt,
                                                uint32_t base, int tid) {
    // A: 128 rows x 32k = 512 16B-chunks, one per thread
    {
        int row = tid >> 2, k8 = tid & 3;
        const __nv_bfloat16* src = A + (size_t)(bm + row) * K + kt * 32 + k8 * 8;
        CP16(base + (uint32_t)row * 80 + (uint32_t)k8 * 16, src);
    }
    // B: 32 rows x 256n = 1024 16B-chunks, two per thread
    #pragma unroll
    for (int t = 0; t < 2; t++) {
        int c = tid + t * 512;
        int row = c >> 5, n8 = c & 31;
        const __nv_bfloat16* src = B + (size_t)(kt * 32 + row) * N + bn + n8 * 8;
        CP16(base + A_BYTES + (uint32_t)row * 528 + (uint32_t)n8 * 16, src);
    }
    CP_COMMIT();
}

template <int E>
__global__ __launch_bounds__(512, 1)
void gemm_bf16(const __nv_bfloat16* __restrict__ A, const __nv_bfloat16* __restrict__ B,
               int M, int N, int K, Epi e) {
    extern __shared__ __align__(128) char smc[];
    uint32_t smb = smem_u32(smc);
    int tid = threadIdx.x, warp = tid >> 5, lane = tid & 31;
    int bm = blockIdx.y * 128, bn = blockIdx.x * 256;
    int wm = (warp >> 2) * 32, wn = (warp & 3) * 64;
    const int nt = K >> 5;

    float acc[2][8][4];
    #pragma unroll
    for (int i = 0; i < 2; i++)
        #pragma unroll
        for (int j = 0; j < 8; j++)
            #pragma unroll
            for (int k = 0; k < 4; k++) acc[i][j][k] = 0.f;

    gemm_load_stage(A, B, K, N, bm, bn, 0, smb, tid);
    gemm_load_stage(A, B, K, N, bm, bn, 1, smb + STAGE, tid);

    int frow = (lane & 7) + ((lane >> 3) & 1) * 8;
    int hi = lane >> 4;

    for (int i = 0; i < nt; i++) {
        CP_WAIT1();
        __syncthreads();
        if (i + 2 < nt)
            gemm_load_stage(A, B, K, N, bm, bn, i + 2, smb + (uint32_t)((i + 2) % 3) * STAGE, tid);

        uint32_t abase = smb + (uint32_t)(i % 3) * STAGE;
        uint32_t bbase = abase + A_BYTES;
        #pragma unroll
        for (int k16 = 0; k16 < 2; k16++) {
            uint32_t a[2][4], bf[4][4];
            #pragma unroll
            for (int mt = 0; mt < 2; mt++) {
                uint32_t ad = abase + (uint32_t)(wm + mt * 16 + frow) * 80
                            + (uint32_t)(k16 * 2 + hi) * 16;
                LDSM_X4(a[mt], ad);
            }
            #pragma unroll
            for (int nt16 = 0; nt16 < 4; nt16++) {
                uint32_t bd = bbase + (uint32_t)(k16 * 16 + frow) * 528
                            + (uint32_t)(((wn + nt16 * 16) >> 3) + hi) * 16;
                LDSM_X4T(bf[nt16], bd);
            }
            #pragma unroll
            for (int mt = 0; mt < 2; mt++)
                #pragma unroll
                for (int n8 = 0; n8 < 8; n8++)
                    mma16(acc[mt][n8], a[mt], bf[n8 >> 1][(n8 & 1) * 2], bf[n8 >> 1][(n8 & 1) * 2 + 1]);
        }
    }

    int g = lane >> 2, tq = lane & 3;
    #pragma unroll
    for (int mt = 0; mt < 2; mt++) {
        int r0 = bm + wm + mt * 16 + g;
        #pragma unroll
        for (int n8 = 0; n8 < 8; n8++) {
            int c0 = bn + wn + n8 * 8 + tq * 2;
            emit2<E>(r0,     c0, N, acc[mt][n8][0], acc[mt][n8][1], e);
            emit2<E>(r0 + 8, c0, N, acc[mt][n8][2], acc[mt][n8][3], e);
        }
    }
}

// ======== flash attention: bf16 mma16 + ldmatrix, P in registers (hi+lo) ========
#define AKV_ROWB 272
#define AKV_MATB 17408
#define ATTN_SMEM (AKV_MATB * 5)

__global__ __launch_bounds__(128, 2)
void attn_bf16(const __nv_bfloat16* __restrict__ Q, const __nv_bfloat16* __restrict__ K,
               const __nv_bfloat16* __restrict__ V, const int* __restrict__ mask,
               const int* __restrict__ flag, __nv_bfloat16* __restrict__ ctx) {
    extern __shared__ __align__(128) char sma[];
    uint32_t smb = smem_u32(sma);
    int tid = threadIdx.x, warp = tid >> 5, lane = tid & 31;
    int g = lane >> 2, tq = lane & 3;
    int frow = (lane & 7) + ((lane >> 3) & 1) * 8;
    int hi = lane >> 4;
    int qt = blockIdx.x, bh = blockIdx.y;
    int b = bh >> 4, h = bh & 15;
    const __nv_bfloat16* Qg = Q + (size_t)bh * SEQ * DKH + (size_t)(qt * 64) * DKH;
    const __nv_bfloat16* Kg = K + (size_t)bh * SEQ * DKH;
    const __nv_bfloat16* Vg = V + (size_t)bh * SEQ * DKH;
    int q0 = qt * 64 + warp * 16;
    int allv = flag[0];

    {
        int row = tid >> 1, c16b = (tid & 1) * 8;
        #pragma unroll
        for (int t = 0; t < 8; t++) {
            CP16(smb + (uint32_t)row * AKV_ROWB + (uint32_t)(c16b + t) * 16,
                 Qg + (size_t)row * DKH + (c16b + t) * 8);
        }
        #pragma unroll
        for (int t = 0; t < 8; t++) {
            CP16(smb + AKV_MATB + (uint32_t)row * AKV_ROWB + (uint32_t)(c16b + t) * 16,
                 Kg + (size_t)row * DKH + (c16b + t) * 8);
            CP16(smb + AKV_MATB + AKV_MATB + (uint32_t)row * AKV_ROWB + (uint32_t)(c16b + t) * 16,
                 Vg + (size_t)row * DKH + (c16b + t) * 8);
        }
        CP_COMMIT();
        #pragma unroll
        for (int t = 0; t < 8; t++) {
            CP16(smb + AKV_MATB * 3 + (uint32_t)row * AKV_ROWB + (uint32_t)(c16b + t) * 16,
                 Kg + (size_t)(64 + row) * DKH + (c16b + t) * 8);
            CP16(smb + AKV_MATB * 4 + (uint32_t)row * AKV_ROWB + (uint32_t)(c16b + t) * 16,
                 Vg + (size_t)(64 + row) * DKH + (c16b + t) * 8);
        }
        CP_COMMIT();
    }

    CP_WAIT1();
    __syncthreads();

    uint32_t qa[8][4];
    #pragma unroll
    for (int k16 = 0; k16 < 8; k16++)
        LDSM_X4(qa[k16], smb + (uint32_t)(warp * 16 + frow) * AKV_ROWB
                             + (uint32_t)(k16 * 2 + hi) * 16);

    float o[16][4];
    #pragma unroll
    for (int i = 0; i < 16; i++)
        #pragma unroll
        for (int j = 0; j < 4; j++) o[i][j] = 0.f;
    float mA = -1e30f, mB = -1e30f, lA = 0.f, lB = 0.f;

    for (int j = 0; j < 32; j++) {
        if (j > 0) { CP_WAIT1(); __syncthreads(); }
        int buf = j & 1;
        uint32_t kbase = smb + AKV_MATB + (uint32_t)buf * (2 * AKV_MATB);
        uint32_t vbase = kbase + AKV_MATB;

        float sc[8][4];
        #pragma unroll
        for (int ni = 0; ni < 8; ni++)
            #pragma unroll
            for (int c = 0; c < 4; c++) sc[ni][c] = 0.f;
        #pragma unroll
        for (int k16 = 0; k16 < 8; k16++) {
            #pragma unroll
            for (int n16 = 0; n16 < 4; n16++) {
                uint32_t kb[4];
                LDSM_X4(kb, kbase + (uint32_t)(n16 * 16 + frow) * AKV_ROWB
                                  + (uint32_t)(k16 * 2 + hi) * 16);
                mma16(sc[n16 * 2],     qa[k16], kb[0], kb[2]);
                mma16(sc[n16 * 2 + 1], qa[k16], kb[1], kb[3]);
            }
        }
        const float sscale = 0.0883883476483184f;
        #pragma unroll
        for (int ni = 0; ni < 8; ni++)
            #pragma unroll
            for (int c = 0; c < 4; c++) sc[ni][c] *= sscale;

        if (!allv) {
            #pragma unroll
            for (int ni = 0; ni < 8; ni++) {
                int kc = j * 64 + ni * 8 + tq * 2;
                int r0 = q0 + g, r1 = q0 + g + 8;
                if (mask[(size_t)r0 * SEQ + kc] == 0)     sc[ni][0] = -1e9f;
                if (mask[(size_t)r0 * SEQ + kc + 1] == 0) sc[ni][1] = -1e9f;
                if (mask[(size_t)r1 * SEQ + kc] == 0)     sc[ni][2] = -1e9f;
                if (mask[(size_t)r1 * SEQ + kc + 1] == 0) sc[ni][3] = -1e9f;
            }
        }

        float mxA = -1e30f, mxB = -1e30f;
        #pragma unroll
        for (int ni = 0; ni < 8; ni++) {
            mxA = fmaxf(mxA, fmaxf(sc[ni][0], sc[ni][1]));
            mxB = fmaxf(mxB, fmaxf(sc[ni][2], sc[ni][3]));
        }
        mxA = fmaxf(mxA, __shfl_xor_sync(0xffffffffu, mxA, 1));
        mxA = fmaxf(mxA, __shfl_xor_sync(0xffffffffu, mxA, 2));
        mxB = fmaxf(mxB, __shfl_xor_sync(0xffffffffu, mxB, 1));
        mxB = fmaxf(mxB, __shfl_xor_sync(0xffffffffu, mxB, 2));
        float mAn = fmaxf(mA, mxA), mBn = fmaxf(mB, mxB);
        float aA = __expf(mA - mAn), aB = __expf(mB - mBn);
        float sA = 0.f, sB = 0.f;
        #pragma unroll
        for (int ni = 0; ni < 8; ni++) {
            sc[ni][0] = __expf(sc[ni][0] - mAn); sA += sc[ni][0];
            sc[ni][1] = __expf(sc[ni][1] - mAn); sA += sc[ni][1];
            sc[ni][2] = __expf(sc[ni][2] - mBn); sB += sc[ni][2];
            sc[ni][3] = __expf(sc[ni][3] - mBn); sB += sc[ni][3];
        }
        sA += __shfl_xor_sync(0xffffffffu, sA, 1);
        sA += __shfl_xor_sync(0xffffffffu, sA, 2);
        sB += __shfl_xor_sync(0xffffffffu, sB, 1);
        sB += __shfl_xor_sync(0xffffffffu, sB, 2);
        lA = lA * aA + sA;
        lB = lB * aB + sB;
        mA = mAn; mB = mBn;
        #pragma unroll
        for (int ni = 0; ni < 16; ni++) {
            o[ni][0] *= aA; o[ni][1] *= aA;
            o[ni][2] *= aB; o[ni][3] *= aB;
        }

        uint32_t pa[4][4], pl[4][4];
        #pragma unroll
        for (int jj = 0; jj < 4; jj++) {
            float* e0 = sc[2 * jj];
            float* e1 = sc[2 * jj + 1];
            float h00 = __bfloat162float(__float2bfloat16_rn(e0[0]));
            float h01 = __bfloat162float(__float2bfloat16_rn(e0[1]));
            float h02 = __bfloat162float(__float2bfloat16_rn(e0[2]));
            float h03 = __bfloat162float(__float2bfloat16_rn(e0[3]));
            float h10 = __bfloat162float(__float2bfloat16_rn(e1[0]));
            float h11 = __bfloat162float(__float2bfloat16_rn(e1[1]));
            float h12 = __bfloat162float(__float2bfloat16_rn(e1[2]));
            float h13 = __bfloat162float(__float2bfloat16_rn(e1[3]));
            pa[jj][0] = pack_bf2(h00, h01);
            pa[jj][1] = pack_bf2(h02, h03);
            pa[jj][2] = pack_bf2(h10, h11);
            pa[jj][3] = pack_bf2(h12, h13);
            pl[jj][0] = pack_bf2(e0[0] - h00, e0[1] - h01);
            pl[jj][1] = pack_bf2(e0[2] - h02, e0[3] - h03);
            pl[jj][2] = pack_bf2(e1[0] - h10, e1[1] - h11);
            pl[jj][3] = pack_bf2(e1[2] - h12, e1[3] - h13);
        }

        #pragma unroll
        for (int k16 = 0; k16 < 4; k16++) {
            #pragma unroll
            for (int n16 = 0; n16 < 8; n16++) {
                uint32_t vb4[4];
                LDSM_X4T(vb4, vbase + (uint32_t)(k16 * 16 + frow) * AKV_ROWB
                                    + (uint32_t)(n16 * 2 + hi) * 16);
                mma16(o[n16 * 2],     pa[k16], vb4[0], vb4[1]);
                mma16(o[n16 * 2 + 1], pa[k16], vb4[2], vb4[3]);
                mma16(o[n16 * 2],     pl[k16], vb4[0], vb4[1]);
                mma16(o[n16 * 2 + 1], pl[k16], vb4[2], vb4[3]);
            }
        }

        __syncthreads();
        if (j + 2 < 32) {
            int row = tid >> 1, c16b = (tid & 1) * 8;
            uint32_t kd = smb + AKV_MATB + (uint32_t)buf * (2 * AKV_MATB);
            const __nv_bfloat16* ks = Kg + (size_t)((j + 2) * 64 + row) * DKH;
            const __nv_bfloat16* vs = Vg + (size_t)((j + 2) * 64 + row) * DKH;
            #pragma unroll
            for (int t = 0; t < 8; t++) {
                CP16(kd + (uint32_t)row * AKV_ROWB + (uint32_t)(c16b + t) * 16,
                     ks + (c16b + t) * 8);
                CP16(kd + AKV_MATB + (uint32_t)row * AKV_ROWB + (uint32_t)(c16b + t) * 16,
                     vs + (c16b + t) * 8);
            }
            CP_COMMIT();
        }
    }

    float rA = 1.f / lA, rB = 1.f / lB;
    int tok0 = b * SEQ + q0 + g, tok1 = tok0 + 8;
    #pragma unroll
    for (int ni = 0; ni < 16; ni++) {
        int d = ni * 8 + tq * 2;
        __nv_bfloat16* p0 = ctx + (size_t)tok0 * DMODEL + h * DKH + d;
        __nv_bfloat16* p1 = ctx + (size_t)tok1 * DMODEL + h * DKH + d;
        *(__nv_bfloat162*)p0 = __floats2bfloat162_rn(o[ni][0] * rA, o[ni][1] * rA);
        *(__nv_bfloat162*)p1 = __floats2bfloat162_rn(o[ni][2] * rB, o[ni][3] * rB);
    }
}

// ---------------- launch ----------------
extern "C" void kernel_launch(void* const* d_in, const int* in_sizes, int n_in,
                              void* d_out, int out_size) {
    const float* x     = (const float*)d_in[0];
    const int*   mask  = (const int*)d_in[1];
    const float* w_qkv = (const float*)d_in[2];
    const float* w_o   = (const float*)d_in[3];
    const float* ga1   = (const float*)d_in[4];
    const float* be1   = (const float*)d_in[5];
    const float* ga2   = (const float*)d_in[6];
    const float* be2   = (const float*)d_in[7];
    const float* w1    = (const float*)d_in[8];
    const float* b1    = (const float*)d_in[9];
    const float* w2    = (const float*)d_in[10];
    const float* b2    = (const float*)d_in[11];
    const float* ls    = (const float*)d_in[12];
    float* out = (float*)d_out;

    __nv_bfloat16 *ln1, *ln2, *q, *k, *v, *ctx, *hbuf, *wqkvb, *wob, *w1b, *w2b;
    int* flag;
    cudaGetSymbolAddress((void**)&ln1,   g_ln1);
    cudaGetSymbolAddress((void**)&ln2,   g_ln2);
    cudaGetSymbolAddress((void**)&q,     g_q);
    cudaGetSymbolAddress((void**)&k,     g_k);
    cudaGetSymbolAddress((void**)&v,     g_v);
    cudaGetSymbolAddress((void**)&ctx,   g_ctx);
    cudaGetSymbolAddress((void**)&hbuf,  g_h);
    cudaGetSymbolAddress((void**)&wqkvb, g_wqkv);
    cudaGetSymbolAddress((void**)&wob,   g_wo);
    cudaGetSymbolAddress((void**)&w1b,   g_w1);
    cudaGetSymbolAddress((void**)&w2b,   g_w2);
    cudaGetSymbolAddress((void**)&flag,  g_flag);

    cudaFuncSetAttribute(attn_bf16, cudaFuncAttributeMaxDynamicSharedMemorySize, ATTN_SMEM);
    cudaFuncSetAttribute(gemm_bf16<0>, cudaFuncAttributeMaxDynamicSharedMemorySize, SMEM_GEMM);
    cudaFuncSetAttribute(gemm_bf16<1>, cudaFuncAttributeMaxDynamicSharedMemorySize, SMEM_GEMM);
    cudaFuncSetAttribute(gemm_bf16<2>, cudaFuncAttributeMaxDynamicSharedMemorySize, SMEM_GEMM);
    cudaFuncSetAttribute(gemm_bf16<3>, cudaFuncAttributeMaxDynamicSharedMemorySize, SMEM_GEMM);

    // weight conversions (fp32 -> bf16)
    cvt_kernel<<<(DMODEL * 3 * DMODEL) / 4 / 256, 256>>>(w_qkv, wqkvb, DMODEL * 3 * DMODEL);
    cvt_kernel<<<(DMODEL * DMODEL) / 4 / 256, 256>>>(w_o, wob, DMODEL * DMODEL);
    cvt_kernel<<<(DMODEL * DFF) / 4 / 256, 256>>>(w1, w1b, DMODEL * DFF);
    cvt_kernel<<<(DFF * DMODEL) / 4 / 256, 256>>>(w2, w2b, DFF * DMODEL);

    // layernorms (both on x) -> bf16
    ln_kernel<<<TOKS, 256>>>(x, ga1, be1, ga2, be2, ln1, ln2);

    // mask all-visible flag
    flag_init<<<1, 32>>>(flag);
    mask_reduce<<<256, 256>>>(mask, in_sizes[1], flag);

    // QKV projection -> bf16 q/k/v in head layout
    Epi e1 = {nullptr, nullptr, nullptr, q, k, v};
    gemm_bf16<0><<<dim3(24, 32), 512, SMEM_GEMM>>>(ln1, wqkvb, TOKS, 3 * DMODEL, DMODEL, e1);

    // attention -> bf16 ctx
    attn_bf16<<<dim3(32, 32), 128, ATTN_SMEM>>>(q, k, v, mask, flag, ctx);

    // output projection + residual with fp32 x: out = x + ctx @ w_o
    Epi e2 = {x, nullptr, out, nullptr, nullptr, nullptr};
    gemm_bf16<1><<<dim3(8, 32), 512, SMEM_GEMM>>>(ctx, wob, TOKS, DMODEL, DMODEL, e2);

    // FF1 + exact gelu -> bf16 h
    Epi e3 = {b1, nullptr, nullptr, hbuf, nullptr, nullptr};
    gemm_bf16<2><<<dim3(32, 32), 512, SMEM_GEMM>>>(ln2, w1b, TOKS, DFF, DMODEL, e3);

    // FF2 + bias + layer_scale, accumulate into out (fp32)
    Epi e4 = {b2, ls, out, nullptr, nullptr, nullptr};
    gemm_bf16<3><<<dim3(8, 32), 512, SMEM_GEMM>>>(hbuf, w2b, TOKS, DMODEL, DFF, e4);
}

// round 7
// speedup vs baseline: 2.2549x; 1.0406x over previous
#include <cuda_runtime.h>
#include <cuda_fp16.h>
#include <cstdint>
#include <cmath>

// ---------------- problem constants ----------------
#define TOKS 4096
#define DMODEL 2048
#define DFF 8192
#define NHEADS 16
#define DKH 128
#define SEQ 2048
#define BATCH 2

// ---------------- scratch (device globals) ----------------
__device__ __align__(128) __half g_ln1[TOKS * DMODEL];
__device__ __align__(128) __half g_ln2[TOKS * DMODEL];
__device__ __align__(128) __half g_q[TOKS * DMODEL];
__device__ __align__(128) __half g_k[TOKS * DMODEL];
__device__ __align__(128) __half g_v[TOKS * DMODEL];
__device__ __align__(128) __half g_ctx[TOKS * DMODEL];
__device__ __align__(128) __half g_h[TOKS * DFF];
__device__ __align__(128) __half g_wqkv[DMODEL * 3 * DMODEL];
__device__ __align__(128) __half g_wo[DMODEL * DMODEL];
__device__ __align__(128) __half g_w1[DMODEL * DFF];
__device__ __align__(128) __half g_w2[DFF * DMODEL];
__device__ int g_flag[1];

// ---------------- helpers ----------------
__device__ __forceinline__ uint32_t smem_u32(const void* p) {
    uint32_t a;
    asm("{ .reg .u64 t; cvta.to.shared.u64 t, %1; cvt.u32.u64 %0, t; }"
        : "=r"(a) : "l"(p));
    return a;
}

#define CP16(dst, src) \
    asm volatile("cp.async.cg.shared.global [%0], [%1], 16;" \
                 :: "r"(dst), "l"(src) : "memory")
#define CP_COMMIT() asm volatile("cp.async.commit_group;" ::: "memory")
#define CP_WAIT1()  asm volatile("cp.async.wait_group 1;" ::: "memory")

#define LDSM_X4(r, addr) \
    asm volatile("ldmatrix.sync.aligned.m8n8.x4.shared.b16 {%0,%1,%2,%3}, [%4];" \
        : "=r"((r)[0]), "=r"((r)[1]), "=r"((r)[2]), "=r"((r)[3]) : "r"(addr))
#define LDSM_X4T(r, addr) \
    asm volatile("ldmatrix.sync.aligned.m8n8.x4.trans.shared.b16 {%0,%1,%2,%3}, [%4];" \
        : "=r"((r)[0]), "=r"((r)[1]), "=r"((r)[2]), "=r"((r)[3]) : "r"(addr))

__device__ __forceinline__ void mma16(float* c, const uint32_t* a, uint32_t b0, uint32_t b1) {
    asm volatile(
        "mma.sync.aligned.m16n8k16.row.col.f32.f16.f16.f32 "
        "{%0,%1,%2,%3},{%4,%5,%6,%7},{%8,%9},{%0,%1,%2,%3};"
        : "+f"(c[0]), "+f"(c[1]), "+f"(c[2]), "+f"(c[3])
        : "r"(a[0]), "r"(a[1]), "r"(a[2]), "r"(a[3]), "r"(b0), "r"(b1));
}

__device__ __forceinline__ uint32_t pack_h2(float x, float y) {
    __half2 t = __floats2half2_rn(x, y);
    return *(uint32_t*)&t;
}

// ---------------- fp32 -> fp16 converter ----------------
__global__ void cvt_kernel(const float* __restrict__ in, __half* __restrict__ out, int n) {
    int i = (blockIdx.x * blockDim.x + threadIdx.x) * 4;
    if (i < n) {
        float4 v = *(const float4*)(in + i);
        *(__half2*)(out + i)     = __floats2half2_rn(v.x, v.y);
        *(__half2*)(out + i + 2) = __floats2half2_rn(v.z, v.w);
    }
}

// ---------------- LayerNorm: fp32 x -> fp16 ln1, ln2 ----------------
__global__ void ln_kernel(const float* __restrict__ x,
                          const float* __restrict__ ga1, const float* __restrict__ be1,
                          const float* __restrict__ ga2, const float* __restrict__ be2,
                          __half* __restrict__ o1, __half* __restrict__ o2) {
    int t = blockIdx.x;
    int tid = threadIdx.x;
    const float4* xr = (const float4*)(x + (size_t)t * DMODEL);
    float4 a = xr[tid];
    float4 bq = xr[tid + 256];
    float s  = a.x + a.y + a.z + a.w + bq.x + bq.y + bq.z + bq.w;
    float s2 = a.x*a.x + a.y*a.y + a.z*a.z + a.w*a.w +
               bq.x*bq.x + bq.y*bq.y + bq.z*bq.z + bq.w*bq.w;
    #pragma unroll
    for (int o = 16; o; o >>= 1) {
        s  += __shfl_xor_sync(0xffffffffu, s,  o);
        s2 += __shfl_xor_sync(0xffffffffu, s2, o);
    }
    __shared__ float rs[8], rs2[8], stats[2];
    if ((tid & 31) == 0) { rs[tid >> 5] = s; rs2[tid >> 5] = s2; }
    __syncthreads();
    if (tid == 0) {
        float S = 0.f, S2 = 0.f;
        for (int i = 0; i < 8; i++) { S += rs[i]; S2 += rs2[i]; }
        float mu = S * (1.0f / DMODEL);
        float var = S2 * (1.0f / DMODEL) - mu * mu;
        stats[0] = mu;
        stats[1] = rsqrtf(var + 1e-5f);
    }
    __syncthreads();
    float mu = stats[0], r = stats[1];
    const float4* G1 = (const float4*)ga1;
    const float4* B1 = (const float4*)be1;
    const float4* G2 = (const float4*)ga2;
    const float4* B2 = (const float4*)be2;
    __half2* O1 = (__half2*)(o1 + (size_t)t * DMODEL);
    __half2* O2 = (__half2*)(o2 + (size_t)t * DMODEL);
    #pragma unroll
    for (int i = 0; i < 2; i++) {
        int idx = tid + i * 256;
        float4 v = (i == 0) ? a : bq;
        float nx = (v.x - mu) * r, ny = (v.y - mu) * r, nz = (v.z - mu) * r, nw = (v.w - mu) * r;
        float4 g1v = G1[idx], b1v = B1[idx], g2v = G2[idx], b2v = B2[idx];
        O1[idx * 2]     = __floats2half2_rn(nx * g1v.x + b1v.x, ny * g1v.y + b1v.y);
        O1[idx * 2 + 1] = __floats2half2_rn(nz * g1v.z + b1v.z, nw * g1v.w + b1v.w);
        O2[idx * 2]     = __floats2half2_rn(nx * g2v.x + b2v.x, ny * g2v.y + b2v.y);
        O2[idx * 2 + 1] = __floats2half2_rn(nz * g2v.z + b2v.z, nw * g2v.w + b2v.w);
    }
}

// ---------------- mask flag ----------------
__global__ void flag_init(int* flag) { if (threadIdx.x == 0) flag[0] = 1; }

__global__ void mask_reduce(const int* __restrict__ mask, int n, int* __restrict__ flag) {
    bool bad = false;
    for (int i = blockIdx.x * blockDim.x + threadIdx.x; i < n; i += gridDim.x * blockDim.x)
        if (mask[i] == 0) bad = true;
    if (bad) flag[0] = 0;
}

// ================= fp16 GEMM: 128x256x32 tiles, 512 threads (16 warps) =================
#define A_BYTES 10240
#define STAGE   27136
#define NSTAGE  3
#define SMEM_GEMM (STAGE * NSTAGE)

struct Epi {
    const float* c0;
    const float* c1;
    float* o0;
    __half* bo0;
    __half* bo1;
    __half* bo2;
};

template <int E>
__device__ __forceinline__ void emit2(int r, int c, int N, float v0, float v1, const Epi& e) {
    if (E == 0) {
        int which = c >> 11, hh = (c >> 7) & 15, d0 = c & 127;
        __half* dst = (which == 0) ? e.bo0 : ((which == 1) ? e.bo1 : e.bo2);
        int b = r >> 11, s = r & 2047;
        __half* p = dst + (size_t)((b << 4) + hh) * (SEQ * DKH) + (size_t)s * DKH + d0;
        *(__half2*)p = __floats2half2_rn(v0, v1);
    } else if (E == 1) {
        size_t i = (size_t)r * N + c;
        float2 xv = *(const float2*)(e.c0 + i);
        float2 o;
        o.x = xv.x + v0;
        o.y = xv.y + v1;
        *(float2*)(e.o0 + i) = o;
    } else if (E == 2) {
        const float is2 = 0.70710678118654752f;
        float t0 = v0 + e.c0[c], t1 = v1 + e.c0[c + 1];
        float g0 = 0.5f * t0 * (1.0f + erff(t0 * is2));
        float g1 = 0.5f * t1 * (1.0f + erff(t1 * is2));
        __half* p = e.bo0 + (size_t)r * N + c;
        *(__half2*)p = __floats2half2_rn(g0, g1);
    } else {
        size_t i = (size_t)r * N + c;
        float2 bb = *(const float2*)(e.c0 + c);
        float2 ls = *(const float2*)(e.c1 + c);
        float2 o  = *(const float2*)(e.o0 + i);
        o.x += ls.x * (v0 + bb.x);
        o.y += ls.y * (v1 + bb.y);
        *(float2*)(e.o0 + i) = o;
    }
}

__device__ __forceinline__ void gemm_load_stage(const __half* A, const __half* B,
                                                int K, int N, int bm, int bn, int kt,
                                                uint32_t base, int tid) {
    {
        int row = tid >> 2, k8 = tid & 3;
        const __half* src = A + (size_t)(bm + row) * K + kt * 32 + k8 * 8;
        CP16(base + (uint32_t)row * 80 + (uint32_t)k8 * 16, src);
    }
    #pragma unroll
    for (int t = 0; t < 2; t++) {
        int c = tid + t * 512;
        int row = c >> 5, n8 = c & 31;
        const __half* src = B + (size_t)(kt * 32 + row) * N + bn + n8 * 8;
        CP16(base + A_BYTES + (uint32_t)row * 528 + (uint32_t)n8 * 16, src);
    }
    CP_COMMIT();
}

template <int E>
__global__ __launch_bounds__(512, 1)
void gemm_f16(const __half* __restrict__ A, const __half* __restrict__ B,
              int M, int N, int K, Epi e) {
    extern __shared__ __align__(128) char smc[];
    uint32_t smb = smem_u32(smc);
    int tid = threadIdx.x, warp = tid >> 5, lane = tid & 31;
    int bm = blockIdx.y * 128, bn = blockIdx.x * 256;
    int wm = (warp >> 2) * 32, wn = (warp & 3) * 64;
    const int nt = K >> 5;

    float acc[2][8][4];
    #pragma unroll
    for (int i = 0; i < 2; i++)
        #pragma unroll
        for (int j = 0; j < 8; j++)
            #pragma unroll
            for (int k = 0; k < 4; k++) acc[i][j][k] = 0.f;

    gemm_load_stage(A, B, K, N, bm, bn, 0, smb, tid);
    gemm_load_stage(A, B, K, N, bm, bn, 1, smb + STAGE, tid);

    int frow = (lane & 7) + ((lane >> 3) & 1) * 8;
    int hi = lane >> 4;

    for (int i = 0; i < nt; i++) {
        CP_WAIT1();
        __syncthreads();
        if (i + 2 < nt)
            gemm_load_stage(A, B, K, N, bm, bn, i + 2, smb + (uint32_t)((i + 2) % 3) * STAGE, tid);

        uint32_t abase = smb + (uint32_t)(i % 3) * STAGE;
        uint32_t bbase = abase + A_BYTES;
        #pragma unroll
        for (int k16 = 0; k16 < 2; k16++) {
            uint32_t a[2][4], bf[4][4];
            #pragma unroll
            for (int mt = 0; mt < 2; mt++) {
                uint32_t ad = abase + (uint32_t)(wm + mt * 16 + frow) * 80
                            + (uint32_t)(k16 * 2 + hi) * 16;
                LDSM_X4(a[mt], ad);
            }
            #pragma unroll
            for (int nt16 = 0; nt16 < 4; nt16++) {
                uint32_t bd = bbase + (uint32_t)(k16 * 16 + frow) * 528
                            + (uint32_t)(((wn + nt16 * 16) >> 3) + hi) * 16;
                LDSM_X4T(bf[nt16], bd);
            }
            #pragma unroll
            for (int mt = 0; mt < 2; mt++)
                #pragma unroll
                for (int n8 = 0; n8 < 8; n8++)
                    mma16(acc[mt][n8], a[mt], bf[n8 >> 1][(n8 & 1) * 2], bf[n8 >> 1][(n8 & 1) * 2 + 1]);
        }
    }

    int g = lane >> 2, tq = lane & 3;
    #pragma unroll
    for (int mt = 0; mt < 2; mt++) {
        int r0 = bm + wm + mt * 16 + g;
        #pragma unroll
        for (int n8 = 0; n8 < 8; n8++) {
            int c0 = bn + wn + n8 * 8 + tq * 2;
            emit2<E>(r0,     c0, N, acc[mt][n8][0], acc[mt][n8][1], e);
            emit2<E>(r0 + 8, c0, N, acc[mt][n8][2], acc[mt][n8][3], e);
        }
    }
}

// ======== flash attention: fp16 mma16 + ldmatrix, single fp16 P ========
#define AKV_ROWB 272
#define AKV_MATB 17408
#define ATTN_SMEM (AKV_MATB * 5)

__global__ __launch_bounds__(128, 2)
void attn_f16(const __half* __restrict__ Q, const __half* __restrict__ K,
              const __half* __restrict__ V, const int* __restrict__ mask,
              const int* __restrict__ flag, __half* __restrict__ ctx) {
    extern __shared__ __align__(128) char sma[];
    uint32_t smb = smem_u32(sma);
    int tid = threadIdx.x, warp = tid >> 5, lane = tid & 31;
    int g = lane >> 2, tq = lane & 3;
    int frow = (lane & 7) + ((lane >> 3) & 1) * 8;
    int hi = lane >> 4;
    int qt = blockIdx.x, bh = blockIdx.y;
    int b = bh >> 4, h = bh & 15;
    const __half* Qg = Q + (size_t)bh * SEQ * DKH + (size_t)(qt * 64) * DKH;
    const __half* Kg = K + (size_t)bh * SEQ * DKH;
    const __half* Vg = V + (size_t)bh * SEQ * DKH;
    int q0 = qt * 64 + warp * 16;
    int allv = flag[0];

    {
        int row = tid >> 1, c16b = (tid & 1) * 8;
        #pragma unroll
        for (int t = 0; t < 8; t++) {
            CP16(smb + (uint32_t)row * AKV_ROWB + (uint32_t)(c16b + t) * 16,
                 Qg + (size_t)row * DKH + (c16b + t) * 8);
        }
        #pragma unroll
        for (int t = 0; t < 8; t++) {
            CP16(smb + AKV_MATB + (uint32_t)row * AKV_ROWB + (uint32_t)(c16b + t) * 16,
                 Kg + (size_t)row * DKH + (c16b + t) * 8);
            CP16(smb + AKV_MATB + AKV_MATB + (uint32_t)row * AKV_ROWB + (uint32_t)(c16b + t) * 16,
                 Vg + (size_t)row * DKH + (c16b + t) * 8);
        }
        CP_COMMIT();
        #pragma unroll
        for (int t = 0; t < 8; t++) {
            CP16(smb + AKV_MATB * 3 + (uint32_t)row * AKV_ROWB + (uint32_t)(c16b + t) * 16,
                 Kg + (size_t)(64 + row) * DKH + (c16b + t) * 8);
            CP16(smb + AKV_MATB * 4 + (uint32_t)row * AKV_ROWB + (uint32_t)(c16b + t) * 16,
                 Vg + (size_t)(64 + row) * DKH + (c16b + t) * 8);
        }
        CP_COMMIT();
    }

    CP_WAIT1();
    __syncthreads();

    uint32_t qa[8][4];
    #pragma unroll
    for (int k16 = 0; k16 < 8; k16++)
        LDSM_X4(qa[k16], smb + (uint32_t)(warp * 16 + frow) * AKV_ROWB
                             + (uint32_t)(k16 * 2 + hi) * 16);

    float o[16][4];
    #pragma unroll
    for (int i = 0; i < 16; i++)
        #pragma unroll
        for (int j = 0; j < 4; j++) o[i][j] = 0.f;
    float mA = -1e30f, mB = -1e30f, lA = 0.f, lB = 0.f;

    for (int j = 0; j < 32; j++) {
        if (j > 0) { CP_WAIT1(); __syncthreads(); }
        int buf = j & 1;
        uint32_t kbase = smb + AKV_MATB + (uint32_t)buf * (2 * AKV_MATB);
        uint32_t vbase = kbase + AKV_MATB;

        float sc[8][4];
        #pragma unroll
        for (int ni = 0; ni < 8; ni++)
            #pragma unroll
            for (int c = 0; c < 4; c++) sc[ni][c] = 0.f;
        #pragma unroll
        for (int k16 = 0; k16 < 8; k16++) {
            #pragma unroll
            for (int n16 = 0; n16 < 4; n16++) {
                uint32_t kb[4];
                LDSM_X4(kb, kbase + (uint32_t)(n16 * 16 + frow) * AKV_ROWB
                                  + (uint32_t)(k16 * 2 + hi) * 16);
                mma16(sc[n16 * 2],     qa[k16], kb[0], kb[2]);
                mma16(sc[n16 * 2 + 1], qa[k16], kb[1], kb[3]);
            }
        }
        const float sscale = 0.0883883476483184f;
        #pragma unroll
        for (int ni = 0; ni < 8; ni++)
            #pragma unroll
            for (int c = 0; c < 4; c++) sc[ni][c] *= sscale;

        if (!allv) {
            #pragma unroll
            for (int ni = 0; ni < 8; ni++) {
                int kc = j * 64 + ni * 8 + tq * 2;
                int r0 = q0 + g, r1 = q0 + g + 8;
                if (mask[(size_t)r0 * SEQ + kc] == 0)     sc[ni][0] = -1e9f;
                if (mask[(size_t)r0 * SEQ + kc + 1] == 0) sc[ni][1] = -1e9f;
                if (mask[(size_t)r1 * SEQ + kc] == 0)     sc[ni][2] = -1e9f;
                if (mask[(size_t)r1 * SEQ + kc + 1] == 0) sc[ni][3] = -1e9f;
            }
        }

        float mxA = -1e30f, mxB = -1e30f;
        #pragma unroll
        for (int ni = 0; ni < 8; ni++) {
            mxA = fmaxf(mxA, fmaxf(sc[ni][0], sc[ni][1]));
            mxB = fmaxf(mxB, fmaxf(sc[ni][2], sc[ni][3]));
        }
        mxA = fmaxf(mxA, __shfl_xor_sync(0xffffffffu, mxA, 1));
        mxA = fmaxf(mxA, __shfl_xor_sync(0xffffffffu, mxA, 2));
        mxB = fmaxf(mxB, __shfl_xor_sync(0xffffffffu, mxB, 1));
        mxB = fmaxf(mxB, __shfl_xor_sync(0xffffffffu, mxB, 2));
        float mAn = fmaxf(mA, mxA), mBn = fmaxf(mB, mxB);
        float aA = __expf(mA - mAn), aB = __expf(mB - mBn);
        float sA = 0.f, sB = 0.f;
        #pragma unroll
        for (int ni = 0; ni < 8; ni++) {
            sc[ni][0] = __expf(sc[ni][0] - mAn); sA += sc[ni][0];
            sc[ni][1] = __expf(sc[ni][1] - mAn); sA += sc[ni][1];
            sc[ni][2] = __expf(sc[ni][2] - mBn); sB += sc[ni][2];
            sc[ni][3] = __expf(sc[ni][3] - mBn); sB += sc[ni][3];
        }
        sA += __shfl_xor_sync(0xffffffffu, sA, 1);
        sA += __shfl_xor_sync(0xffffffffu, sA, 2);
        sB += __shfl_xor_sync(0xffffffffu, sB, 1);
        sB += __shfl_xor_sync(0xffffffffu, sB, 2);
        lA = lA * aA + sA;
        lB = lB * aB + sB;
        mA = mAn; mB = mBn;
        #pragma unroll
        for (int ni = 0; ni < 16; ni++) {
            o[ni][0] *= aA; o[ni][1] *= aA;
            o[ni][2] *= aB; o[ni][3] *= aB;
        }

        // P -> fp16 A-fragments (registers only, single precision level)
        uint32_t pa[4][4];
        #pragma unroll
        for (int jj = 0; jj < 4; jj++) {
            float* e0 = sc[2 * jj];
            float* e1 = sc[2 * jj + 1];
            pa[jj][0] = pack_h2(e0[0], e0[1]);
            pa[jj][1] = pack_h2(e0[2], e0[3]);
            pa[jj][2] = pack_h2(e1[0], e1[1]);
            pa[jj][3] = pack_h2(e1[2], e1[3]);
        }

        #pragma unroll
        for (int k16 = 0; k16 < 4; k16++) {
            #pragma unroll
            for (int n16 = 0; n16 < 8; n16++) {
                uint32_t vb4[4];
                LDSM_X4T(vb4, vbase + (uint32_t)(k16 * 16 + frow) * AKV_ROWB
                                    + (uint32_t)(n16 * 2 + hi) * 16);
                mma16(o[n16 * 2],     pa[k16], vb4[0], vb4[1]);
                mma16(o[n16 * 2 + 1], pa[k16], vb4[2], vb4[3]);
            }
        }

        __syncthreads();
        if (j + 2 < 32) {
            int row = tid >> 1, c16b = (tid & 1) * 8;
            uint32_t kd = smb + AKV_MATB + (uint32_t)buf * (2 * AKV_MATB);
            const __half* ks = Kg + (size_t)((j + 2) * 64 + row) * DKH;
            const __half* vs = Vg + (size_t)((j + 2) * 64 + row) * DKH;
            #pragma unroll
            for (int t = 0; t < 8; t++) {
                CP16(kd + (uint32_t)row * AKV_ROWB + (uint32_t)(c16b + t) * 16,
                     ks + (c16b + t) * 8);
                CP16(kd + AKV_MATB + (uint32_t)row * AKV_ROWB + (uint32_t)(c16b + t) * 16,
                     vs + (c16b + t) * 8);
            }
            CP_COMMIT();
        }
    }

    float rA = 1.f / lA, rB = 1.f / lB;
    int tok0 = b * SEQ + q0 + g, tok1 = tok0 + 8;
    #pragma unroll
    for (int ni = 0; ni < 16; ni++) {
        int d = ni * 8 + tq * 2;
        __half* p0 = ctx + (size_t)tok0 * DMODEL + h * DKH + d;
        __half* p1 = ctx + (size_t)tok1 * DMODEL + h * DKH + d;
        *(__half2*)p0 = __floats2half2_rn(o[ni][0] * rA, o[ni][1] * rA);
        *(__half2*)p1 = __floats2half2_rn(o[ni][2] * rB, o[ni][3] * rB);
    }
}

// ---------------- launch ----------------
extern "C" void kernel_launch(void* const* d_in, const int* in_sizes, int n_in,
                              void* d_out, int out_size) {
    const float* x     = (const float*)d_in[0];
    const int*   mask  = (const int*)d_in[1];
    const float* w_qkv = (const float*)d_in[2];
    const float* w_o   = (const float*)d_in[3];
    const float* ga1   = (const float*)d_in[4];
    const float* be1   = (const float*)d_in[5];
    const float* ga2   = (const float*)d_in[6];
    const float* be2   = (const float*)d_in[7];
    const float* w1    = (const float*)d_in[8];
    const float* b1    = (const float*)d_in[9];
    const float* w2    = (const float*)d_in[10];
    const float* b2    = (const float*)d_in[11];
    const float* ls    = (const float*)d_in[12];
    float* out = (float*)d_out;

    __half *ln1, *ln2, *q, *k, *v, *ctx, *hbuf, *wqkvb, *wob, *w1b, *w2b;
    int* flag;
    cudaGetSymbolAddress((void**)&ln1,   g_ln1);
    cudaGetSymbolAddress((void**)&ln2,   g_ln2);
    cudaGetSymbolAddress((void**)&q,     g_q);
    cudaGetSymbolAddress((void**)&k,     g_k);
    cudaGetSymbolAddress((void**)&v,     g_v);
    cudaGetSymbolAddress((void**)&ctx,   g_ctx);
    cudaGetSymbolAddress((void**)&hbuf,  g_h);
    cudaGetSymbolAddress((void**)&wqkvb, g_wqkv);
    cudaGetSymbolAddress((void**)&wob,   g_wo);
    cudaGetSymbolAddress((void**)&w1b,   g_w1);
    cudaGetSymbolAddress((void**)&w2b,   g_w2);
    cudaGetSymbolAddress((void**)&flag,  g_flag);

    cudaFuncSetAttribute(attn_f16, cudaFuncAttributeMaxDynamicSharedMemorySize, ATTN_SMEM);
    cudaFuncSetAttribute(gemm_f16<0>, cudaFuncAttributeMaxDynamicSharedMemorySize, SMEM_GEMM);
    cudaFuncSetAttribute(gemm_f16<1>, cudaFuncAttributeMaxDynamicSharedMemorySize, SMEM_GEMM);
    cudaFuncSetAttribute(gemm_f16<2>, cudaFuncAttributeMaxDynamicSharedMemorySize, SMEM_GEMM);
    cudaFuncSetAttribute(gemm_f16<3>, cudaFuncAttributeMaxDynamicSharedMemorySize, SMEM_GEMM);

    // launches 0-3: weight conversions (fp32 -> fp16)
    cvt_kernel<<<(DMODEL * 3 * DMODEL) / 4 / 256, 256>>>(w_qkv, wqkvb, DMODEL * 3 * DMODEL);
    cvt_kernel<<<(DMODEL * DMODEL) / 4 / 256, 256>>>(w_o, wob, DMODEL * DMODEL);
    cvt_kernel<<<(DMODEL * DFF) / 4 / 256, 256>>>(w1, w1b, DMODEL * DFF);
    cvt_kernel<<<(DFF * DMODEL) / 4 / 256, 256>>>(w2, w2b, DFF * DMODEL);

    // launch 4: layernorms
    ln_kernel<<<TOKS, 256>>>(x, ga1, be1, ga2, be2, ln1, ln2);

    // launch 5 (ncu capture slot): FF1 + exact gelu -> fp16 h
    Epi e3 = {b1, nullptr, nullptr, hbuf, nullptr, nullptr};
    gemm_f16<2><<<dim3(32, 32), 512, SMEM_GEMM>>>(ln2, w1b, TOKS, DFF, DMODEL, e3);

    // QKV projection -> fp16 q/k/v in head layout
    Epi e1 = {nullptr, nullptr, nullptr, q, k, v};
    gemm_f16<0><<<dim3(24, 32), 512, SMEM_GEMM>>>(ln1, wqkvb, TOKS, 3 * DMODEL, DMODEL, e1);

    // mask all-visible flag
    flag_init<<<1, 32>>>(flag);
    mask_reduce<<<256, 256>>>(mask, in_sizes[1], flag);

    // attention -> fp16 ctx
    attn_f16<<<dim3(32, 32), 128, ATTN_SMEM>>>(q, k, v, mask, flag, ctx);

    // output projection + residual with fp32 x: out = x + ctx @ w_o
    Epi e2 = {x, nullptr, out, nullptr, nullptr, nullptr};
    gemm_f16<1><<<dim3(8, 32), 512, SMEM_GEMM>>>(ctx, wob, TOKS, DMODEL, DMODEL, e2);

    // FF2 + bias + layer_scale, accumulate into out (fp32)
    Epi e4 = {b2, ls, out, nullptr, nullptr, nullptr};
    gemm_f16<3><<<dim3(8, 32), 512, SMEM_GEMM>>>(hbuf, w2b, TOKS, DMODEL, DFF, e4);
}

// round 8
// speedup vs baseline: 2.3327x; 1.0345x over previous
#include <cuda_runtime.h>
#include <cuda_fp16.h>
#include <cstdint>
#include <cmath>

// ---------------- problem constants ----------------
#define TOKS 4096
#define DMODEL 2048
#define DFF 8192
#define NHEADS 16
#define DKH 128
#define SEQ 2048
#define BATCH 2

// ---------------- scratch (device globals) ----------------
__device__ __align__(128) __half g_ln1[TOKS * DMODEL];
__device__ __align__(128) __half g_ln2[TOKS * DMODEL];
__device__ __align__(128) __half g_q[TOKS * DMODEL];
__device__ __align__(128) __half g_k[TOKS * DMODEL];
__device__ __align__(128) __half g_v[TOKS * DMODEL];
__device__ __align__(128) __half g_ctx[TOKS * DMODEL];
__device__ __align__(128) __half g_h[TOKS * DFF];
__device__ __align__(128) __half g_wqkv[DMODEL * 3 * DMODEL];
__device__ __align__(128) __half g_wo[DMODEL * DMODEL];
__device__ __align__(128) __half g_w1[DMODEL * DFF];
__device__ __align__(128) __half g_w2[DFF * DMODEL];
__device__ int g_flag[1];

// ---------------- helpers ----------------
__device__ __forceinline__ uint32_t smem_u32(const void* p) {
    uint32_t a;
    asm("{ .reg .u64 t; cvta.to.shared.u64 t, %1; cvt.u32.u64 %0, t; }"
        : "=r"(a) : "l"(p));
    return a;
}

#define CP16(dst, src) \
    asm volatile("cp.async.cg.shared.global [%0], [%1], 16;" \
                 :: "r"(dst), "l"(src) : "memory")
#define CP_COMMIT() asm volatile("cp.async.commit_group;" ::: "memory")
#define CP_WAIT1()  asm volatile("cp.async.wait_group 1;" ::: "memory")

#define LDSM_X4(r, addr) \
    asm volatile("ldmatrix.sync.aligned.m8n8.x4.shared.b16 {%0,%1,%2,%3}, [%4];" \
        : "=r"((r)[0]), "=r"((r)[1]), "=r"((r)[2]), "=r"((r)[3]) : "r"(addr))
#define LDSM_X4T(r, addr) \
    asm volatile("ldmatrix.sync.aligned.m8n8.x4.trans.shared.b16 {%0,%1,%2,%3}, [%4];" \
        : "=r"((r)[0]), "=r"((r)[1]), "=r"((r)[2]), "=r"((r)[3]) : "r"(addr))

__device__ __forceinline__ void mma16(float* c, const uint32_t* a, uint32_t b0, uint32_t b1) {
    asm volatile(
        "mma.sync.aligned.m16n8k16.row.col.f32.f16.f16.f32 "
        "{%0,%1,%2,%3},{%4,%5,%6,%7},{%8,%9},{%0,%1,%2,%3};"
        : "+f"(c[0]), "+f"(c[1]), "+f"(c[2]), "+f"(c[3])
        : "r"(a[0]), "r"(a[1]), "r"(a[2]), "r"(a[3]), "r"(b0), "r"(b1));
}

__device__ __forceinline__ uint32_t pack_h2(float x, float y) {
    __half2 t = __floats2half2_rn(x, y);
    return *(uint32_t*)&t;
}

// ---------------- fp32 -> fp16 converter (all 4 weights, one launch) ----------------
#define CVT_N0 (DMODEL * 3 * DMODEL / 4)
#define CVT_N1 (DMODEL * DMODEL / 4)
#define CVT_N2 (DMODEL * DFF / 4)
__global__ void cvt_all(const float* __restrict__ wqkv, const float* __restrict__ wo,
                        const float* __restrict__ w1, const float* __restrict__ w2,
                        __half* __restrict__ oqkv, __half* __restrict__ owo,
                        __half* __restrict__ ow1, __half* __restrict__ ow2) {
    int idx = blockIdx.x * blockDim.x + threadIdx.x;
    const float* in;
    __half* out;
    int off;
    if (idx < CVT_N0)                          { in = wqkv; out = oqkv; off = idx; }
    else if (idx < CVT_N0 + CVT_N1)            { in = wo;   out = owo;  off = idx - CVT_N0; }
    else if (idx < CVT_N0 + CVT_N1 + CVT_N2)   { in = w1;   out = ow1;  off = idx - CVT_N0 - CVT_N1; }
    else                                       { in = w2;   out = ow2;  off = idx - CVT_N0 - CVT_N1 - CVT_N2; }
    float4 v = ((const float4*)in)[off];
    ((__half2*)out)[off * 2]     = __floats2half2_rn(v.x, v.y);
    ((__half2*)out)[off * 2 + 1] = __floats2half2_rn(v.z, v.w);
}

// ---------------- LayerNorm: fp32 x -> fp16 ln1, ln2 ----------------
__global__ void ln_kernel(const float* __restrict__ x,
                          const float* __restrict__ ga1, const float* __restrict__ be1,
                          const float* __restrict__ ga2, const float* __restrict__ be2,
                          __half* __restrict__ o1, __half* __restrict__ o2) {
    int t = blockIdx.x;
    int tid = threadIdx.x;
    const float4* xr = (const float4*)(x + (size_t)t * DMODEL);
    float4 a = xr[tid];
    float4 bq = xr[tid + 256];
    float s  = a.x + a.y + a.z + a.w + bq.x + bq.y + bq.z + bq.w;
    float s2 = a.x*a.x + a.y*a.y + a.z*a.z + a.w*a.w +
               bq.x*bq.x + bq.y*bq.y + bq.z*bq.z + bq.w*bq.w;
    #pragma unroll
    for (int o = 16; o; o >>= 1) {
        s  += __shfl_xor_sync(0xffffffffu, s,  o);
        s2 += __shfl_xor_sync(0xffffffffu, s2, o);
    }
    __shared__ float rs[8], rs2[8], stats[2];
    if ((tid & 31) == 0) { rs[tid >> 5] = s; rs2[tid >> 5] = s2; }
    __syncthreads();
    if (tid == 0) {
        float S = 0.f, S2 = 0.f;
        for (int i = 0; i < 8; i++) { S += rs[i]; S2 += rs2[i]; }
        float mu = S * (1.0f / DMODEL);
        float var = S2 * (1.0f / DMODEL) - mu * mu;
        stats[0] = mu;
        stats[1] = rsqrtf(var + 1e-5f);
    }
    __syncthreads();
    float mu = stats[0], r = stats[1];
    const float4* G1 = (const float4*)ga1;
    const float4* B1 = (const float4*)be1;
    const float4* G2 = (const float4*)ga2;
    const float4* B2 = (const float4*)be2;
    __half2* O1 = (__half2*)(o1 + (size_t)t * DMODEL);
    __half2* O2 = (__half2*)(o2 + (size_t)t * DMODEL);
    #pragma unroll
    for (int i = 0; i < 2; i++) {
        int idx = tid + i * 256;
        float4 v = (i == 0) ? a : bq;
        float nx = (v.x - mu) * r, ny = (v.y - mu) * r, nz = (v.z - mu) * r, nw = (v.w - mu) * r;
        float4 g1v = G1[idx], b1v = B1[idx], g2v = G2[idx], b2v = B2[idx];
        O1[idx * 2]     = __floats2half2_rn(nx * g1v.x + b1v.x, ny * g1v.y + b1v.y);
        O1[idx * 2 + 1] = __floats2half2_rn(nz * g1v.z + b1v.z, nw * g1v.w + b1v.w);
        O2[idx * 2]     = __floats2half2_rn(nx * g2v.x + b2v.x, ny * g2v.y + b2v.y);
        O2[idx * 2 + 1] = __floats2half2_rn(nz * g2v.z + b2v.z, nw * g2v.w + b2v.w);
    }
}

// ---------------- mask flag ----------------
__global__ void flag_init(int* flag) { if (threadIdx.x == 0) flag[0] = 1; }

__global__ void mask_reduce(const int* __restrict__ mask, int n, int* __restrict__ flag) {
    bool bad = false;
    for (int i = blockIdx.x * blockDim.x + threadIdx.x; i < n; i += gridDim.x * blockDim.x)
        if (mask[i] == 0) bad = true;
    if (bad) flag[0] = 0;
}

// ================= fp16 GEMM: 128x256x32 tiles, 512 threads (16 warps) =================
#define A_BYTES 10240
#define STAGE   27136
#define NSTAGE  3
#define SMEM_GEMM (STAGE * NSTAGE)

struct Epi {
    const float* c0;   // bias
    const float* c1;   // layer_scale
    const float* c2;   // x residual
    float* o0;         // fp32 out
    __half* bo0;
    __half* bo1;
    __half* bo2;
};

// E=0: QKV head split.  E=1: out += v (WO accumulate).
// E=2: h = gelu(v + b1). E=3: out = x + ls*(v + b2) (FF2 init).
template <int E>
__device__ __forceinline__ void emit2(int r, int c, int N, float v0, float v1, const Epi& e) {
    if (E == 0) {
        int which = c >> 11, hh = (c >> 7) & 15, d0 = c & 127;
        __half* dst = (which == 0) ? e.bo0 : ((which == 1) ? e.bo1 : e.bo2);
        int b = r >> 11, s = r & 2047;
        __half* p = dst + (size_t)((b << 4) + hh) * (SEQ * DKH) + (size_t)s * DKH + d0;
        *(__half2*)p = __floats2half2_rn(v0, v1);
    } else if (E == 1) {
        size_t i = (size_t)r * N + c;
        float2 o = *(const float2*)(e.o0 + i);
        o.x += v0;
        o.y += v1;
        *(float2*)(e.o0 + i) = o;
    } else if (E == 2) {
        const float is2 = 0.70710678118654752f;
        float t0 = v0 + e.c0[c], t1 = v1 + e.c0[c + 1];
        float g0 = 0.5f * t0 * (1.0f + erff(t0 * is2));
        float g1 = 0.5f * t1 * (1.0f + erff(t1 * is2));
        __half* p = e.bo0 + (size_t)r * N + c;
        *(__half2*)p = __floats2half2_rn(g0, g1);
    } else {
        size_t i = (size_t)r * N + c;
        float2 xv = *(const float2*)(e.c2 + i);
        float2 bb = *(const float2*)(e.c0 + c);
        float2 ls = *(const float2*)(e.c1 + c);
        float2 o;
        o.x = xv.x + ls.x * (v0 + bb.x);
        o.y = xv.y + ls.y * (v1 + bb.y);
        *(float2*)(e.o0 + i) = o;
    }
}

__device__ __forceinline__ void gemm_load_stage(const __half* A, const __half* B,
                                                int K, int N, int bm, int bn, int kt,
                                                uint32_t base, int tid) {
    {
        int row = tid >> 2, k8 = tid & 3;
        const __half* src = A + (size_t)(bm + row) * K + kt * 32 + k8 * 8;
        CP16(base + (uint32_t)row * 80 + (uint32_t)k8 * 16, src);
    }
    #pragma unroll
    for (int t = 0; t < 2; t++) {
        int c = tid + t * 512;
        int row = c >> 5, n8 = c & 31;
        const __half* src = B + (size_t)(kt * 32 + row) * N + bn + n8 * 8;
        CP16(base + A_BYTES + (uint32_t)row * 528 + (uint32_t)n8 * 16, src);
    }
    CP_COMMIT();
}

template <int E>
__global__ __launch_bounds__(512, 1)
void gemm_f16(const __half* __restrict__ A, const __half* __restrict__ B,
              int M, int N, int K, Epi e) {
    extern __shared__ __align__(128) char smc[];
    uint32_t smb = smem_u32(smc);
    int tid = threadIdx.x, warp = tid >> 5, lane = tid & 31;
    int bm = blockIdx.y * 128, bn = blockIdx.x * 256;
    int wm = (warp >> 2) * 32, wn = (warp & 3) * 64;
    const int nt = K >> 5;

    float acc[2][8][4];
    #pragma unroll
    for (int i = 0; i < 2; i++)
        #pragma unroll
        for (int j = 0; j < 8; j++)
            #pragma unroll
            for (int k = 0; k < 4; k++) acc[i][j][k] = 0.f;

    gemm_load_stage(A, B, K, N, bm, bn, 0, smb, tid);
    gemm_load_stage(A, B, K, N, bm, bn, 1, smb + STAGE, tid);

    int frow = (lane & 7) + ((lane >> 3) & 1) * 8;
    int hi = lane >> 4;

    for (int i = 0; i < nt; i++) {
        CP_WAIT1();
        __syncthreads();
        if (i + 2 < nt)
            gemm_load_stage(A, B, K, N, bm, bn, i + 2, smb + (uint32_t)((i + 2) % 3) * STAGE, tid);

        uint32_t abase = smb + (uint32_t)(i % 3) * STAGE;
        uint32_t bbase = abase + A_BYTES;
        #pragma unroll
        for (int k16 = 0; k16 < 2; k16++) {
            uint32_t a[2][4], bf[4][4];
            #pragma unroll
            for (int mt = 0; mt < 2; mt++) {
                uint32_t ad = abase + (uint32_t)(wm + mt * 16 + frow) * 80
                            + (uint32_t)(k16 * 2 + hi) * 16;
                LDSM_X4(a[mt], ad);
            }
            #pragma unroll
            for (int nt16 = 0; nt16 < 4; nt16++) {
                uint32_t bd = bbase + (uint32_t)(k16 * 16 + frow) * 528
                            + (uint32_t)(((wn + nt16 * 16) >> 3) + hi) * 16;
                LDSM_X4T(bf[nt16], bd);
            }
            #pragma unroll
            for (int mt = 0; mt < 2; mt++)
                #pragma unroll
                for (int n8 = 0; n8 < 8; n8++)
                    mma16(acc[mt][n8], a[mt], bf[n8 >> 1][(n8 & 1) * 2], bf[n8 >> 1][(n8 & 1) * 2 + 1]);
        }
    }

    int g = lane >> 2, tq = lane & 3;
    #pragma unroll
    for (int mt = 0; mt < 2; mt++) {
        int r0 = bm + wm + mt * 16 + g;
        #pragma unroll
        for (int n8 = 0; n8 < 8; n8++) {
            int c0 = bn + wn + n8 * 8 + tq * 2;
            emit2<E>(r0,     c0, N, acc[mt][n8][0], acc[mt][n8][1], e);
            emit2<E>(r0 + 8, c0, N, acc[mt][n8][2], acc[mt][n8][3], e);
        }
    }
}

// ======== flash attention: fp16 mma16 + ldmatrix, single fp16 P ========
#define AKV_ROWB 272
#define AKV_MATB 17408
#define ATTN_SMEM (AKV_MATB * 5)

__global__ __launch_bounds__(128, 2)
void attn_f16(const __half* __restrict__ Q, const __half* __restrict__ K,
              const __half* __restrict__ V, const int* __restrict__ mask,
              const int* __restrict__ flag, __half* __restrict__ ctx) {
    extern __shared__ __align__(128) char sma[];
    uint32_t smb = smem_u32(sma);
    int tid = threadIdx.x, warp = tid >> 5, lane = tid & 31;
    int g = lane >> 2, tq = lane & 3;
    int frow = (lane & 7) + ((lane >> 3) & 1) * 8;
    int hi = lane >> 4;
    int qt = blockIdx.x, bh = blockIdx.y;
    int b = bh >> 4, h = bh & 15;
    const __half* Qg = Q + (size_t)bh * SEQ * DKH + (size_t)(qt * 64) * DKH;
    const __half* Kg = K + (size_t)bh * SEQ * DKH;
    const __half* Vg = V + (size_t)bh * SEQ * DKH;
    int q0 = qt * 64 + warp * 16;
    int allv = flag[0];

    {
        int row = tid >> 1, c16b = (tid & 1) * 8;
        #pragma unroll
        for (int t = 0; t < 8; t++) {
            CP16(smb + (uint32_t)row * AKV_ROWB + (uint32_t)(c16b + t) * 16,
                 Qg + (size_t)row * DKH + (c16b + t) * 8);
        }
        #pragma unroll
        for (int t = 0; t < 8; t++) {
            CP16(smb + AKV_MATB + (uint32_t)row * AKV_ROWB + (uint32_t)(c16b + t) * 16,
                 Kg + (size_t)row * DKH + (c16b + t) * 8);
            CP16(smb + AKV_MATB + AKV_MATB + (uint32_t)row * AKV_ROWB + (uint32_t)(c16b + t) * 16,
                 Vg + (size_t)row * DKH + (c16b + t) * 8);
        }
        CP_COMMIT();
        #pragma unroll
        for (int t = 0; t < 8; t++) {
            CP16(smb + AKV_MATB * 3 + (uint32_t)row * AKV_ROWB + (uint32_t)(c16b + t) * 16,
                 Kg + (size_t)(64 + row) * DKH + (c16b + t) * 8);
            CP16(smb + AKV_MATB * 4 + (uint32_t)row * AKV_ROWB + (uint32_t)(c16b + t) * 16,
                 Vg + (size_t)(64 + row) * DKH + (c16b + t) * 8);
        }
        CP_COMMIT();
    }

    CP_WAIT1();
    __syncthreads();

    uint32_t qa[8][4];
    #pragma unroll
    for (int k16 = 0; k16 < 8; k16++)
        LDSM_X4(qa[k16], smb + (uint32_t)(warp * 16 + frow) * AKV_ROWB
                             + (uint32_t)(k16 * 2 + hi) * 16);

    float o[16][4];
    #pragma unroll
    for (int i = 0; i < 16; i++)
        #pragma unroll
        for (int j = 0; j < 4; j++) o[i][j] = 0.f;
    float mA = -1e30f, mB = -1e30f, lA = 0.f, lB = 0.f;

    for (int j = 0; j < 32; j++) {
        if (j > 0) { CP_WAIT1(); __syncthreads(); }
        int buf = j & 1;
        uint32_t kbase = smb + AKV_MATB + (uint32_t)buf * (2 * AKV_MATB);
        uint32_t vbase = kbase + AKV_MATB;

        float sc[8][4];
        #pragma unroll
        for (int ni = 0; ni < 8; ni++)
            #pragma unroll
            for (int c = 0; c < 4; c++) sc[ni][c] = 0.f;
        #pragma unroll
        for (int k16 = 0; k16 < 8; k16++) {
            #pragma unroll
            for (int n16 = 0; n16 < 4; n16++) {
                uint32_t kb[4];
                LDSM_X4(kb, kbase + (uint32_t)(n16 * 16 + frow) * AKV_ROWB
                                  + (uint32_t)(k16 * 2 + hi) * 16);
                mma16(sc[n16 * 2],     qa[k16], kb[0], kb[2]);
                mma16(sc[n16 * 2 + 1], qa[k16], kb[1], kb[3]);
            }
        }
        const float sscale = 0.0883883476483184f;
        #pragma unroll
        for (int ni = 0; ni < 8; ni++)
            #pragma unroll
            for (int c = 0; c < 4; c++) sc[ni][c] *= sscale;

        if (!allv) {
            #pragma unroll
            for (int ni = 0; ni < 8; ni++) {
                int kc = j * 64 + ni * 8 + tq * 2;
                int r0 = q0 + g, r1 = q0 + g + 8;
                if (mask[(size_t)r0 * SEQ + kc] == 0)     sc[ni][0] = -1e9f;
                if (mask[(size_t)r0 * SEQ + kc + 1] == 0) sc[ni][1] = -1e9f;
                if (mask[(size_t)r1 * SEQ + kc] == 0)     sc[ni][2] = -1e9f;
                if (mask[(size_t)r1 * SEQ + kc + 1] == 0) sc[ni][3] = -1e9f;
            }
        }

        float mxA = -1e30f, mxB = -1e30f;
        #pragma unroll
        for (int ni = 0; ni < 8; ni++) {
            mxA = fmaxf(mxA, fmaxf(sc[ni][0], sc[ni][1]));
            mxB = fmaxf(mxB, fmaxf(sc[ni][2], sc[ni][3]));
        }
        mxA = fmaxf(mxA, __shfl_xor_sync(0xffffffffu, mxA, 1));
        mxA = fmaxf(mxA, __shfl_xor_sync(0xffffffffu, mxA, 2));
        mxB = fmaxf(mxB, __shfl_xor_sync(0xffffffffu, mxB, 1));
        mxB = fmaxf(mxB, __shfl_xor_sync(0xffffffffu, mxB, 2));
        float mAn = fmaxf(mA, mxA), mBn = fmaxf(mB, mxB);
        float aA = __expf(mA - mAn), aB = __expf(mB - mBn);
        float sA = 0.f, sB = 0.f;
        #pragma unroll
        for (int ni = 0; ni < 8; ni++) {
            sc[ni][0] = __expf(sc[ni][0] - mAn); sA += sc[ni][0];
            sc[ni][1] = __expf(sc[ni][1] - mAn); sA += sc[ni][1];
            sc[ni][2] = __expf(sc[ni][2] - mBn); sB += sc[ni][2];
            sc[ni][3] = __expf(sc[ni][3] - mBn); sB += sc[ni][3];
        }
        sA += __shfl_xor_sync(0xffffffffu, sA, 1);
        sA += __shfl_xor_sync(0xffffffffu, sA, 2);
        sB += __shfl_xor_sync(0xffffffffu, sB, 1);
        sB += __shfl_xor_sync(0xffffffffu, sB, 2);
        lA = lA * aA + sA;
        lB = lB * aB + sB;
        mA = mAn; mB = mBn;
        #pragma unroll
        for (int ni = 0; ni < 16; ni++) {
            o[ni][0] *= aA; o[ni][1] *= aA;
            o[ni][2] *= aB; o[ni][3] *= aB;
        }

        uint32_t pa[4][4];
        #pragma unroll
        for (int jj = 0; jj < 4; jj++) {
            float* e0 = sc[2 * jj];
            float* e1 = sc[2 * jj + 1];
            pa[jj][0] = pack_h2(e0[0], e0[1]);
            pa[jj][1] = pack_h2(e0[2], e0[3]);
            pa[jj][2] = pack_h2(e1[0], e1[1]);
            pa[jj][3] = pack_h2(e1[2], e1[3]);
        }

        #pragma unroll
        for (int k16 = 0; k16 < 4; k16++) {
            #pragma unroll
            for (int n16 = 0; n16 < 8; n16++) {
                uint32_t vb4[4];
                LDSM_X4T(vb4, vbase + (uint32_t)(k16 * 16 + frow) * AKV_ROWB
                                    + (uint32_t)(n16 * 2 + hi) * 16);
                mma16(o[n16 * 2],     pa[k16], vb4[0], vb4[1]);
                mma16(o[n16 * 2 + 1], pa[k16], vb4[2], vb4[3]);
            }
        }

        __syncthreads();
        if (j + 2 < 32) {
            int row = tid >> 1, c16b = (tid & 1) * 8;
            uint32_t kd = smb + AKV_MATB + (uint32_t)buf * (2 * AKV_MATB);
            const __half* ks = Kg + (size_t)((j + 2) * 64 + row) * DKH;
            const __half* vs = Vg + (size_t)((j + 2) * 64 + row) * DKH;
            #pragma unroll
            for (int t = 0; t < 8; t++) {
                CP16(kd + (uint32_t)row * AKV_ROWB + (uint32_t)(c16b + t) * 16,
                     ks + (c16b + t) * 8);
                CP16(kd + AKV_MATB + (uint32_t)row * AKV_ROWB + (uint32_t)(c16b + t) * 16,
                     vs + (c16b + t) * 8);
            }
            CP_COMMIT();
        }
    }

    float rA = 1.f / lA, rB = 1.f / lB;
    int tok0 = b * SEQ + q0 + g, tok1 = tok0 + 8;
    #pragma unroll
    for (int ni = 0; ni < 16; ni++) {
        int d = ni * 8 + tq * 2;
        __half* p0 = ctx + (size_t)tok0 * DMODEL + h * DKH + d;
        __half* p1 = ctx + (size_t)tok1 * DMODEL + h * DKH + d;
        *(__half2*)p0 = __floats2half2_rn(o[ni][0] * rA, o[ni][1] * rA);
        *(__half2*)p1 = __floats2half2_rn(o[ni][2] * rB, o[ni][3] * rB);
    }
}

// ---------------- launch ----------------
extern "C" void kernel_launch(void* const* d_in, const int* in_sizes, int n_in,
                              void* d_out, int out_size) {
    const float* x     = (const float*)d_in[0];
    const int*   mask  = (const int*)d_in[1];
    const float* w_qkv = (const float*)d_in[2];
    const float* w_o   = (const float*)d_in[3];
    const float* ga1   = (const float*)d_in[4];
    const float* be1   = (const float*)d_in[5];
    const float* ga2   = (const float*)d_in[6];
    const float* be2   = (const float*)d_in[7];
    const float* w1    = (const float*)d_in[8];
    const float* b1    = (const float*)d_in[9];
    const float* w2    = (const float*)d_in[10];
    const float* b2    = (const float*)d_in[11];
    const float* ls    = (const float*)d_in[12];
    float* out = (float*)d_out;

    __half *ln1, *ln2, *q, *k, *v, *ctx, *hbuf, *wqkvb, *wob, *w1b, *w2b;
    int* flag;
    cudaGetSymbolAddress((void**)&ln1,   g_ln1);
    cudaGetSymbolAddress((void**)&ln2,   g_ln2);
    cudaGetSymbolAddress((void**)&q,     g_q);
    cudaGetSymbolAddress((void**)&k,     g_k);
    cudaGetSymbolAddress((void**)&v,     g_v);
    cudaGetSymbolAddress((void**)&ctx,   g_ctx);
    cudaGetSymbolAddress((void**)&hbuf,  g_h);
    cudaGetSymbolAddress((void**)&wqkvb, g_wqkv);
    cudaGetSymbolAddress((void**)&wob,   g_wo);
    cudaGetSymbolAddress((void**)&w1b,   g_w1);
    cudaGetSymbolAddress((void**)&w2b,   g_w2);
    cudaGetSymbolAddress((void**)&flag,  g_flag);

    cudaFuncSetAttribute(attn_f16, cudaFuncAttributeMaxDynamicSharedMemorySize, ATTN_SMEM);
    cudaFuncSetAttribute(gemm_f16<0>, cudaFuncAttributeMaxDynamicSharedMemorySize, SMEM_GEMM);
    cudaFuncSetAttribute(gemm_f16<1>, cudaFuncAttributeMaxDynamicSharedMemorySize, SMEM_GEMM);
    cudaFuncSetAttribute(gemm_f16<2>, cudaFuncAttributeMaxDynamicSharedMemorySize, SMEM_GEMM);
    cudaFuncSetAttribute(gemm_f16<3>, cudaFuncAttributeMaxDynamicSharedMemorySize, SMEM_GEMM);

    // side stream + events (created once; host resources only, no device memory)
    static cudaStream_t s2 = nullptr;
    static cudaEvent_t evA = nullptr, evC = nullptr, evB = nullptr;
    if (s2 == nullptr) {
        cudaStreamCreateWithFlags(&s2, cudaStreamNonBlocking);
        cudaEventCreateWithFlags(&evA, cudaEventDisableTiming);
        cudaEventCreateWithFlags(&evC, cudaEventDisableTiming);
        cudaEventCreateWithFlags(&evB, cudaEventDisableTiming);
    }

    // ---- main stream: conversions + layernorm ----
    cvt_all<<<(CVT_N0 + CVT_N1 + 2 * CVT_N2) / 256, 256>>>(
        w_qkv, w_o, w1, w2, wqkvb, wob, w1b, w2b);
    ln_kernel<<<TOKS, 256>>>(x, ga1, be1, ga2, be2, ln1, ln2);
    cudaEventRecord(evA, 0);

    // ---- side stream: QKV projection ----
    cudaStreamWaitEvent(s2, evA, 0);
    Epi e1 = {nullptr, nullptr, nullptr, nullptr, q, k, v};
    gemm_f16<0><<<dim3(24, 32), 512, SMEM_GEMM, s2>>>(ln1, wqkvb, TOKS, 3 * DMODEL, DMODEL, e1);

    // ---- main: FF1 (4th launch -> ncu capture slot) ----
    Epi e3 = {b1, nullptr, nullptr, nullptr, hbuf, nullptr, nullptr};
    gemm_f16<2><<<dim3(32, 32), 512, SMEM_GEMM>>>(ln2, w1b, TOKS, DFF, DMODEL, e3);

    // ---- main: mask flag ----
    flag_init<<<1, 32>>>(flag);
    mask_reduce<<<256, 256>>>(mask, in_sizes[1], flag);
    cudaEventRecord(evC, 0);

    // ---- side: attention (needs QKV + mask flag) ----
    cudaStreamWaitEvent(s2, evC, 0);
    attn_f16<<<dim3(32, 32), 128, ATTN_SMEM, s2>>>(q, k, v, mask, flag, ctx);
    cudaEventRecord(evB, s2);

    // ---- main: FF2 initializes out = x + ls*(h@w2 + b2) ----
    Epi e4 = {b2, ls, x, out, nullptr, nullptr, nullptr};
    gemm_f16<3><<<dim3(8, 32), 512, SMEM_GEMM>>>(hbuf, w2b, TOKS, DMODEL, DFF, e4);

    // ---- join, then WO accumulates out += ctx @ w_o ----
    cudaStreamWaitEvent(0, evB, 0);
    Epi e2 = {nullptr, nullptr, nullptr, out, nullptr, nullptr, nullptr};
    gemm_f16<1><<<dim3(8, 32), 512, SMEM_GEMM>>>(ctx, wob, TOKS, DMODEL, DMODEL, e2);
}

// round 9
// speedup vs baseline: 2.4820x; 1.0640x over previous
#include <cuda_runtime.h>
#include <cuda_fp16.h>
#include <cstdint>
#include <cmath>

// ---------------- problem constants ----------------
#define TOKS 4096
#define DMODEL 2048
#define DFF 8192
#define NHEADS 16
#define DKH 128
#define SEQ 2048
#define BATCH 2

// ---------------- scratch (device globals) ----------------
__device__ __align__(128) __half g_ln1[TOKS * DMODEL];
__device__ __align__(128) __half g_ln2[TOKS * DMODEL];
__device__ __align__(128) __half g_q[TOKS * DMODEL];
__device__ __align__(128) __half g_k[TOKS * DMODEL];
__device__ __align__(128) __half g_v[TOKS * DMODEL];
__device__ __align__(128) __half g_ctx[TOKS * DMODEL];
__device__ __align__(128) __half g_h[TOKS * DFF];
__device__ __align__(128) __half g_wqkv[DMODEL * 3 * DMODEL];
__device__ __align__(128) __half g_wo[DMODEL * DMODEL];
__device__ __align__(128) __half g_w1[DMODEL * DFF];
__device__ __align__(128) __half g_w2[DFF * DMODEL];
__device__ int g_flag[1];

// ---------------- helpers ----------------
__device__ __forceinline__ uint32_t smem_u32(const void* p) {
    uint32_t a;
    asm("{ .reg .u64 t; cvta.to.shared.u64 t, %1; cvt.u32.u64 %0, t; }"
        : "=r"(a) : "l"(p));
    return a;
}

#define CP16(dst, src) \
    asm volatile("cp.async.cg.shared.global [%0], [%1], 16;" \
                 :: "r"(dst), "l"(src) : "memory")
#define CP_COMMIT() asm volatile("cp.async.commit_group;" ::: "memory")
#define CP_WAIT1()  asm volatile("cp.async.wait_group 1;" ::: "memory")

#define LDSM_X4(r, addr) \
    asm volatile("ldmatrix.sync.aligned.m8n8.x4.shared.b16 {%0,%1,%2,%3}, [%4];" \
        : "=r"((r)[0]), "=r"((r)[1]), "=r"((r)[2]), "=r"((r)[3]) : "r"(addr))
#define LDSM_X4T(r, addr) \
    asm volatile("ldmatrix.sync.aligned.m8n8.x4.trans.shared.b16 {%0,%1,%2,%3}, [%4];" \
        : "=r"((r)[0]), "=r"((r)[1]), "=r"((r)[2]), "=r"((r)[3]) : "r"(addr))

__device__ __forceinline__ void mma16(float* c, const uint32_t* a, uint32_t b0, uint32_t b1) {
    asm volatile(
        "mma.sync.aligned.m16n8k16.row.col.f32.f16.f16.f32 "
        "{%0,%1,%2,%3},{%4,%5,%6,%7},{%8,%9},{%0,%1,%2,%3};"
        : "+f"(c[0]), "+f"(c[1]), "+f"(c[2]), "+f"(c[3])
        : "r"(a[0]), "r"(a[1]), "r"(a[2]), "r"(a[3]), "r"(b0), "r"(b1));
}

__device__ __forceinline__ uint32_t pack_h2(float x, float y) {
    __half2 t = __floats2half2_rn(x, y);
    return *(uint32_t*)&t;
}

// ---------------- fp32 -> fp16 converter (all 4 weights, one launch) ----------------
#define CVT_N0 (DMODEL * 3 * DMODEL / 4)
#define CVT_N1 (DMODEL * DMODEL / 4)
#define CVT_N2 (DMODEL * DFF / 4)
__global__ void cvt_all(const float* __restrict__ wqkv, const float* __restrict__ wo,
                        const float* __restrict__ w1, const float* __restrict__ w2,
                        __half* __restrict__ oqkv, __half* __restrict__ owo,
                        __half* __restrict__ ow1, __half* __restrict__ ow2) {
    int idx = blockIdx.x * blockDim.x + threadIdx.x;
    const float* in;
    __half* out;
    int off;
    if (idx < CVT_N0)                          { in = wqkv; out = oqkv; off = idx; }
    else if (idx < CVT_N0 + CVT_N1)            { in = wo;   out = owo;  off = idx - CVT_N0; }
    else if (idx < CVT_N0 + CVT_N1 + CVT_N2)   { in = w1;   out = ow1;  off = idx - CVT_N0 - CVT_N1; }
    else                                       { in = w2;   out = ow2;  off = idx - CVT_N0 - CVT_N1 - CVT_N2; }
    float4 v = ((const float4*)in)[off];
    ((__half2*)out)[off * 2]     = __floats2half2_rn(v.x, v.y);
    ((__half2*)out)[off * 2 + 1] = __floats2half2_rn(v.z, v.w);
}

// ---------------- LayerNorm: fp32 x -> fp16 ln1, ln2 ----------------
__global__ void ln_kernel(const float* __restrict__ x,
                          const float* __restrict__ ga1, const float* __restrict__ be1,
                          const float* __restrict__ ga2, const float* __restrict__ be2,
                          __half* __restrict__ o1, __half* __restrict__ o2) {
    int t = blockIdx.x;
    int tid = threadIdx.x;
    const float4* xr = (const float4*)(x + (size_t)t * DMODEL);
    float4 a = xr[tid];
    float4 bq = xr[tid + 256];
    float s  = a.x + a.y + a.z + a.w + bq.x + bq.y + bq.z + bq.w;
    float s2 = a.x*a.x + a.y*a.y + a.z*a.z + a.w*a.w +
               bq.x*bq.x + bq.y*bq.y + bq.z*bq.z + bq.w*bq.w;
    #pragma unroll
    for (int o = 16; o; o >>= 1) {
        s  += __shfl_xor_sync(0xffffffffu, s,  o);
        s2 += __shfl_xor_sync(0xffffffffu, s2, o);
    }
    __shared__ float rs[8], rs2[8], stats[2];
    if ((tid & 31) == 0) { rs[tid >> 5] = s; rs2[tid >> 5] = s2; }
    __syncthreads();
    if (tid == 0) {
        float S = 0.f, S2 = 0.f;
        for (int i = 0; i < 8; i++) { S += rs[i]; S2 += rs2[i]; }
        float mu = S * (1.0f / DMODEL);
        float var = S2 * (1.0f / DMODEL) - mu * mu;
        stats[0] = mu;
        stats[1] = rsqrtf(var + 1e-5f);
    }
    __syncthreads();
    float mu = stats[0], r = stats[1];
    const float4* G1 = (const float4*)ga1;
    const float4* B1 = (const float4*)be1;
    const float4* G2 = (const float4*)ga2;
    const float4* B2 = (const float4*)be2;
    __half2* O1 = (__half2*)(o1 + (size_t)t * DMODEL);
    __half2* O2 = (__half2*)(o2 + (size_t)t * DMODEL);
    #pragma unroll
    for (int i = 0; i < 2; i++) {
        int idx = tid + i * 256;
        float4 v = (i == 0) ? a : bq;
        float nx = (v.x - mu) * r, ny = (v.y - mu) * r, nz = (v.z - mu) * r, nw = (v.w - mu) * r;
        float4 g1v = G1[idx], b1v = B1[idx], g2v = G2[idx], b2v = B2[idx];
        O1[idx * 2]     = __floats2half2_rn(nx * g1v.x + b1v.x, ny * g1v.y + b1v.y);
        O1[idx * 2 + 1] = __floats2half2_rn(nz * g1v.z + b1v.z, nw * g1v.w + b1v.w);
        O2[idx * 2]     = __floats2half2_rn(nx * g2v.x + b2v.x, ny * g2v.y + b2v.y);
        O2[idx * 2 + 1] = __floats2half2_rn(nz * g2v.z + b2v.z, nw * g2v.w + b2v.w);
    }
}

// ---------------- mask flag ----------------
__global__ void flag_init(int* flag) { if (threadIdx.x == 0) flag[0] = 1; }

__global__ void mask_reduce(const int* __restrict__ mask, int n, int* __restrict__ flag) {
    bool bad = false;
    for (int i = blockIdx.x * blockDim.x + threadIdx.x; i < n; i += gridDim.x * blockDim.x)
        if (mask[i] == 0) bad = true;
    if (bad) flag[0] = 0;
}

// ======== fp16 GEMM: 128x256 tile, K-chunk 64, 3 stages, 512 threads ========
#define A_ROWB  144                 // 64 halfs + 16B pad
#define A_BYTES (128 * A_ROWB)      // 18432
#define B_ROWB  528
#define STAGE   (A_BYTES + 64 * B_ROWB)   // 18432 + 33792 = 52224
#define NSTAGE  3
#define SMEM_GEMM (STAGE * NSTAGE)        // 156672

struct Epi {
    const float* c0;   // bias
    const float* c1;   // layer_scale
    const float* c2;   // x residual
    float* o0;         // fp32 out
    __half* bo0;
    __half* bo1;
    __half* bo2;
};

// E=0: QKV head split.  E=1: out += v (WO accumulate).
// E=2: h = gelu(v + b1). E=3: out = x + ls*(v + b2) (FF2 init).
template <int E>
__device__ __forceinline__ void emit2(int r, int c, int N, float v0, float v1, const Epi& e) {
    if (E == 0) {
        int which = c >> 11, hh = (c >> 7) & 15, d0 = c & 127;
        __half* dst = (which == 0) ? e.bo0 : ((which == 1) ? e.bo1 : e.bo2);
        int b = r >> 11, s = r & 2047;
        __half* p = dst + (size_t)((b << 4) + hh) * (SEQ * DKH) + (size_t)s * DKH + d0;
        *(__half2*)p = __floats2half2_rn(v0, v1);
    } else if (E == 1) {
        size_t i = (size_t)r * N + c;
        float2 o = *(const float2*)(e.o0 + i);
        o.x += v0;
        o.y += v1;
        *(float2*)(e.o0 + i) = o;
    } else if (E == 2) {
        const float is2 = 0.70710678118654752f;
        float t0 = v0 + e.c0[c], t1 = v1 + e.c0[c + 1];
        float g0 = 0.5f * t0 * (1.0f + erff(t0 * is2));
        float g1 = 0.5f * t1 * (1.0f + erff(t1 * is2));
        __half* p = e.bo0 + (size_t)r * N + c;
        *(__half2*)p = __floats2half2_rn(g0, g1);
    } else {
        size_t i = (size_t)r * N + c;
        float2 xv = *(const float2*)(e.c2 + i);
        float2 bb = *(const float2*)(e.c0 + c);
        float2 ls = *(const float2*)(e.c1 + c);
        float2 o;
        o.x = xv.x + ls.x * (v0 + bb.x);
        o.y = xv.y + ls.y * (v1 + bb.y);
        *(float2*)(e.o0 + i) = o;
    }
}

__device__ __forceinline__ void gemm_load_stage(const __half* A, const __half* B,
                                                int K, int N, int bm, int bn, int kt,
                                                uint32_t base, int tid) {
    // A: 128 rows x 64 halfs = 1024 16B-chunks
    #pragma unroll
    for (int t = 0; t < 2; t++) {
        int c = tid + t * 512;
        int row = c >> 3, k8 = c & 7;
        const __half* src = A + (size_t)(bm + row) * K + kt * 64 + k8 * 8;
        CP16(base + (uint32_t)row * A_ROWB + (uint32_t)k8 * 16, src);
    }
    // B: 64 rows x 256 halfs = 2048 16B-chunks
    #pragma unroll
    for (int t = 0; t < 4; t++) {
        int c = tid + t * 512;
        int row = c >> 5, n8 = c & 31;
        const __half* src = B + (size_t)(kt * 64 + row) * N + bn + n8 * 8;
        CP16(base + A_BYTES + (uint32_t)row * B_ROWB + (uint32_t)n8 * 16, src);
    }
    CP_COMMIT();
}

template <int E>
__global__ __launch_bounds__(512, 1)
void gemm_f16(const __half* __restrict__ A, const __half* __restrict__ B,
              int M, int N, int K, Epi e) {
    extern __shared__ __align__(128) char smc[];
    uint32_t smb = smem_u32(smc);
    int tid = threadIdx.x, warp = tid >> 5, lane = tid & 31;
    int bm = blockIdx.y * 128, bn = blockIdx.x * 256;
    int wm = (warp >> 2) * 32, wn = (warp & 3) * 64;
    const int nt = K >> 6;

    float acc[2][8][4];
    #pragma unroll
    for (int i = 0; i < 2; i++)
        #pragma unroll
        for (int j = 0; j < 8; j++)
            #pragma unroll
            for (int k = 0; k < 4; k++) acc[i][j][k] = 0.f;

    gemm_load_stage(A, B, K, N, bm, bn, 0, smb, tid);
    gemm_load_stage(A, B, K, N, bm, bn, 1, smb + STAGE, tid);

    int frow = (lane & 7) + ((lane >> 3) & 1) * 8;
    int hi = lane >> 4;

    for (int i = 0; i < nt; i++) {
        CP_WAIT1();
        __syncthreads();
        if (i + 2 < nt)
            gemm_load_stage(A, B, K, N, bm, bn, i + 2, smb + (uint32_t)((i + 2) % 3) * STAGE, tid);

        uint32_t abase = smb + (uint32_t)(i % 3) * STAGE;
        uint32_t bbase = abase + A_BYTES;
        #pragma unroll
        for (int k16 = 0; k16 < 4; k16++) {
            uint32_t a[2][4], bf[4][4];
            #pragma unroll
            for (int mt = 0; mt < 2; mt++) {
                uint32_t ad = abase + (uint32_t)(wm + mt * 16 + frow) * A_ROWB
                            + (uint32_t)(k16 * 2 + hi) * 16;
                LDSM_X4(a[mt], ad);
            }
            #pragma unroll
            for (int nt16 = 0; nt16 < 4; nt16++) {
                uint32_t bd = bbase + (uint32_t)(k16 * 16 + frow) * B_ROWB
                            + (uint32_t)(((wn + nt16 * 16) >> 3) + hi) * 16;
                LDSM_X4T(bf[nt16], bd);
            }
            #pragma unroll
            for (int mt = 0; mt < 2; mt++)
                #pragma unroll
                for (int n8 = 0; n8 < 8; n8++)
                    mma16(acc[mt][n8], a[mt], bf[n8 >> 1][(n8 & 1) * 2], bf[n8 >> 1][(n8 & 1) * 2 + 1]);
        }
    }

    int g = lane >> 2, tq = lane & 3;
    #pragma unroll
    for (int mt = 0; mt < 2; mt++) {
        int r0 = bm + wm + mt * 16 + g;
        #pragma unroll
        for (int n8 = 0; n8 < 8; n8++) {
            int c0 = bn + wn + n8 * 8 + tq * 2;
            emit2<E>(r0,     c0, N, acc[mt][n8][0], acc[mt][n8][1], e);
            emit2<E>(r0 + 8, c0, N, acc[mt][n8][2], acc[mt][n8][3], e);
        }
    }
}

// ======== flash attention: fp16 mma16 + ldmatrix, single fp16 P ========
#define AKV_ROWB 272
#define AKV_MATB 17408
#define ATTN_SMEM (AKV_MATB * 5)

__global__ __launch_bounds__(128, 2)
void attn_f16(const __half* __restrict__ Q, const __half* __restrict__ K,
              const __half* __restrict__ V, const int* __restrict__ mask,
              const int* __restrict__ flag, __half* __restrict__ ctx) {
    extern __shared__ __align__(128) char sma[];
    uint32_t smb = smem_u32(sma);
    int tid = threadIdx.x, warp = tid >> 5, lane = tid & 31;
    int g = lane >> 2, tq = lane & 3;
    int frow = (lane & 7) + ((lane >> 3) & 1) * 8;
    int hi = lane >> 4;
    int qt = blockIdx.x, bh = blockIdx.y;
    int b = bh >> 4, h = bh & 15;
    const __half* Qg = Q + (size_t)bh * SEQ * DKH + (size_t)(qt * 64) * DKH;
    const __half* Kg = K + (size_t)bh * SEQ * DKH;
    const __half* Vg = V + (size_t)bh * SEQ * DKH;
    int q0 = qt * 64 + warp * 16;
    int allv = flag[0];

    {
        int row = tid >> 1, c16b = (tid & 1) * 8;
        #pragma unroll
        for (int t = 0; t < 8; t++) {
            CP16(smb + (uint32_t)row * AKV_ROWB + (uint32_t)(c16b + t) * 16,
                 Qg + (size_t)row * DKH + (c16b + t) * 8);
        }
        #pragma unroll
        for (int t = 0; t < 8; t++) {
            CP16(smb + AKV_MATB + (uint32_t)row * AKV_ROWB + (uint32_t)(c16b + t) * 16,
                 Kg + (size_t)row * DKH + (c16b + t) * 8);
            CP16(smb + AKV_MATB + AKV_MATB + (uint32_t)row * AKV_ROWB + (uint32_t)(c16b + t) * 16,
                 Vg + (size_t)row * DKH + (c16b + t) * 8);
        }
        CP_COMMIT();
        #pragma unroll
        for (int t = 0; t < 8; t++) {
            CP16(smb + AKV_MATB * 3 + (uint32_t)row * AKV_ROWB + (uint32_t)(c16b + t) * 16,
                 Kg + (size_t)(64 + row) * DKH + (c16b + t) * 8);
            CP16(smb + AKV_MATB * 4 + (uint32_t)row * AKV_ROWB + (uint32_t)(c16b + t) * 16,
                 Vg + (size_t)(64 + row) * DKH + (c16b + t) * 8);
        }
        CP_COMMIT();
    }

    CP_WAIT1();
    __syncthreads();

    uint32_t qa[8][4];
    #pragma unroll
    for (int k16 = 0; k16 < 8; k16++)
        LDSM_X4(qa[k16], smb + (uint32_t)(warp * 16 + frow) * AKV_ROWB
                             + (uint32_t)(k16 * 2 + hi) * 16);

    float o[16][4];
    #pragma unroll
    for (int i = 0; i < 16; i++)
        #pragma unroll
        for (int j = 0; j < 4; j++) o[i][j] = 0.f;
    float mA = -1e30f, mB = -1e30f, lA = 0.f, lB = 0.f;

    for (int j = 0; j < 32; j++) {
        if (j > 0) { CP_WAIT1(); __syncthreads(); }
        int buf = j & 1;
        uint32_t kbase = smb + AKV_MATB + (uint32_t)buf * (2 * AKV_MATB);
        uint32_t vbase = kbase + AKV_MATB;

        float sc[8][4];
        #pragma unroll
        for (int ni = 0; ni < 8; ni++)
            #pragma unroll
            for (int c = 0; c < 4; c++) sc[ni][c] = 0.f;
        #pragma unroll
        for (int k16 = 0; k16 < 8; k16++) {
            #pragma unroll
            for (int n16 = 0; n16 < 4; n16++) {
                uint32_t kb[4];
                LDSM_X4(kb, kbase + (uint32_t)(n16 * 16 + frow) * AKV_ROWB
                                  + (uint32_t)(k16 * 2 + hi) * 16);
                mma16(sc[n16 * 2],     qa[k16], kb[0], kb[2]);
                mma16(sc[n16 * 2 + 1], qa[k16], kb[1], kb[3]);
            }
        }
        const float sscale = 0.0883883476483184f;
        #pragma unroll
        for (int ni = 0; ni < 8; ni++)
            #pragma unroll
            for (int c = 0; c < 4; c++) sc[ni][c] *= sscale;

        if (!allv) {
            #pragma unroll
            for (int ni = 0; ni < 8; ni++) {
                int kc = j * 64 + ni * 8 + tq * 2;
                int r0 = q0 + g, r1 = q0 + g + 8;
                if (mask[(size_t)r0 * SEQ + kc] == 0)     sc[ni][0] = -1e9f;
                if (mask[(size_t)r0 * SEQ + kc + 1] == 0) sc[ni][1] = -1e9f;
                if (mask[(size_t)r1 * SEQ + kc] == 0)     sc[ni][2] = -1e9f;
                if (mask[(size_t)r1 * SEQ + kc + 1] == 0) sc[ni][3] = -1e9f;
            }
        }

        float mxA = -1e30f, mxB = -1e30f;
        #pragma unroll
        for (int ni = 0; ni < 8; ni++) {
            mxA = fmaxf(mxA, fmaxf(sc[ni][0], sc[ni][1]));
            mxB = fmaxf(mxB, fmaxf(sc[ni][2], sc[ni][3]));
        }
        mxA = fmaxf(mxA, __shfl_xor_sync(0xffffffffu, mxA, 1));
        mxA = fmaxf(mxA, __shfl_xor_sync(0xffffffffu, mxA, 2));
        mxB = fmaxf(mxB, __shfl_xor_sync(0xffffffffu, mxB, 1));
        mxB = fmaxf(mxB, __shfl_xor_sync(0xffffffffu, mxB, 2));
        float mAn = fmaxf(mA, mxA), mBn = fmaxf(mB, mxB);
        float aA = __expf(mA - mAn), aB = __expf(mB - mBn);
        float sA = 0.f, sB = 0.f;
        #pragma unroll
        for (int ni = 0; ni < 8; ni++) {
            sc[ni][0] = __expf(sc[ni][0] - mAn); sA += sc[ni][0];
            sc[ni][1] = __expf(sc[ni][1] - mAn); sA += sc[ni][1];
            sc[ni][2] = __expf(sc[ni][2] - mBn); sB += sc[ni][2];
            sc[ni][3] = __expf(sc[ni][3] - mBn); sB += sc[ni][3];
        }
        sA += __shfl_xor_sync(0xffffffffu, sA, 1);
        sA += __shfl_xor_sync(0xffffffffu, sA, 2);
        sB += __shfl_xor_sync(0xffffffffu, sB, 1);
        sB += __shfl_xor_sync(0xffffffffu, sB, 2);
        lA = lA * aA + sA;
        lB = lB * aB + sB;
        mA = mAn; mB = mBn;
        #pragma unroll
        for (int ni = 0; ni < 16; ni++) {
            o[ni][0] *= aA; o[ni][1] *= aA;
            o[ni][2] *= aB; o[ni][3] *= aB;
        }

        uint32_t pa[4][4];
        #pragma unroll
        for (int jj = 0; jj < 4; jj++) {
            float* e0 = sc[2 * jj];
            float* e1 = sc[2 * jj + 1];
            pa[jj][0] = pack_h2(e0[0], e0[1]);
            pa[jj][1] = pack_h2(e0[2], e0[3]);
            pa[jj][2] = pack_h2(e1[0], e1[1]);
            pa[jj][3] = pack_h2(e1[2], e1[3]);
        }

        #pragma unroll
        for (int k16 = 0; k16 < 4; k16++) {
            #pragma unroll
            for (int n16 = 0; n16 < 8; n16++) {
                uint32_t vb4[4];
                LDSM_X4T(vb4, vbase + (uint32_t)(k16 * 16 + frow) * AKV_ROWB
                                    + (uint32_t)(n16 * 2 + hi) * 16);
                mma16(o[n16 * 2],     pa[k16], vb4[0], vb4[1]);
                mma16(o[n16 * 2 + 1], pa[k16], vb4[2], vb4[3]);
            }
        }

        __syncthreads();
        if (j + 2 < 32) {
            int row = tid >> 1, c16b = (tid & 1) * 8;
            uint32_t kd = smb + AKV_MATB + (uint32_t)buf * (2 * AKV_MATB);
            const __half* ks = Kg + (size_t)((j + 2) * 64 + row) * DKH;
            const __half* vs = Vg + (size_t)((j + 2) * 64 + row) * DKH;
            #pragma unroll
            for (int t = 0; t < 8; t++) {
                CP16(kd + (uint32_t)row * AKV_ROWB + (uint32_t)(c16b + t) * 16,
                     ks + (c16b + t) * 8);
                CP16(kd + AKV_MATB + (uint32_t)row * AKV_ROWB + (uint32_t)(c16b + t) * 16,
                     vs + (c16b + t) * 8);
            }
            CP_COMMIT();
        }
    }

    float rA = 1.f / lA, rB = 1.f / lB;
    int tok0 = b * SEQ + q0 + g, tok1 = tok0 + 8;
    #pragma unroll
    for (int ni = 0; ni < 16; ni++) {
        int d = ni * 8 + tq * 2;
        __half* p0 = ctx + (size_t)tok0 * DMODEL + h * DKH + d;
        __half* p1 = ctx + (size_t)tok1 * DMODEL + h * DKH + d;
        *(__half2*)p0 = __floats2half2_rn(o[ni][0] * rA, o[ni][1] * rA);
        *(__half2*)p1 = __floats2half2_rn(o[ni][2] * rB, o[ni][3] * rB);
    }
}

// ---------------- launch ----------------
extern "C" void kernel_launch(void* const* d_in, const int* in_sizes, int n_in,
                              void* d_out, int out_size) {
    const float* x     = (const float*)d_in[0];
    const int*   mask  = (const int*)d_in[1];
    const float* w_qkv = (const float*)d_in[2];
    const float* w_o   = (const float*)d_in[3];
    const float* ga1   = (const float*)d_in[4];
    const float* be1   = (const float*)d_in[5];
    const float* ga2   = (const float*)d_in[6];
    const float* be2   = (const float*)d_in[7];
    const float* w1    = (const float*)d_in[8];
    const float* b1    = (const float*)d_in[9];
    const float* w2    = (const float*)d_in[10];
    const float* b2    = (const float*)d_in[11];
    const float* ls    = (const float*)d_in[12];
    float* out = (float*)d_out;

    __half *ln1, *ln2, *q, *k, *v, *ctx, *hbuf, *wqkvb, *wob, *w1b, *w2b;
    int* flag;
    cudaGetSymbolAddress((void**)&ln1,   g_ln1);
    cudaGetSymbolAddress((void**)&ln2,   g_ln2);
    cudaGetSymbolAddress((void**)&q,     g_q);
    cudaGetSymbolAddress((void**)&k,     g_k);
    cudaGetSymbolAddress((void**)&v,     g_v);
    cudaGetSymbolAddress((void**)&ctx,   g_ctx);
    cudaGetSymbolAddress((void**)&hbuf,  g_h);
    cudaGetSymbolAddress((void**)&wqkvb, g_wqkv);
    cudaGetSymbolAddress((void**)&wob,   g_wo);
    cudaGetSymbolAddress((void**)&w1b,   g_w1);
    cudaGetSymbolAddress((void**)&w2b,   g_w2);
    cudaGetSymbolAddress((void**)&flag,  g_flag);

    cudaFuncSetAttribute(attn_f16, cudaFuncAttributeMaxDynamicSharedMemorySize, ATTN_SMEM);
    cudaFuncSetAttribute(gemm_f16<0>, cudaFuncAttributeMaxDynamicSharedMemorySize, SMEM_GEMM);
    cudaFuncSetAttribute(gemm_f16<1>, cudaFuncAttributeMaxDynamicSharedMemorySize, SMEM_GEMM);
    cudaFuncSetAttribute(gemm_f16<2>, cudaFuncAttributeMaxDynamicSharedMemorySize, SMEM_GEMM);
    cudaFuncSetAttribute(gemm_f16<3>, cudaFuncAttributeMaxDynamicSharedMemorySize, SMEM_GEMM);

    // side stream + events (host resources only; created once)
    static cudaStream_t s2 = nullptr;
    static cudaEvent_t evA = nullptr, evC = nullptr, evB = nullptr;
    if (s2 == nullptr) {
        cudaStreamCreateWithFlags(&s2, cudaStreamNonBlocking);
        cudaEventCreateWithFlags(&evA, cudaEventDisableTiming);
        cudaEventCreateWithFlags(&evC, cudaEventDisableTiming);
        cudaEventCreateWithFlags(&evB, cudaEventDisableTiming);
    }

    // ---- main stream: conversions + layernorm ----
    cvt_all<<<(CVT_N0 + CVT_N1 + 2 * CVT_N2) / 256, 256>>>(
        w_qkv, w_o, w1, w2, wqkvb, wob, w1b, w2b);
    ln_kernel<<<TOKS, 256>>>(x, ga1, be1, ga2, be2, ln1, ln2);
    cudaEventRecord(evA, 0);

    // ---- side stream: QKV projection ----
    cudaStreamWaitEvent(s2, evA, 0);
    Epi e1 = {nullptr, nullptr, nullptr, nullptr, q, k, v};
    gemm_f16<0><<<dim3(24, 32), 512, SMEM_GEMM, s2>>>(ln1, wqkvb, TOKS, 3 * DMODEL, DMODEL, e1);

    // ---- main: FF1 (ncu capture slot) ----
    Epi e3 = {b1, nullptr, nullptr, nullptr, hbuf, nullptr, nullptr};
    gemm_f16<2><<<dim3(32, 32), 512, SMEM_GEMM>>>(ln2, w1b, TOKS, DFF, DMODEL, e3);

    // ---- main: mask flag ----
    flag_init<<<1, 32>>>(flag);
    mask_reduce<<<256, 256>>>(mask, in_sizes[1], flag);
    cudaEventRecord(evC, 0);

    // ---- side: attention (needs QKV + mask flag) ----
    cudaStreamWaitEvent(s2, evC, 0);
    attn_f16<<<dim3(32, 32), 128, ATTN_SMEM, s2>>>(q, k, v, mask, flag, ctx);
    cudaEventRecord(evB, s2);

    // ---- main: FF2 initializes out = x + ls*(h@w2 + b2) ----
    Epi e4 = {b2, ls, x, out, nullptr, nullptr, nullptr};
    gemm_f16<3><<<dim3(8, 32), 512, SMEM_GEMM>>>(hbuf, w2b, TOKS, DMODEL, DFF, e4);

    // ---- join, then WO accumulates out += ctx @ w_o ----
    cudaStreamWaitEvent(0, evB, 0);
    Epi e2 = {nullptr, nullptr, nullptr, out, nullptr, nullptr, nullptr};
    gemm_f16<1><<<dim3(8, 32), 512, SMEM_GEMM>>>(ctx, wob, TOKS, DMODEL, DMODEL, e2);
}